// round 3
// baseline (speedup 1.0000x reference)
#include <cuda_runtime.h>
#include <math.h>
#include <stdint.h>

// ---------------- constants ----------------
#define DIMC   1024
#define TEMBC  512
#define NTOK   3456     // NF*S = 24*144
#define TENC   128      // T
#define WQN    5        // number of windows
#define LWIN   1280     // T + CL*S
#define LVV    1152     // CL*S
#define SROW   576      // STRIDE*S
#define MQ     6400     // WQN*LWIN
#define MFF    3584     // TENC + NTOK
#define HEADS_ 16
#define HD_    64

// ---------------- device scratch ----------------
__device__ float g_emb1[6144];
__device__ float g_emb2[6144];
__device__ float g_x  [(size_t)MQ * DIMC];
__device__ float g_q  [(size_t)MQ * DIMC];
__device__ float g_k  [(size_t)MQ * DIMC];
__device__ float g_v  [(size_t)MQ * DIMC];
__device__ float g_ao [(size_t)MQ * DIMC];
__device__ float g_o2 [(size_t)MQ * DIMC];
__device__ float g_ffin [(size_t)MFF * DIMC];
__device__ float g_h1   [(size_t)MFF * 4096];
__device__ float g_ffout[(size_t)MFF * DIMC];

__constant__ float c_pyr[8] = {1.f,2.f,3.f,4.f,4.f,3.f,2.f,1.f};

// ---------------- helpers ----------------
__device__ __forceinline__ void block_reduce_2(float &s, float &s2) {
    __shared__ float ra[8], rb[8];
#pragma unroll
    for (int m = 16; m > 0; m >>= 1) {
        s  += __shfl_xor_sync(0xffffffffu, s,  m);
        s2 += __shfl_xor_sync(0xffffffffu, s2, m);
    }
    int wid = threadIdx.x >> 5;
    if ((threadIdx.x & 31) == 0) { ra[wid] = s; rb[wid] = s2; }
    __syncthreads();
    s  = ra[0]+ra[1]+ra[2]+ra[3]+ra[4]+ra[5]+ra[6]+ra[7];
    s2 = rb[0]+rb[1]+rb[2]+rb[3]+rb[4]+rb[5]+rb[6]+rb[7];
    __syncthreads();
}

__device__ __forceinline__ float gelu_tanh(float x) {
    float x3 = x * x * x;
    return 0.5f * x * (1.f + tanhf(0.79788456080286535588f * (x + 0.044715f * x3)));
}

// ---------------- emb = silu(temb) @ W + b (both emb1, emb2) ----------------
__global__ __launch_bounds__(256) void emb_kernel(
    const float* __restrict__ temb,
    const float* __restrict__ w1, const float* __restrict__ b1,
    const float* __restrict__ w2, const float* __restrict__ b2)
{
    __shared__ float st[TEMBC];
    int tid = threadIdx.x;
    for (int i = tid; i < TEMBC; i += 256) {
        float t = temb[i];
        st[i] = t / (1.f + expf(-t));
    }
    __syncthreads();
    int j = blockIdx.x * 256 + tid;  // 0..12287
    const float* w; const float* bb; float* out; int col;
    if (j < 6144) { w = w1; bb = b1; out = g_emb1; col = j; }
    else          { w = w2; bb = b2; out = g_emb2; col = j - 6144; }
    float acc = 0.f;
#pragma unroll 8
    for (int kk = 0; kk < TEMBC; kk++)
        acc += st[kk] * w[(size_t)kk * 6144 + col];
    out[col] = acc + bb[col];
}

// ---------------- build x = [mod-LN(enc); mod-LN(chunks)] ----------------
__global__ __launch_bounds__(256) void build_x_kernel(
    const float* __restrict__ hs, const float* __restrict__ enc,
    const float* __restrict__ g, const float* __restrict__ b)
{
    int row = blockIdx.x;               // 0..MQ-1
    int w = row / LWIN, l = row % LWIN;
    const float* src; int sc_off, sh_off;
    if (l < TENC) { src = enc + (size_t)l * DIMC; sc_off = 4096; sh_off = 3072; }
    else {
        int gidx = w * SROW + (l - TENC);
        src = hs + (size_t)gidx * DIMC; sc_off = 1024; sh_off = 0;
    }
    int tid = threadIdx.x;
    float x[4]; float s = 0.f, s2 = 0.f;
#pragma unroll
    for (int i = 0; i < 4; i++) {
        x[i] = src[tid + i * 256];
        s += x[i]; s2 += x[i] * x[i];
    }
    block_reduce_2(s, s2);
    float mean = s * (1.f / DIMC);
    float var  = s2 * (1.f / DIMC) - mean * mean;
    float inv  = rsqrtf(var + 1e-5f);
    float* dst = g_x + (size_t)row * DIMC;
#pragma unroll
    for (int i = 0; i < 4; i++) {
        int d = tid + i * 256;
        float v = (x[i] - mean) * inv * g[d] + b[d];
        dst[d] = v * (1.f + g_emb1[sc_off + d]) + g_emb1[sh_off + d];
    }
}

// ---------------- generic SGEMM: C = A(MxK) * B(KxN) [+bias][gelu] ----------------
// M % 128 == 0, N % 128 == 0, K % 16 == 0 (holds for all uses)
__global__ __launch_bounds__(256) void gemm_kernel(
    const float* __restrict__ A, const float* __restrict__ B,
    const float* __restrict__ bias, float* __restrict__ C,
    int M, int N, int K, int act)
{
    __shared__ float As[16][132];   // [BK][BM+4], transposed
    __shared__ float Bs[16][128];
    int bm = blockIdx.y, bn = blockIdx.x;
    int tid = threadIdx.x;
    int r0 = (tid >> 4) * 8, c0 = (tid & 15) * 8;
    float acc[8][8];
#pragma unroll
    for (int i = 0; i < 8; i++)
#pragma unroll
        for (int j = 0; j < 8; j++) acc[i][j] = 0.f;

    const float* Ab = A + (size_t)bm * 128 * K;
    const float* Bb = B + (size_t)bn * 128;

    for (int k0 = 0; k0 < K; k0 += 16) {
#pragma unroll
        for (int i = 0; i < 2; i++) {
            int f = tid + i * 256;           // 0..511
            int r = f >> 2; int kq = (f & 3) * 4;
            float4 av = *(const float4*)(Ab + (size_t)r * K + k0 + kq);
            As[kq + 0][r] = av.x; As[kq + 1][r] = av.y;
            As[kq + 2][r] = av.z; As[kq + 3][r] = av.w;
        }
#pragma unroll
        for (int i = 0; i < 2; i++) {
            int f = tid + i * 256;
            int kk = f >> 5; int cq = (f & 31) * 4;
            *(float4*)(&Bs[kk][cq]) = *(const float4*)(Bb + (size_t)(k0 + kk) * N + cq);
        }
        __syncthreads();
#pragma unroll
        for (int kk = 0; kk < 16; kk++) {
            float a[8], b[8];
            *(float4*)(a)     = *(const float4*)(&As[kk][r0]);
            *(float4*)(a + 4) = *(const float4*)(&As[kk][r0 + 4]);
            *(float4*)(b)     = *(const float4*)(&Bs[kk][c0]);
            *(float4*)(b + 4) = *(const float4*)(&Bs[kk][c0 + 4]);
#pragma unroll
            for (int i = 0; i < 8; i++)
#pragma unroll
                for (int j = 0; j < 8; j++)
                    acc[i][j] += a[i] * b[j];
        }
        __syncthreads();
    }

#pragma unroll
    for (int i = 0; i < 8; i++) {
        size_t row = (size_t)bm * 128 + r0 + i;
        float* Cp = C + row * N + bn * 128 + c0;
        float out[8];
#pragma unroll
        for (int j = 0; j < 8; j++) {
            float v = acc[i][j];
            if (bias) v += bias[bn * 128 + c0 + j];
            if (act)  v = gelu_tanh(v);
            out[j] = v;
        }
        *(float4*)(Cp)     = *(const float4*)(out);
        *(float4*)(Cp + 4) = *(const float4*)(out + 4);
    }
}

// ---------------- per-head LN on q/k (eps 1e-6) ----------------
__global__ __launch_bounds__(256) void qkln_kernel(
    float* __restrict__ buf, const float* __restrict__ g, const float* __restrict__ b)
{
    int seg  = blockIdx.x * 8 + (threadIdx.x >> 5);  // 0..MQ*16-1
    int lane = threadIdx.x & 31;
    float* p = buf + (size_t)(seg >> 4) * DIMC + (seg & 15) * HD_;
    float x0 = p[lane], x1 = p[lane + 32];
    float s = x0 + x1, s2 = x0 * x0 + x1 * x1;
#pragma unroll
    for (int m = 16; m > 0; m >>= 1) {
        s  += __shfl_xor_sync(0xffffffffu, s,  m);
        s2 += __shfl_xor_sync(0xffffffffu, s2, m);
    }
    float mean = s * (1.f / 64.f);
    float var  = s2 * (1.f / 64.f) - mean * mean;
    float inv  = rsqrtf(var + 1e-6f);
    p[lane]      = (x0 - mean) * inv * g[lane]      + b[lane];
    p[lane + 32] = (x1 - mean) * inv * g[lane + 32] + b[lane + 32];
}

// ---------------- attention (flash style), one 64-row Q tile per block --------
__global__ __launch_bounds__(256) void attn_kernel(
    const float* __restrict__ q, const float* __restrict__ k,
    const float* __restrict__ v, float* __restrict__ o)
{
    extern __shared__ float sm[];
    float* Qs = sm;                     // 64*64
    float* Ks = sm + 4096;              // 64 cols, stride 68 (transposed); reused as Ps
    float* Vs = sm + 4096 + 64 * 68;    // 64*64
    int qt = blockIdx.x, h = blockIdx.y, w = blockIdx.z;
    int tid = threadIdx.x;
    int r0 = (tid >> 4) * 4, c0 = (tid & 15) * 4;
    const size_t base = (size_t)w * LWIN * DIMC + (size_t)h * HD_;

#pragma unroll 4
    for (int i = 0; i < 16; i++) {
        int e = tid + i * 256; int r = e >> 6, d = e & 63;
        Qs[r * 64 + d] = q[base + (size_t)(qt * 64 + r) * DIMC + d] * 0.125f;
    }

    float m[4], l[4], accO[4][4];
#pragma unroll
    for (int i = 0; i < 4; i++) {
        m[i] = -1e30f; l[i] = 0.f;
#pragma unroll
        for (int j = 0; j < 4; j++) accO[i][j] = 0.f;
    }

    for (int kt = 0; kt < 20; kt++) {
        __syncthreads();
#pragma unroll 4
        for (int i = 0; i < 16; i++) {
            int e = tid + i * 256; int r = e >> 6, d = e & 63;
            size_t gi = base + (size_t)(kt * 64 + r) * DIMC + d;
            Ks[d * 68 + r] = k[gi];
            Vs[r * 64 + d] = v[gi];
        }
        __syncthreads();

        float s[4][4];
#pragma unroll
        for (int i = 0; i < 4; i++)
#pragma unroll
            for (int j = 0; j < 4; j++) s[i][j] = 0.f;

#pragma unroll 4
        for (int d = 0; d < 64; d++) {
            float4 kv = *(const float4*)(Ks + d * 68 + c0);
            float a0 = Qs[(r0 + 0) * 64 + d];
            float a1 = Qs[(r0 + 1) * 64 + d];
            float a2 = Qs[(r0 + 2) * 64 + d];
            float a3 = Qs[(r0 + 3) * 64 + d];
            s[0][0] += a0 * kv.x; s[0][1] += a0 * kv.y; s[0][2] += a0 * kv.z; s[0][3] += a0 * kv.w;
            s[1][0] += a1 * kv.x; s[1][1] += a1 * kv.y; s[1][2] += a1 * kv.z; s[1][3] += a1 * kv.w;
            s[2][0] += a2 * kv.x; s[2][1] += a2 * kv.y; s[2][2] += a2 * kv.z; s[2][3] += a2 * kv.w;
            s[3][0] += a3 * kv.x; s[3][1] += a3 * kv.y; s[3][2] += a3 * kv.z; s[3][3] += a3 * kv.w;
        }

        float p[4][4];
#pragma unroll
        for (int i = 0; i < 4; i++) {
            float tm = fmaxf(fmaxf(s[i][0], s[i][1]), fmaxf(s[i][2], s[i][3]));
#pragma unroll
            for (int msk = 8; msk > 0; msk >>= 1)
                tm = fmaxf(tm, __shfl_xor_sync(0xffffffffu, tm, msk));
            float mn = fmaxf(m[i], tm);
            float f  = expf(m[i] - mn);
            m[i] = mn;
            float rs = 0.f;
#pragma unroll
            for (int j = 0; j < 4; j++) { p[i][j] = expf(s[i][j] - mn); rs += p[i][j]; }
#pragma unroll
            for (int msk = 8; msk > 0; msk >>= 1)
                rs += __shfl_xor_sync(0xffffffffu, rs, msk);
            l[i] = l[i] * f + rs;
#pragma unroll
            for (int j = 0; j < 4; j++) accO[i][j] *= f;
        }

        __syncthreads();   // all Ks reads done before overwrite with P
#pragma unroll
        for (int i = 0; i < 4; i++) {
            float4 pv = make_float4(p[i][0], p[i][1], p[i][2], p[i][3]);
            *(float4*)(Ks + (r0 + i) * 68 + c0) = pv;
        }
        __syncthreads();

#pragma unroll 2
        for (int jj = 0; jj < 64; jj++) {
            float4 vv = *(const float4*)(Vs + jj * 64 + c0);
            float p0 = Ks[(r0 + 0) * 68 + jj];
            float p1 = Ks[(r0 + 1) * 68 + jj];
            float p2 = Ks[(r0 + 2) * 68 + jj];
            float p3 = Ks[(r0 + 3) * 68 + jj];
            accO[0][0] += p0 * vv.x; accO[0][1] += p0 * vv.y; accO[0][2] += p0 * vv.z; accO[0][3] += p0 * vv.w;
            accO[1][0] += p1 * vv.x; accO[1][1] += p1 * vv.y; accO[1][2] += p1 * vv.z; accO[1][3] += p1 * vv.w;
            accO[2][0] += p2 * vv.x; accO[2][1] += p2 * vv.y; accO[2][2] += p2 * vv.z; accO[2][3] += p2 * vv.w;
            accO[3][0] += p3 * vv.x; accO[3][1] += p3 * vv.y; accO[3][2] += p3 * vv.z; accO[3][3] += p3 * vv.w;
        }
    }

#pragma unroll
    for (int i = 0; i < 4; i++) {
        float invl = 1.f / l[i];
        float4 ov = make_float4(accO[i][0] * invl, accO[i][1] * invl,
                                accO[i][2] * invl, accO[i][3] * invl);
        *(float4*)(o + base + (size_t)(qt * 64 + r0 + i) * DIMC + c0) = ov;
    }
}

// ---------------- combine: hidden residual + pyramid-weighted window blend -----
__global__ __launch_bounds__(256) void combine_hidden_kernel(
    const float* __restrict__ hs, float* __restrict__ out)
{
    int gidx = blockIdx.x;               // 0..NTOK-1
    int tid  = threadIdx.x;
    int blk  = gidx / SROW;              // 0..5
    float acc[4] = {0.f, 0.f, 0.f, 0.f};
    float wsum = 0.f;
#pragma unroll
    for (int dw = -1; dw <= 0; dw++) {
        int w = blk + dw;
        if (w < 0 || w > 4) continue;
        int lv = gidx - w * SROW;        // in [0, LVV)
        float wt = c_pyr[lv / 144];
        wsum += wt;
        const float* op = g_o2 + ((size_t)w * LWIN + TENC + lv) * DIMC;
#pragma unroll
        for (int i = 0; i < 4; i++) acc[i] += wt * op[tid + i * 256];
    }
    float inv = 1.f / wsum;
#pragma unroll
    for (int i = 0; i < 4; i++) {
        int d = tid + i * 256;
        out[(size_t)gidx * DIMC + d] =
            hs[(size_t)gidx * DIMC + d] + g_emb1[2048 + d] * acc[i] * inv;
    }
}

// ---------------- combine: enc residual + mean over windows ----------------
__global__ __launch_bounds__(256) void combine_enc_kernel(
    const float* __restrict__ enc, float* __restrict__ out)
{
    int t = blockIdx.x; int tid = threadIdx.x;
#pragma unroll
    for (int i = 0; i < 4; i++) {
        int d = tid + i * 256;
        float a = 0.f;
#pragma unroll
        for (int w = 0; w < WQN; w++)
            a += g_o2[((size_t)w * LWIN + t) * DIMC + d];
        out[(size_t)t * DIMC + d] =
            enc[(size_t)t * DIMC + d] + g_emb1[5120 + d] * a * 0.2f;
    }
}

// ---------------- build ff_in = [mod-LN2(enc_new); mod-LN2(hidden_new)] --------
__global__ __launch_bounds__(256) void build_ffin_kernel(
    const float* __restrict__ dout,
    const float* __restrict__ g, const float* __restrict__ b)
{
    int row = blockIdx.x;                // 0..MFF-1
    const float* src; int sc_off, sh_off;
    if (row < TENC) { src = dout + (size_t)NTOK * DIMC + (size_t)row * DIMC; sc_off = 4096; sh_off = 3072; }
    else            { src = dout + (size_t)(row - TENC) * DIMC;              sc_off = 1024; sh_off = 0;    }
    int tid = threadIdx.x;
    float x[4]; float s = 0.f, s2 = 0.f;
#pragma unroll
    for (int i = 0; i < 4; i++) {
        x[i] = src[tid + i * 256];
        s += x[i]; s2 += x[i] * x[i];
    }
    block_reduce_2(s, s2);
    float mean = s * (1.f / DIMC);
    float var  = s2 * (1.f / DIMC) - mean * mean;
    float inv  = rsqrtf(var + 1e-5f);
    float* dst = g_ffin + (size_t)row * DIMC;
#pragma unroll
    for (int i = 0; i < 4; i++) {
        int d = tid + i * 256;
        float v = (x[i] - mean) * inv * g[d] + b[d];
        dst[d] = v * (1.f + g_emb2[sc_off + d]) + g_emb2[sh_off + d];
    }
}

// ---------------- final residual add --------------------------------------
__global__ __launch_bounds__(256) void final_add_kernel(float* __restrict__ dout)
{
    int row = blockIdx.x;                // 0..MFF-1
    int tid = threadIdx.x;
    if (row < TENC) {
        float* p = dout + (size_t)NTOK * DIMC + (size_t)row * DIMC;
#pragma unroll
        for (int i = 0; i < 4; i++) {
            int d = tid + i * 256;
            p[d] += g_emb2[5120 + d] * g_ffout[(size_t)row * DIMC + d];
        }
    } else {
        float* p = dout + (size_t)(row - TENC) * DIMC;
#pragma unroll
        for (int i = 0; i < 4; i++) {
            int d = tid + i * 256;
            p[d] += g_emb2[2048 + d] * g_ffout[(size_t)row * DIMC + d];
        }
    }
}

// ---------------- host side ----------------
static void launch_gemm(const float* A, const float* B, const float* bias,
                        float* C, int M, int N, int K, int act)
{
    dim3 grid(N / 128, M / 128);
    gemm_kernel<<<grid, 256>>>(A, B, bias, C, M, N, K, act);
}

extern "C" void kernel_launch(void* const* d_in, const int* in_sizes, int n_in,
                              void* d_out, int out_size)
{
    const float* hs    = (const float*)d_in[0];
    const float* enc   = (const float*)d_in[1];
    const float* temb  = (const float*)d_in[2];
    const float* n1w   = (const float*)d_in[3];
    const float* n1b   = (const float*)d_in[4];
    const float* n1g   = (const float*)d_in[5];
    const float* n1bb  = (const float*)d_in[6];
    const float* wq    = (const float*)d_in[7];
    const float* wk    = (const float*)d_in[8];
    const float* wv    = (const float*)d_in[9];
    const float* nqg   = (const float*)d_in[10];
    const float* nqb   = (const float*)d_in[11];
    const float* nkg   = (const float*)d_in[12];
    const float* nkb   = (const float*)d_in[13];
    const float* wo    = (const float*)d_in[14];
    const float* bo    = (const float*)d_in[15];
    const float* n2w   = (const float*)d_in[16];
    const float* n2b   = (const float*)d_in[17];
    const float* n2g   = (const float*)d_in[18];
    const float* n2bb  = (const float*)d_in[19];
    const float* ffw1  = (const float*)d_in[20];
    const float* ffb1  = (const float*)d_in[21];
    const float* ffw2  = (const float*)d_in[22];
    const float* ffb2  = (const float*)d_in[23];
    (void)in_sizes; (void)n_in;

    float* out = (float*)d_out;
    float* out_hidden = out;                           // [NTOK, DIMC]
    float* out_enc    = out + (size_t)NTOK * DIMC;     // [TENC, DIMC]
    (void)out_size;

    // resolve scratch symbol addresses (host cannot take &__device__ directly)
    float *p_x, *p_q, *p_k, *p_v, *p_ao, *p_o2, *p_ffin, *p_h1, *p_ffout;
    cudaGetSymbolAddress((void**)&p_x,    g_x);
    cudaGetSymbolAddress((void**)&p_q,    g_q);
    cudaGetSymbolAddress((void**)&p_k,    g_k);
    cudaGetSymbolAddress((void**)&p_v,    g_v);
    cudaGetSymbolAddress((void**)&p_ao,   g_ao);
    cudaGetSymbolAddress((void**)&p_o2,   g_o2);
    cudaGetSymbolAddress((void**)&p_ffin, g_ffin);
    cudaGetSymbolAddress((void**)&p_h1,   g_h1);
    cudaGetSymbolAddress((void**)&p_ffout,g_ffout);

    const int ATTN_SMEM = (4096 + 64 * 68 + 64 * 64) * 4;  // 50176 B
    cudaFuncSetAttribute(attn_kernel, cudaFuncAttributeMaxDynamicSharedMemorySize, ATTN_SMEM);

    // 1. modulation embeddings
    emb_kernel<<<48, 256>>>(temb, n1w, n1b, n2w, n2b);
    // 2. x = modulated LN of [enc ; gathered chunks]
    build_x_kernel<<<MQ, 256>>>(hs, enc, n1g, n1bb);
    // 3. qkv projections
    launch_gemm(p_x, wq, nullptr, p_q, MQ, DIMC, DIMC, 0);
    launch_gemm(p_x, wk, nullptr, p_k, MQ, DIMC, DIMC, 0);
    launch_gemm(p_x, wv, nullptr, p_v, MQ, DIMC, DIMC, 0);
    // 4. per-head LN on q, k
    qkln_kernel<<<MQ * HEADS_ / 8, 256>>>(p_q, nqg, nqb);
    qkln_kernel<<<MQ * HEADS_ / 8, 256>>>(p_k, nkg, nkb);
    // 5. attention
    attn_kernel<<<dim3(LWIN / 64, HEADS_, WQN), 256, ATTN_SMEM>>>(p_q, p_k, p_v, p_ao);
    // 6. output projection
    launch_gemm(p_ao, wo, bo, p_o2, MQ, DIMC, DIMC, 0);
    // 7. residual + window blending
    combine_hidden_kernel<<<NTOK, 256>>>(hs, out_hidden);
    combine_enc_kernel<<<TENC, 256>>>(enc, out_enc);
    // 8. FFN
    build_ffin_kernel<<<MFF, 256>>>(out, n2g, n2bb);
    launch_gemm(p_ffin, ffw1, ffb1, p_h1, MFF, 4096, DIMC, 1);
    launch_gemm(p_h1, ffw2, ffb2, p_ffout, MFF, DIMC, 4096, 0);
    // 9. final gated residual
    final_add_kernel<<<MFF, 256>>>(out);
}

// round 4
// speedup vs baseline: 2.0044x; 2.0044x over previous
#include <cuda_runtime.h>
#include <math.h>
#include <stdint.h>

// ---------------- constants ----------------
#define DIMC   1024
#define TEMBC  512
#define NTOK   3456     // NF*S = 24*144
#define TENC   128      // T
#define WQN    5        // number of windows
#define LWIN   1280     // T + CL*S
#define LVV    1152     // CL*S
#define SROW   576      // STRIDE*S
#define MQ     6400     // WQN*LWIN
#define MFF    3584     // TENC + NTOK
#define HEADS_ 16
#define HD_    64

#define MEG 1048576

// ---------------- device scratch ----------------
__device__ float g_emb1[6144];
__device__ float g_emb2[6144];
__device__ float g_x  [(size_t)MQ * DIMC];
__device__ float g_q  [(size_t)MQ * DIMC];
__device__ float g_k  [(size_t)MQ * DIMC];
__device__ float g_v  [(size_t)MQ * DIMC];
__device__ float g_ao [(size_t)MQ * DIMC];
__device__ float g_o2 [(size_t)MQ * DIMC];
__device__ float g_ffin [(size_t)MFF * DIMC];
__device__ float g_h1   [(size_t)MFF * 4096];
__device__ float g_ffout[(size_t)MFF * DIMC];
__device__ float g_wr  [(size_t)12 * MEG];   // rounded weights: wq,wk,wv,wo, w1(4M), w2(4M)

__constant__ float c_pyr[8] = {1.f,2.f,3.f,4.f,4.f,3.f,2.f,1.f};

// ---------------- helpers ----------------
__device__ __forceinline__ float to_tf32(float x) {
    uint32_t u;
    asm("cvt.rna.tf32.f32 %0, %1;" : "=r"(u) : "f"(x));
    return __uint_as_float(u);
}

__device__ __forceinline__ void block_reduce_2(float &s, float &s2) {
    __shared__ float ra[8], rb[8];
#pragma unroll
    for (int m = 16; m > 0; m >>= 1) {
        s  += __shfl_xor_sync(0xffffffffu, s,  m);
        s2 += __shfl_xor_sync(0xffffffffu, s2, m);
    }
    int wid = threadIdx.x >> 5;
    if ((threadIdx.x & 31) == 0) { ra[wid] = s; rb[wid] = s2; }
    __syncthreads();
    s  = ra[0]+ra[1]+ra[2]+ra[3]+ra[4]+ra[5]+ra[6]+ra[7];
    s2 = rb[0]+rb[1]+rb[2]+rb[3]+rb[4]+rb[5]+rb[6]+rb[7];
    __syncthreads();
}

__device__ __forceinline__ float gelu_tanh(float x) {
    float x3 = x * x * x;
    return 0.5f * x * (1.f + tanhf(0.79788456080286535588f * (x + 0.044715f * x3)));
}

__device__ __forceinline__ void mma_tf32(float* d, const uint32_t* a, const uint32_t* b) {
    asm volatile(
        "mma.sync.aligned.m16n8k8.row.col.f32.tf32.tf32.f32 "
        "{%0,%1,%2,%3}, {%4,%5,%6,%7}, {%8,%9}, {%0,%1,%2,%3};"
        : "+f"(d[0]), "+f"(d[1]), "+f"(d[2]), "+f"(d[3])
        : "r"(a[0]), "r"(a[1]), "r"(a[2]), "r"(a[3]), "r"(b[0]), "r"(b[1]));
}

// ---------------- round weights to tf32 (one pass) ----------------
__global__ __launch_bounds__(256) void round_w_kernel(const float4* __restrict__ src,
                                                      float4* __restrict__ dst, int n4)
{
    int i = blockIdx.x * 256 + threadIdx.x;
    if (i >= n4) return;
    float4 v = src[i];
    v.x = to_tf32(v.x); v.y = to_tf32(v.y); v.z = to_tf32(v.z); v.w = to_tf32(v.w);
    dst[i] = v;
}

// ---------------- emb = silu(temb) @ W + b (both emb1, emb2) ----------------
__global__ __launch_bounds__(256) void emb_kernel(
    const float* __restrict__ temb,
    const float* __restrict__ w1, const float* __restrict__ b1,
    const float* __restrict__ w2, const float* __restrict__ b2)
{
    __shared__ float st[TEMBC];
    int tid = threadIdx.x;
    for (int i = tid; i < TEMBC; i += 256) {
        float t = temb[i];
        st[i] = t / (1.f + expf(-t));
    }
    __syncthreads();
    int j = blockIdx.x * 256 + tid;  // 0..12287
    const float* w; const float* bb; float* out; int col;
    if (j < 6144) { w = w1; bb = b1; out = g_emb1; col = j; }
    else          { w = w2; bb = b2; out = g_emb2; col = j - 6144; }
    float acc = 0.f;
#pragma unroll 8
    for (int kk = 0; kk < TEMBC; kk++)
        acc += st[kk] * w[(size_t)kk * 6144 + col];
    out[col] = acc + bb[col];
}

// ---------------- build x = [mod-LN(enc); mod-LN(chunks)]  (tf32-rounded) -----
__global__ __launch_bounds__(256) void build_x_kernel(
    const float* __restrict__ hs, const float* __restrict__ enc,
    const float* __restrict__ g, const float* __restrict__ b)
{
    int row = blockIdx.x;               // 0..MQ-1
    int w = row / LWIN, l = row % LWIN;
    const float* src; int sc_off, sh_off;
    if (l < TENC) { src = enc + (size_t)l * DIMC; sc_off = 4096; sh_off = 3072; }
    else {
        int gidx = w * SROW + (l - TENC);
        src = hs + (size_t)gidx * DIMC; sc_off = 1024; sh_off = 0;
    }
    int tid = threadIdx.x;
    float x[4]; float s = 0.f, s2 = 0.f;
#pragma unroll
    for (int i = 0; i < 4; i++) {
        x[i] = src[tid + i * 256];
        s += x[i]; s2 += x[i] * x[i];
    }
    block_reduce_2(s, s2);
    float mean = s * (1.f / DIMC);
    float var  = s2 * (1.f / DIMC) - mean * mean;
    float inv  = rsqrtf(var + 1e-5f);
    float* dst = g_x + (size_t)row * DIMC;
#pragma unroll
    for (int i = 0; i < 4; i++) {
        int d = tid + i * 256;
        float v = (x[i] - mean) * inv * g[d] + b[d];
        dst[d] = to_tf32(v * (1.f + g_emb1[sc_off + d]) + g_emb1[sh_off + d]);
    }
}

// ---------------- TF32 tensor-core GEMM: C = A(MxK) * B(KxN) [+bias][gelu][rnd]
// M % 128 == 0, N % 128 == 0, K % 32 == 0. A,B must already be tf32-rounded.
#define BM 128
#define BN 128
#define BK 32
#define ASTR 36
#define BSTR 132
#define STAGE_F (BM * ASTR + BK * BSTR)   // 8832 floats per stage

__global__ __launch_bounds__(256, 2) void gemm_tc_kernel(
    const float* __restrict__ A, const float* __restrict__ B,
    const float* __restrict__ bias, float* __restrict__ C,
    int M, int N, int K, int flags)
{
    extern __shared__ float sm[];
    float* As0 = sm;
    float* Bs0 = sm + (size_t)2 * BM * ASTR;

    int tid = threadIdx.x;
    int bm = blockIdx.y, bn = blockIdx.x;
    int lane = tid & 31, wid = tid >> 5;
    int wm = (wid & 1) * 64, wn = (wid >> 1) * 32;
    int gid = lane >> 2, tig = lane & 3;

    const float* Ag = A + (size_t)bm * BM * K;
    const float* Bg = B + (size_t)bn * BN;

    float acc[4][4][4];
#pragma unroll
    for (int a = 0; a < 4; a++)
#pragma unroll
        for (int b = 0; b < 4; b++)
#pragma unroll
            for (int c = 0; c < 4; c++) acc[a][b][c] = 0.f;

#define LOAD_TILE(kt, buf)                                                        \
    {                                                                             \
        float* ad = As0 + (buf) * BM * ASTR;                                      \
        const float* asrc = Ag + (kt) * BK;                                       \
        _Pragma("unroll")                                                         \
        for (int i = 0; i < 4; i++) {                                             \
            int c = tid + i * 256;                                                \
            int r = c >> 3, kc = (c & 7) << 2;                                    \
            uint32_t dsm = (uint32_t)__cvta_generic_to_shared(ad + r * ASTR + kc);\
            const float* s = asrc + (size_t)r * K + kc;                           \
            asm volatile("cp.async.cg.shared.global [%0], [%1], 16;"              \
                         :: "r"(dsm), "l"(s));                                    \
        }                                                                         \
        float* bd = Bs0 + (buf) * BK * BSTR;                                      \
        const float* bsrc = Bg + (size_t)(kt) * BK * N;                           \
        _Pragma("unroll")                                                         \
        for (int i = 0; i < 4; i++) {                                             \
            int c = tid + i * 256;                                                \
            int r = c >> 5, nc = (c & 31) << 2;                                   \
            uint32_t dsm = (uint32_t)__cvta_generic_to_shared(bd + r * BSTR + nc);\
            const float* s = bsrc + (size_t)r * N + nc;                           \
            asm volatile("cp.async.cg.shared.global [%0], [%1], 16;"              \
                         :: "r"(dsm), "l"(s));                                    \
        }                                                                         \
    }

    LOAD_TILE(0, 0);
    asm volatile("cp.async.commit_group;");

    int ktiles = K / BK;
    for (int t = 0; t < ktiles; t++) {
        int buf = t & 1;
        if (t + 1 < ktiles) {
            LOAD_TILE(t + 1, buf ^ 1);
            asm volatile("cp.async.commit_group;");
            asm volatile("cp.async.wait_group 1;");
        } else {
            asm volatile("cp.async.wait_group 0;");
        }
        __syncthreads();

        const float* Ab = As0 + buf * BM * ASTR;
        const float* Bb = Bs0 + buf * BK * BSTR;
#pragma unroll
        for (int ks = 0; ks < 4; ks++) {
            int k0 = ks * 8;
            uint32_t af[4][4], bf[4][2];
#pragma unroll
            for (int mt = 0; mt < 4; mt++) {
                const float* ap = Ab + (wm + mt * 16 + gid) * ASTR + k0 + tig;
                af[mt][0] = __float_as_uint(ap[0]);
                af[mt][1] = __float_as_uint(ap[8 * ASTR]);
                af[mt][2] = __float_as_uint(ap[4]);
                af[mt][3] = __float_as_uint(ap[8 * ASTR + 4]);
            }
#pragma unroll
            for (int nt = 0; nt < 4; nt++) {
                const float* bp = Bb + (k0 + tig) * BSTR + wn + nt * 8 + gid;
                bf[nt][0] = __float_as_uint(bp[0]);
                bf[nt][1] = __float_as_uint(bp[4 * BSTR]);
            }
#pragma unroll
            for (int mt = 0; mt < 4; mt++)
#pragma unroll
                for (int nt = 0; nt < 4; nt++)
                    mma_tf32(acc[mt][nt], af[mt], bf[nt]);
        }
        __syncthreads();
    }

    int act = flags & 1, rnd = flags & 2;
#pragma unroll
    for (int mt = 0; mt < 4; mt++) {
        int row = bm * BM + wm + mt * 16 + gid;
#pragma unroll
        for (int nt = 0; nt < 4; nt++) {
            int col = bn * BN + wn + nt * 8 + tig * 2;
            float b0 = bias ? bias[col] : 0.f;
            float b1 = bias ? bias[col + 1] : 0.f;
            float v0 = acc[mt][nt][0] + b0, v1 = acc[mt][nt][1] + b1;
            float v2 = acc[mt][nt][2] + b0, v3 = acc[mt][nt][3] + b1;
            if (act) { v0 = gelu_tanh(v0); v1 = gelu_tanh(v1); v2 = gelu_tanh(v2); v3 = gelu_tanh(v3); }
            if (rnd) { v0 = to_tf32(v0); v1 = to_tf32(v1); v2 = to_tf32(v2); v3 = to_tf32(v3); }
            float2 lo = make_float2(v0, v1), hi = make_float2(v2, v3);
            *(float2*)(C + (size_t)row * N + col)       = lo;
            *(float2*)(C + (size_t)(row + 8) * N + col) = hi;
        }
    }
}

// ---------------- per-head LN on q/k (eps 1e-6) ----------------
__global__ __launch_bounds__(256) void qkln_kernel(
    float* __restrict__ buf, const float* __restrict__ g, const float* __restrict__ b)
{
    int seg  = blockIdx.x * 8 + (threadIdx.x >> 5);  // 0..MQ*16-1
    int lane = threadIdx.x & 31;
    float* p = buf + (size_t)(seg >> 4) * DIMC + (seg & 15) * HD_;
    float x0 = p[lane], x1 = p[lane + 32];
    float s = x0 + x1, s2 = x0 * x0 + x1 * x1;
#pragma unroll
    for (int m = 16; m > 0; m >>= 1) {
        s  += __shfl_xor_sync(0xffffffffu, s,  m);
        s2 += __shfl_xor_sync(0xffffffffu, s2, m);
    }
    float mean = s * (1.f / 64.f);
    float var  = s2 * (1.f / 64.f) - mean * mean;
    float inv  = rsqrtf(var + 1e-6f);
    p[lane]      = (x0 - mean) * inv * g[lane]      + b[lane];
    p[lane + 32] = (x1 - mean) * inv * g[lane + 32] + b[lane + 32];
}

// ---------------- attention (flash style), one 64-row Q tile per block --------
__global__ __launch_bounds__(256) void attn_kernel(
    const float* __restrict__ q, const float* __restrict__ k,
    const float* __restrict__ v, float* __restrict__ o)
{
    extern __shared__ float sm[];
    float* Qs = sm;                     // 64*64
    float* Ks = sm + 4096;              // 64 cols, stride 68 (transposed); reused as Ps
    float* Vs = sm + 4096 + 64 * 68;    // 64*64
    int qt = blockIdx.x, h = blockIdx.y, w = blockIdx.z;
    int tid = threadIdx.x;
    int r0 = (tid >> 4) * 4, c0 = (tid & 15) * 4;
    const size_t base = (size_t)w * LWIN * DIMC + (size_t)h * HD_;

#pragma unroll 4
    for (int i = 0; i < 16; i++) {
        int e = tid + i * 256; int r = e >> 6, d = e & 63;
        Qs[r * 64 + d] = q[base + (size_t)(qt * 64 + r) * DIMC + d] * 0.125f;
    }

    float m[4], l[4], accO[4][4];
#pragma unroll
    for (int i = 0; i < 4; i++) {
        m[i] = -1e30f; l[i] = 0.f;
#pragma unroll
        for (int j = 0; j < 4; j++) accO[i][j] = 0.f;
    }

    for (int kt = 0; kt < 20; kt++) {
        __syncthreads();
#pragma unroll 4
        for (int i = 0; i < 16; i++) {
            int e = tid + i * 256; int r = e >> 6, d = e & 63;
            size_t gi = base + (size_t)(kt * 64 + r) * DIMC + d;
            Ks[d * 68 + r] = k[gi];
            Vs[r * 64 + d] = v[gi];
        }
        __syncthreads();

        float s[4][4];
#pragma unroll
        for (int i = 0; i < 4; i++)
#pragma unroll
            for (int j = 0; j < 4; j++) s[i][j] = 0.f;

#pragma unroll 4
        for (int d = 0; d < 64; d++) {
            float4 kv = *(const float4*)(Ks + d * 68 + c0);
            float a0 = Qs[(r0 + 0) * 64 + d];
            float a1 = Qs[(r0 + 1) * 64 + d];
            float a2 = Qs[(r0 + 2) * 64 + d];
            float a3 = Qs[(r0 + 3) * 64 + d];
            s[0][0] += a0 * kv.x; s[0][1] += a0 * kv.y; s[0][2] += a0 * kv.z; s[0][3] += a0 * kv.w;
            s[1][0] += a1 * kv.x; s[1][1] += a1 * kv.y; s[1][2] += a1 * kv.z; s[1][3] += a1 * kv.w;
            s[2][0] += a2 * kv.x; s[2][1] += a2 * kv.y; s[2][2] += a2 * kv.z; s[2][3] += a2 * kv.w;
            s[3][0] += a3 * kv.x; s[3][1] += a3 * kv.y; s[3][2] += a3 * kv.z; s[3][3] += a3 * kv.w;
        }

        float p[4][4];
#pragma unroll
        for (int i = 0; i < 4; i++) {
            float tm = fmaxf(fmaxf(s[i][0], s[i][1]), fmaxf(s[i][2], s[i][3]));
#pragma unroll
            for (int msk = 8; msk > 0; msk >>= 1)
                tm = fmaxf(tm, __shfl_xor_sync(0xffffffffu, tm, msk));
            float mn = fmaxf(m[i], tm);
            float f  = expf(m[i] - mn);
            m[i] = mn;
            float rs = 0.f;
#pragma unroll
            for (int j = 0; j < 4; j++) { p[i][j] = expf(s[i][j] - mn); rs += p[i][j]; }
#pragma unroll
            for (int msk = 8; msk > 0; msk >>= 1)
                rs += __shfl_xor_sync(0xffffffffu, rs, msk);
            l[i] = l[i] * f + rs;
#pragma unroll
            for (int j = 0; j < 4; j++) accO[i][j] *= f;
        }

        __syncthreads();   // all Ks reads done before overwrite with P
#pragma unroll
        for (int i = 0; i < 4; i++) {
            float4 pv = make_float4(p[i][0], p[i][1], p[i][2], p[i][3]);
            *(float4*)(Ks + (r0 + i) * 68 + c0) = pv;
        }
        __syncthreads();

#pragma unroll 2
        for (int jj = 0; jj < 64; jj++) {
            float4 vv = *(const float4*)(Vs + jj * 64 + c0);
            float p0 = Ks[(r0 + 0) * 68 + jj];
            float p1 = Ks[(r0 + 1) * 68 + jj];
            float p2 = Ks[(r0 + 2) * 68 + jj];
            float p3 = Ks[(r0 + 3) * 68 + jj];
            accO[0][0] += p0 * vv.x; accO[0][1] += p0 * vv.y; accO[0][2] += p0 * vv.z; accO[0][3] += p0 * vv.w;
            accO[1][0] += p1 * vv.x; accO[1][1] += p1 * vv.y; accO[1][2] += p1 * vv.z; accO[1][3] += p1 * vv.w;
            accO[2][0] += p2 * vv.x; accO[2][1] += p2 * vv.y; accO[2][2] += p2 * vv.z; accO[2][3] += p2 * vv.w;
            accO[3][0] += p3 * vv.x; accO[3][1] += p3 * vv.y; accO[3][2] += p3 * vv.z; accO[3][3] += p3 * vv.w;
        }
    }

#pragma unroll
    for (int i = 0; i < 4; i++) {
        float invl = 1.f / l[i];
        // output feeds the wo GEMM as A-operand: round to tf32 here
        float4 ov = make_float4(to_tf32(accO[i][0] * invl), to_tf32(accO[i][1] * invl),
                                to_tf32(accO[i][2] * invl), to_tf32(accO[i][3] * invl));
        *(float4*)(o + base + (size_t)(qt * 64 + r0 + i) * DIMC + c0) = ov;
    }
}

// ---------------- combine: hidden residual + pyramid-weighted window blend -----
__global__ __launch_bounds__(256) void combine_hidden_kernel(
    const float* __restrict__ hs, float* __restrict__ out)
{
    int gidx = blockIdx.x;               // 0..NTOK-1
    int tid  = threadIdx.x;
    int blk  = gidx / SROW;              // 0..5
    float acc[4] = {0.f, 0.f, 0.f, 0.f};
    float wsum = 0.f;
#pragma unroll
    for (int dw = -1; dw <= 0; dw++) {
        int w = blk + dw;
        if (w < 0 || w > 4) continue;
        int lv = gidx - w * SROW;        // in [0, LVV)
        float wt = c_pyr[lv / 144];
        wsum += wt;
        const float* op = g_o2 + ((size_t)w * LWIN + TENC + lv) * DIMC;
#pragma unroll
        for (int i = 0; i < 4; i++) acc[i] += wt * op[tid + i * 256];
    }
    float inv = 1.f / wsum;
#pragma unroll
    for (int i = 0; i < 4; i++) {
        int d = tid + i * 256;
        out[(size_t)gidx * DIMC + d] =
            hs[(size_t)gidx * DIMC + d] + g_emb1[2048 + d] * acc[i] * inv;
    }
}

// ---------------- combine: enc residual + mean over windows ----------------
__global__ __launch_bounds__(256) void combine_enc_kernel(
    const float* __restrict__ enc, float* __restrict__ out)
{
    int t = blockIdx.x; int tid = threadIdx.x;
#pragma unroll
    for (int i = 0; i < 4; i++) {
        int d = tid + i * 256;
        float a = 0.f;
#pragma unroll
        for (int w = 0; w < WQN; w++)
            a += g_o2[((size_t)w * LWIN + t) * DIMC + d];
        out[(size_t)t * DIMC + d] =
            enc[(size_t)t * DIMC + d] + g_emb1[5120 + d] * a * 0.2f;
    }
}

// ---------------- build ff_in = [mod-LN2(enc_new); mod-LN2(hidden_new)] --------
__global__ __launch_bounds__(256) void build_ffin_kernel(
    const float* __restrict__ dout,
    const float* __restrict__ g, const float* __restrict__ b)
{
    int row = blockIdx.x;                // 0..MFF-1
    const float* src; int sc_off, sh_off;
    if (row < TENC) { src = dout + (size_t)NTOK * DIMC + (size_t)row * DIMC; sc_off = 4096; sh_off = 3072; }
    else            { src = dout + (size_t)(row - TENC) * DIMC;              sc_off = 1024; sh_off = 0;    }
    int tid = threadIdx.x;
    float x[4]; float s = 0.f, s2 = 0.f;
#pragma unroll
    for (int i = 0; i < 4; i++) {
        x[i] = src[tid + i * 256];
        s += x[i]; s2 += x[i] * x[i];
    }
    block_reduce_2(s, s2);
    float mean = s * (1.f / DIMC);
    float var  = s2 * (1.f / DIMC) - mean * mean;
    float inv  = rsqrtf(var + 1e-5f);
    float* dst = g_ffin + (size_t)row * DIMC;
#pragma unroll
    for (int i = 0; i < 4; i++) {
        int d = tid + i * 256;
        float v = (x[i] - mean) * inv * g[d] + b[d];
        dst[d] = to_tf32(v * (1.f + g_emb2[sc_off + d]) + g_emb2[sh_off + d]);
    }
}

// ---------------- final residual add --------------------------------------
__global__ __launch_bounds__(256) void final_add_kernel(float* __restrict__ dout)
{
    int row = blockIdx.x;                // 0..MFF-1
    int tid = threadIdx.x;
    if (row < TENC) {
        float* p = dout + (size_t)NTOK * DIMC + (size_t)row * DIMC;
#pragma unroll
        for (int i = 0; i < 4; i++) {
            int d = tid + i * 256;
            p[d] += g_emb2[5120 + d] * g_ffout[(size_t)row * DIMC + d];
        }
    } else {
        float* p = dout + (size_t)(row - TENC) * DIMC;
#pragma unroll
        for (int i = 0; i < 4; i++) {
            int d = tid + i * 256;
            p[d] += g_emb2[2048 + d] * g_ffout[(size_t)row * DIMC + d];
        }
    }
}

// ---------------- host side ----------------
static void launch_gemm(const float* A, const float* B, const float* bias,
                        float* C, int M, int N, int K, int flags)
{
    dim3 grid(N / 128, M / 128);
    size_t smem = (size_t)2 * STAGE_F * sizeof(float);
    gemm_tc_kernel<<<grid, 256, smem>>>(A, B, bias, C, M, N, K, flags);
}

extern "C" void kernel_launch(void* const* d_in, const int* in_sizes, int n_in,
                              void* d_out, int out_size)
{
    const float* hs    = (const float*)d_in[0];
    const float* enc   = (const float*)d_in[1];
    const float* temb  = (const float*)d_in[2];
    const float* n1w   = (const float*)d_in[3];
    const float* n1b   = (const float*)d_in[4];
    const float* n1g   = (const float*)d_in[5];
    const float* n1bb  = (const float*)d_in[6];
    const float* wq    = (const float*)d_in[7];
    const float* wk    = (const float*)d_in[8];
    const float* wv    = (const float*)d_in[9];
    const float* nqg   = (const float*)d_in[10];
    const float* nqb   = (const float*)d_in[11];
    const float* nkg   = (const float*)d_in[12];
    const float* nkb   = (const float*)d_in[13];
    const float* wo    = (const float*)d_in[14];
    const float* bo    = (const float*)d_in[15];
    const float* n2w   = (const float*)d_in[16];
    const float* n2b   = (const float*)d_in[17];
    const float* n2g   = (const float*)d_in[18];
    const float* n2bb  = (const float*)d_in[19];
    const float* ffw1  = (const float*)d_in[20];
    const float* ffb1  = (const float*)d_in[21];
    const float* ffw2  = (const float*)d_in[22];
    const float* ffb2  = (const float*)d_in[23];
    (void)in_sizes; (void)n_in;

    float* out = (float*)d_out;
    float* out_hidden = out;                           // [NTOK, DIMC]
    float* out_enc    = out + (size_t)NTOK * DIMC;     // [TENC, DIMC]
    (void)out_size;

    float *p_x, *p_q, *p_k, *p_v, *p_ao, *p_o2, *p_ffin, *p_h1, *p_ffout, *p_wr;
    cudaGetSymbolAddress((void**)&p_x,    g_x);
    cudaGetSymbolAddress((void**)&p_q,    g_q);
    cudaGetSymbolAddress((void**)&p_k,    g_k);
    cudaGetSymbolAddress((void**)&p_v,    g_v);
    cudaGetSymbolAddress((void**)&p_ao,   g_ao);
    cudaGetSymbolAddress((void**)&p_o2,   g_o2);
    cudaGetSymbolAddress((void**)&p_ffin, g_ffin);
    cudaGetSymbolAddress((void**)&p_h1,   g_h1);
    cudaGetSymbolAddress((void**)&p_ffout,g_ffout);
    cudaGetSymbolAddress((void**)&p_wr,   g_wr);

    float* wq_r = p_wr;
    float* wk_r = p_wr + (size_t)1 * MEG;
    float* wv_r = p_wr + (size_t)2 * MEG;
    float* wo_r = p_wr + (size_t)3 * MEG;
    float* w1_r = p_wr + (size_t)4 * MEG;
    float* w2_r = p_wr + (size_t)8 * MEG;

    const int ATTN_SMEM = (4096 + 64 * 68 + 64 * 64) * 4;  // 50176 B
    cudaFuncSetAttribute(attn_kernel, cudaFuncAttributeMaxDynamicSharedMemorySize, ATTN_SMEM);
    const int GEMM_SMEM = 2 * STAGE_F * sizeof(float);     // 70656 B
    cudaFuncSetAttribute(gemm_tc_kernel, cudaFuncAttributeMaxDynamicSharedMemorySize, GEMM_SMEM);

    // 0. round weights to tf32 once
    round_w_kernel<<<MEG / 1024, 256>>>((const float4*)wq,   (float4*)wq_r, MEG / 4);
    round_w_kernel<<<MEG / 1024, 256>>>((const float4*)wk,   (float4*)wk_r, MEG / 4);
    round_w_kernel<<<MEG / 1024, 256>>>((const float4*)wv,   (float4*)wv_r, MEG / 4);
    round_w_kernel<<<MEG / 1024, 256>>>((const float4*)wo,   (float4*)wo_r, MEG / 4);
    round_w_kernel<<<4 * MEG / 1024, 256>>>((const float4*)ffw1, (float4*)w1_r, MEG);
    round_w_kernel<<<4 * MEG / 1024, 256>>>((const float4*)ffw2, (float4*)w2_r, MEG);

    // 1. modulation embeddings
    emb_kernel<<<48, 256>>>(temb, n1w, n1b, n2w, n2b);
    // 2. x = modulated LN of [enc ; gathered chunks] (tf32)
    build_x_kernel<<<MQ, 256>>>(hs, enc, n1g, n1bb);
    // 3. qkv projections (tensor cores)
    launch_gemm(p_x, wq_r, nullptr, p_q, MQ, DIMC, DIMC, 0);
    launch_gemm(p_x, wk_r, nullptr, p_k, MQ, DIMC, DIMC, 0);
    launch_gemm(p_x, wv_r, nullptr, p_v, MQ, DIMC, DIMC, 0);
    // 4. per-head LN on q, k
    qkln_kernel<<<MQ * HEADS_ / 8, 256>>>(p_q, nqg, nqb);
    qkln_kernel<<<MQ * HEADS_ / 8, 256>>>(p_k, nkg, nkb);
    // 5. attention
    attn_kernel<<<dim3(LWIN / 64, HEADS_, WQN), 256, ATTN_SMEM>>>(p_q, p_k, p_v, p_ao);
    // 6. output projection
    launch_gemm(p_ao, wo_r, bo, p_o2, MQ, DIMC, DIMC, 0);
    // 7. residual + window blending
    combine_hidden_kernel<<<NTOK, 256>>>(hs, out_hidden);
    combine_enc_kernel<<<TENC, 256>>>(enc, out_enc);
    // 8. FFN (tensor cores; ffn1 output rounded for ffn2 A-operand)
    build_ffin_kernel<<<MFF, 256>>>(out, n2g, n2bb);
    launch_gemm(p_ffin, w1_r, ffb1, p_h1, MFF, 4096, DIMC, 1 | 2);
    launch_gemm(p_h1, w2_r, ffb2, p_ffout, MFF, DIMC, 4096, 0);
    // 9. final gated residual
    final_add_kernel<<<MFF, 256>>>(out);
}

// round 5
// speedup vs baseline: 3.0869x; 1.5401x over previous
#include <cuda_runtime.h>
#include <math.h>
#include <stdint.h>

// ---------------- constants ----------------
#define DIMC   1024
#define TEMBC  512
#define NTOK   3456     // NF*S = 24*144
#define TENC   128      // T
#define WQN    5        // number of windows
#define LWIN   1280     // T + CL*S
#define LVV    1152     // CL*S
#define SROW   576      // STRIDE*S
#define MQ     6400     // WQN*LWIN
#define MFF    3584     // TENC + NTOK
#define HEADS_ 16
#define HD_    64

#define MEG 1048576

// ---------------- device scratch ----------------
__device__ float g_emb1[6144];
__device__ float g_emb2[6144];
__device__ float g_x  [(size_t)MQ * DIMC];
__device__ float g_q  [(size_t)MQ * DIMC];
__device__ float g_k  [(size_t)MQ * DIMC];
__device__ float g_v  [(size_t)MQ * DIMC];
__device__ float g_ao [(size_t)MQ * DIMC];
__device__ float g_o2 [(size_t)MQ * DIMC];
__device__ float g_ffin [(size_t)MFF * DIMC];
__device__ float g_h1   [(size_t)MFF * 4096];
__device__ float g_ffout[(size_t)MFF * DIMC];
__device__ float g_wr  [(size_t)12 * MEG];   // rounded weights

__constant__ float c_pyr[8] = {1.f,2.f,3.f,4.f,4.f,3.f,2.f,1.f};

// ---------------- helpers ----------------
__device__ __forceinline__ float to_tf32(float x) {
    uint32_t u;
    asm("cvt.rna.tf32.f32 %0, %1;" : "=r"(u) : "f"(x));
    return __uint_as_float(u);
}

__device__ __forceinline__ void block_reduce_2(float &s, float &s2) {
    __shared__ float ra[8], rb[8];
#pragma unroll
    for (int m = 16; m > 0; m >>= 1) {
        s  += __shfl_xor_sync(0xffffffffu, s,  m);
        s2 += __shfl_xor_sync(0xffffffffu, s2, m);
    }
    int wid = threadIdx.x >> 5;
    if ((threadIdx.x & 31) == 0) { ra[wid] = s; rb[wid] = s2; }
    __syncthreads();
    s  = ra[0]+ra[1]+ra[2]+ra[3]+ra[4]+ra[5]+ra[6]+ra[7];
    s2 = rb[0]+rb[1]+rb[2]+rb[3]+rb[4]+rb[5]+rb[6]+rb[7];
    __syncthreads();
}

__device__ __forceinline__ float gelu_tanh(float x) {
    float x3 = x * x * x;
    return 0.5f * x * (1.f + tanhf(0.79788456080286535588f * (x + 0.044715f * x3)));
}

__device__ __forceinline__ void mma_tf32(float* d, const uint32_t* a, const uint32_t* b) {
    asm volatile(
        "mma.sync.aligned.m16n8k8.row.col.f32.tf32.tf32.f32 "
        "{%0,%1,%2,%3}, {%4,%5,%6,%7}, {%8,%9}, {%0,%1,%2,%3};"
        : "+f"(d[0]), "+f"(d[1]), "+f"(d[2]), "+f"(d[3])
        : "r"(a[0]), "r"(a[1]), "r"(a[2]), "r"(a[3]), "r"(b[0]), "r"(b[1]));
}

// ---------------- round weights to tf32 (one pass) ----------------
__global__ __launch_bounds__(256) void round_w_kernel(const float4* __restrict__ src,
                                                      float4* __restrict__ dst, int n4)
{
    int i = blockIdx.x * 256 + threadIdx.x;
    if (i >= n4) return;
    float4 v = src[i];
    v.x = to_tf32(v.x); v.y = to_tf32(v.y); v.z = to_tf32(v.z); v.w = to_tf32(v.w);
    dst[i] = v;
}

// ---------------- emb = silu(temb) @ W + b (both emb1, emb2) ----------------
__global__ __launch_bounds__(256) void emb_kernel(
    const float* __restrict__ temb,
    const float* __restrict__ w1, const float* __restrict__ b1,
    const float* __restrict__ w2, const float* __restrict__ b2)
{
    __shared__ float st[TEMBC];
    int tid = threadIdx.x;
    for (int i = tid; i < TEMBC; i += 256) {
        float t = temb[i];
        st[i] = t / (1.f + expf(-t));
    }
    __syncthreads();
    int j = blockIdx.x * 256 + tid;  // 0..12287
    const float* w; const float* bb; float* out; int col;
    if (j < 6144) { w = w1; bb = b1; out = g_emb1; col = j; }
    else          { w = w2; bb = b2; out = g_emb2; col = j - 6144; }
    float acc = 0.f;
#pragma unroll 8
    for (int kk = 0; kk < TEMBC; kk++)
        acc += st[kk] * w[(size_t)kk * 6144 + col];
    out[col] = acc + bb[col];
}

// ---------------- build x = [mod-LN(enc); mod-LN(chunks)]  (tf32-rounded) -----
__global__ __launch_bounds__(256) void build_x_kernel(
    const float* __restrict__ hs, const float* __restrict__ enc,
    const float* __restrict__ g, const float* __restrict__ b)
{
    int row = blockIdx.x;               // 0..MQ-1
    int w = row / LWIN, l = row % LWIN;
    const float* src; int sc_off, sh_off;
    if (l < TENC) { src = enc + (size_t)l * DIMC; sc_off = 4096; sh_off = 3072; }
    else {
        int gidx = w * SROW + (l - TENC);
        src = hs + (size_t)gidx * DIMC; sc_off = 1024; sh_off = 0;
    }
    int tid = threadIdx.x;
    float x[4]; float s = 0.f, s2 = 0.f;
#pragma unroll
    for (int i = 0; i < 4; i++) {
        x[i] = src[tid + i * 256];
        s += x[i]; s2 += x[i] * x[i];
    }
    block_reduce_2(s, s2);
    float mean = s * (1.f / DIMC);
    float var  = s2 * (1.f / DIMC) - mean * mean;
    float inv  = rsqrtf(var + 1e-5f);
    float* dst = g_x + (size_t)row * DIMC;
#pragma unroll
    for (int i = 0; i < 4; i++) {
        int d = tid + i * 256;
        float v = (x[i] - mean) * inv * g[d] + b[d];
        dst[d] = to_tf32(v * (1.f + g_emb1[sc_off + d]) + g_emb1[sh_off + d]);
    }
}

// ---------------- TF32 tensor-core GEMM ----------------
#define BM 128
#define BN 128
#define BK 32
#define ASTR 36
#define BSTR 132
#define STAGE_F (BM * ASTR + BK * BSTR)   // 8832 floats per stage

__global__ __launch_bounds__(256, 2) void gemm_tc_kernel(
    const float* __restrict__ A, const float* __restrict__ B,
    const float* __restrict__ bias, float* __restrict__ C,
    int M, int N, int K, int flags)
{
    extern __shared__ float sm[];
    float* As0 = sm;
    float* Bs0 = sm + (size_t)2 * BM * ASTR;

    int tid = threadIdx.x;
    int bm = blockIdx.y, bn = blockIdx.x;
    int lane = tid & 31, wid = tid >> 5;
    int wm = (wid & 1) * 64, wn = (wid >> 1) * 32;
    int gid = lane >> 2, tig = lane & 3;

    const float* Ag = A + (size_t)bm * BM * K;
    const float* Bg = B + (size_t)bn * BN;

    float acc[4][4][4];
#pragma unroll
    for (int a = 0; a < 4; a++)
#pragma unroll
        for (int b = 0; b < 4; b++)
#pragma unroll
            for (int c = 0; c < 4; c++) acc[a][b][c] = 0.f;

#define LOAD_TILE(kt, buf)                                                        \
    {                                                                             \
        float* ad = As0 + (buf) * BM * ASTR;                                      \
        const float* asrc = Ag + (kt) * BK;                                       \
        _Pragma("unroll")                                                         \
        for (int i = 0; i < 4; i++) {                                             \
            int c = tid + i * 256;                                                \
            int r = c >> 3, kc = (c & 7) << 2;                                    \
            uint32_t dsm = (uint32_t)__cvta_generic_to_shared(ad + r * ASTR + kc);\
            const float* s = asrc + (size_t)r * K + kc;                           \
            asm volatile("cp.async.cg.shared.global [%0], [%1], 16;"              \
                         :: "r"(dsm), "l"(s));                                    \
        }                                                                         \
        float* bd = Bs0 + (buf) * BK * BSTR;                                      \
        const float* bsrc = Bg + (size_t)(kt) * BK * N;                           \
        _Pragma("unroll")                                                         \
        for (int i = 0; i < 4; i++) {                                             \
            int c = tid + i * 256;                                                \
            int r = c >> 5, nc = (c & 31) << 2;                                   \
            uint32_t dsm = (uint32_t)__cvta_generic_to_shared(bd + r * BSTR + nc);\
            const float* s = bsrc + (size_t)r * N + nc;                           \
            asm volatile("cp.async.cg.shared.global [%0], [%1], 16;"              \
                         :: "r"(dsm), "l"(s));                                    \
        }                                                                         \
    }

    LOAD_TILE(0, 0);
    asm volatile("cp.async.commit_group;");

    int ktiles = K / BK;
    for (int t = 0; t < ktiles; t++) {
        int buf = t & 1;
        if (t + 1 < ktiles) {
            LOAD_TILE(t + 1, buf ^ 1);
            asm volatile("cp.async.commit_group;");
            asm volatile("cp.async.wait_group 1;");
        } else {
            asm volatile("cp.async.wait_group 0;");
        }
        __syncthreads();

        const float* Ab = As0 + buf * BM * ASTR;
        const float* Bb = Bs0 + buf * BK * BSTR;
#pragma unroll
        for (int ks = 0; ks < 4; ks++) {
            int k0 = ks * 8;
            uint32_t af[4][4], bf[4][2];
#pragma unroll
            for (int mt = 0; mt < 4; mt++) {
                const float* ap = Ab + (wm + mt * 16 + gid) * ASTR + k0 + tig;
                af[mt][0] = __float_as_uint(ap[0]);
                af[mt][1] = __float_as_uint(ap[8 * ASTR]);
                af[mt][2] = __float_as_uint(ap[4]);
                af[mt][3] = __float_as_uint(ap[8 * ASTR + 4]);
            }
#pragma unroll
            for (int nt = 0; nt < 4; nt++) {
                const float* bp = Bb + (k0 + tig) * BSTR + wn + nt * 8 + gid;
                bf[nt][0] = __float_as_uint(bp[0]);
                bf[nt][1] = __float_as_uint(bp[4 * BSTR]);
            }
#pragma unroll
            for (int mt = 0; mt < 4; mt++)
#pragma unroll
                for (int nt = 0; nt < 4; nt++)
                    mma_tf32(acc[mt][nt], af[mt], bf[nt]);
        }
        __syncthreads();
    }

    int act = flags & 1, rnd = flags & 2;
#pragma unroll
    for (int mt = 0; mt < 4; mt++) {
        int row = bm * BM + wm + mt * 16 + gid;
#pragma unroll
        for (int nt = 0; nt < 4; nt++) {
            int col = bn * BN + wn + nt * 8 + tig * 2;
            float b0 = bias ? bias[col] : 0.f;
            float b1 = bias ? bias[col + 1] : 0.f;
            float v0 = acc[mt][nt][0] + b0, v1 = acc[mt][nt][1] + b1;
            float v2 = acc[mt][nt][2] + b0, v3 = acc[mt][nt][3] + b1;
            if (act) { v0 = gelu_tanh(v0); v1 = gelu_tanh(v1); v2 = gelu_tanh(v2); v3 = gelu_tanh(v3); }
            if (rnd) { v0 = to_tf32(v0); v1 = to_tf32(v1); v2 = to_tf32(v2); v3 = to_tf32(v3); }
            float2 lo = make_float2(v0, v1), hi = make_float2(v2, v3);
            *(float2*)(C + (size_t)row * N + col)       = lo;
            *(float2*)(C + (size_t)(row + 8) * N + col) = hi;
        }
    }
}

// ---------------- per-head LN on q/k (eps 1e-6), outputs tf32-rounded ---------
__global__ __launch_bounds__(256) void qkln_kernel(
    float* __restrict__ buf, const float* __restrict__ g, const float* __restrict__ b)
{
    int seg  = blockIdx.x * 8 + (threadIdx.x >> 5);  // 0..MQ*16-1
    int lane = threadIdx.x & 31;
    float* p = buf + (size_t)(seg >> 4) * DIMC + (seg & 15) * HD_;
    float x0 = p[lane], x1 = p[lane + 32];
    float s = x0 + x1, s2 = x0 * x0 + x1 * x1;
#pragma unroll
    for (int m = 16; m > 0; m >>= 1) {
        s  += __shfl_xor_sync(0xffffffffu, s,  m);
        s2 += __shfl_xor_sync(0xffffffffu, s2, m);
    }
    float mean = s * (1.f / 64.f);
    float var  = s2 * (1.f / 64.f) - mean * mean;
    float inv  = rsqrtf(var + 1e-6f);
    p[lane]      = to_tf32((x0 - mean) * inv * g[lane]      + b[lane]);
    p[lane + 32] = to_tf32((x1 - mean) * inv * g[lane + 32] + b[lane + 32]);
}

// ---------------- TF32 tensor-core flash attention ----------------
// block: 256 threads (8 warps), 128 Q rows; K/V tiles of 64 rows; 20 tiles.
#define QSTR 68
#define KSTR 68
#define VSTR 72
#define ATTN_SMEM_F (128 * QSTR + 64 * KSTR + 64 * VSTR)   // 17664 floats

__global__ __launch_bounds__(256, 2) void attn_tc_kernel(
    const float* __restrict__ q, const float* __restrict__ k,
    const float* __restrict__ v, float* __restrict__ o)
{
    extern __shared__ float sm[];
    float* Qs = sm;                      // 128 x QSTR
    float* Ks = sm + 128 * QSTR;         // 64 x KSTR  (row = k-token, col = d)
    float* Vs = Ks + 64 * KSTR;          // 64 x VSTR  (row = k-token, col = d)

    int qt = blockIdx.x, h = blockIdx.y, w = blockIdx.z;
    int tid = threadIdx.x, lane = tid & 31, wid = tid >> 5;
    int gid = lane >> 2, tig = lane & 3;
    int wq0 = wid * 16;
    const size_t base = (size_t)w * LWIN * DIMC + (size_t)h * HD_;
    const float* qg = q + base + (size_t)qt * 128 * DIMC;

    // load Q tile (scale by 1/8, exact in tf32)
#pragma unroll
    for (int i = 0; i < 8; i++) {
        int e = tid + i * 256;           // 2048 float4
        int r = e >> 4, d4 = (e & 15) * 4;
        float4 t4 = *(const float4*)(qg + (size_t)r * DIMC + d4);
        float* dst = Qs + r * QSTR + d4;
        dst[0] = t4.x * 0.125f; dst[1] = t4.y * 0.125f;
        dst[2] = t4.z * 0.125f; dst[3] = t4.w * 0.125f;
    }

    float accO[8][4];
#pragma unroll
    for (int nt = 0; nt < 8; nt++)
#pragma unroll
        for (int i = 0; i < 4; i++) accO[nt][i] = 0.f;
    float m0 = -1e30f, m1 = -1e30f, l0 = 0.f, l1 = 0.f;

    for (int kt = 0; kt < 20; kt++) {
        __syncthreads();
#pragma unroll
        for (int i = 0; i < 4; i++) {
            int e = tid + i * 256;       // 1024 float4
            int r = e >> 4, d4 = (e & 15) * 4;
            size_t gi = base + (size_t)(kt * 64 + r) * DIMC + d4;
            float4 kk = *(const float4*)(k + gi);
            float4 vv = *(const float4*)(v + gi);
            float* kd = Ks + r * KSTR + d4;
            kd[0] = kk.x; kd[1] = kk.y; kd[2] = kk.z; kd[3] = kk.w;
            float* vd = Vs + r * VSTR + d4;
            vd[0] = vv.x; vd[1] = vv.y; vd[2] = vv.z; vd[3] = vv.w;
        }
        __syncthreads();

        // S = Q * K^T  (each warp: 16 rows x 64 cols)
        float s[8][4];
#pragma unroll
        for (int nt = 0; nt < 8; nt++)
#pragma unroll
            for (int i = 0; i < 4; i++) s[nt][i] = 0.f;

#pragma unroll
        for (int ks = 0; ks < 8; ks++) {
            int k0 = ks * 8;
            uint32_t af[4];
            const float* ap = Qs + (wq0 + gid) * QSTR + k0 + tig;
            af[0] = __float_as_uint(ap[0]);
            af[1] = __float_as_uint(ap[8 * QSTR]);
            af[2] = __float_as_uint(ap[4]);
            af[3] = __float_as_uint(ap[8 * QSTR + 4]);
#pragma unroll
            for (int nt = 0; nt < 8; nt++) {
                uint32_t bf[2];
                const float* bp = Ks + (nt * 8 + gid) * KSTR + k0 + tig;
                bf[0] = __float_as_uint(bp[0]);
                bf[1] = __float_as_uint(bp[4]);
                mma_tf32(s[nt], af, bf);
            }
        }

        // online softmax (rows gid and gid+8 of this warp's 16-row block)
        float mx0 = -1e30f, mx1 = -1e30f;
#pragma unroll
        for (int nt = 0; nt < 8; nt++) {
            mx0 = fmaxf(mx0, fmaxf(s[nt][0], s[nt][1]));
            mx1 = fmaxf(mx1, fmaxf(s[nt][2], s[nt][3]));
        }
        mx0 = fmaxf(mx0, __shfl_xor_sync(0xffffffffu, mx0, 1));
        mx0 = fmaxf(mx0, __shfl_xor_sync(0xffffffffu, mx0, 2));
        mx1 = fmaxf(mx1, __shfl_xor_sync(0xffffffffu, mx1, 1));
        mx1 = fmaxf(mx1, __shfl_xor_sync(0xffffffffu, mx1, 2));
        float mn0 = fmaxf(m0, mx0), mn1 = fmaxf(m1, mx1);
        float f0 = __expf(m0 - mn0), f1 = __expf(m1 - mn1);
        m0 = mn0; m1 = mn1;
        float sum0 = 0.f, sum1 = 0.f;
#pragma unroll
        for (int nt = 0; nt < 8; nt++) {
            s[nt][0] = to_tf32(__expf(s[nt][0] - mn0));
            s[nt][1] = to_tf32(__expf(s[nt][1] - mn0));
            s[nt][2] = to_tf32(__expf(s[nt][2] - mn1));
            s[nt][3] = to_tf32(__expf(s[nt][3] - mn1));
            sum0 += s[nt][0] + s[nt][1];
            sum1 += s[nt][2] + s[nt][3];
        }
        sum0 += __shfl_xor_sync(0xffffffffu, sum0, 1);
        sum0 += __shfl_xor_sync(0xffffffffu, sum0, 2);
        sum1 += __shfl_xor_sync(0xffffffffu, sum1, 1);
        sum1 += __shfl_xor_sync(0xffffffffu, sum1, 2);
        l0 = l0 * f0 + sum0;
        l1 = l1 * f1 + sum1;
#pragma unroll
        for (int nt = 0; nt < 8; nt++) {
            accO[nt][0] *= f0; accO[nt][1] *= f0;
            accO[nt][2] *= f1; accO[nt][3] *= f1;
        }

        // O += P * V ; convert C-frag (cols {2t,2t+1}) -> A-frag (cols {t,t+4})
        // via intra-quad shuffles.
#pragma unroll
        for (int kc = 0; kc < 8; kc++) {
            int srcA = (lane & 28) + (tig >> 1);   // gid*4 + tig/2
            int srcB = srcA + 2;
            float w0a = __shfl_sync(0xffffffffu, s[kc][0], srcA);
            float w1a = __shfl_sync(0xffffffffu, s[kc][1], srcA);
            float w2a = __shfl_sync(0xffffffffu, s[kc][2], srcA);
            float w3a = __shfl_sync(0xffffffffu, s[kc][3], srcA);
            float w0b = __shfl_sync(0xffffffffu, s[kc][0], srcB);
            float w1b = __shfl_sync(0xffffffffu, s[kc][1], srcB);
            float w2b = __shfl_sync(0xffffffffu, s[kc][2], srcB);
            float w3b = __shfl_sync(0xffffffffu, s[kc][3], srcB);
            bool odd = tig & 1;
            uint32_t af[4];
            af[0] = __float_as_uint(odd ? w1a : w0a);   // P[gid][tig]
            af[1] = __float_as_uint(odd ? w3a : w2a);   // P[gid+8][tig]
            af[2] = __float_as_uint(odd ? w1b : w0b);   // P[gid][tig+4]
            af[3] = __float_as_uint(odd ? w3b : w2b);   // P[gid+8][tig+4]
#pragma unroll
            for (int nt = 0; nt < 8; nt++) {
                uint32_t bf[2];
                const float* bp = Vs + (kc * 8 + tig) * VSTR + nt * 8 + gid;
                bf[0] = __float_as_uint(bp[0]);
                bf[1] = __float_as_uint(bp[4 * VSTR]);
                mma_tf32(accO[nt], af, bf);
            }
        }
    }

    // epilogue: normalize, round to tf32 (feeds wo GEMM), store
    float il0 = 1.f / l0, il1 = 1.f / l1;
    int row0 = qt * 128 + wq0 + gid;
#pragma unroll
    for (int nt = 0; nt < 8; nt++) {
        int col = nt * 8 + tig * 2;
        float2 a = make_float2(to_tf32(accO[nt][0] * il0), to_tf32(accO[nt][1] * il0));
        float2 b = make_float2(to_tf32(accO[nt][2] * il1), to_tf32(accO[nt][3] * il1));
        *(float2*)(o + base + (size_t)row0 * DIMC + col)       = a;
        *(float2*)(o + base + (size_t)(row0 + 8) * DIMC + col) = b;
    }
}

// ---------------- combine: hidden residual + pyramid-weighted window blend -----
__global__ __launch_bounds__(256) void combine_hidden_kernel(
    const float* __restrict__ hs, float* __restrict__ out)
{
    int gidx = blockIdx.x;               // 0..NTOK-1
    int tid  = threadIdx.x;
    int blk  = gidx / SROW;              // 0..5
    float acc[4] = {0.f, 0.f, 0.f, 0.f};
    float wsum = 0.f;
#pragma unroll
    for (int dw = -1; dw <= 0; dw++) {
        int w = blk + dw;
        if (w < 0 || w > 4) continue;
        int lv = gidx - w * SROW;        // in [0, LVV)
        float wt = c_pyr[lv / 144];
        wsum += wt;
        const float* op = g_o2 + ((size_t)w * LWIN + TENC + lv) * DIMC;
#pragma unroll
        for (int i = 0; i < 4; i++) acc[i] += wt * op[tid + i * 256];
    }
    float inv = 1.f / wsum;
#pragma unroll
    for (int i = 0; i < 4; i++) {
        int d = tid + i * 256;
        out[(size_t)gidx * DIMC + d] =
            hs[(size_t)gidx * DIMC + d] + g_emb1[2048 + d] * acc[i] * inv;
    }
}

// ---------------- combine: enc residual + mean over windows ----------------
__global__ __launch_bounds__(256) void combine_enc_kernel(
    const float* __restrict__ enc, float* __restrict__ out)
{
    int t = blockIdx.x; int tid = threadIdx.x;
#pragma unroll
    for (int i = 0; i < 4; i++) {
        int d = tid + i * 256;
        float a = 0.f;
#pragma unroll
        for (int w = 0; w < WQN; w++)
            a += g_o2[((size_t)w * LWIN + t) * DIMC + d];
        out[(size_t)t * DIMC + d] =
            enc[(size_t)t * DIMC + d] + g_emb1[5120 + d] * a * 0.2f;
    }
}

// ---------------- build ff_in = [mod-LN2(enc_new); mod-LN2(hidden_new)] --------
__global__ __launch_bounds__(256) void build_ffin_kernel(
    const float* __restrict__ dout,
    const float* __restrict__ g, const float* __restrict__ b)
{
    int row = blockIdx.x;                // 0..MFF-1
    const float* src; int sc_off, sh_off;
    if (row < TENC) { src = dout + (size_t)NTOK * DIMC + (size_t)row * DIMC; sc_off = 4096; sh_off = 3072; }
    else            { src = dout + (size_t)(row - TENC) * DIMC;              sc_off = 1024; sh_off = 0;    }
    int tid = threadIdx.x;
    float x[4]; float s = 0.f, s2 = 0.f;
#pragma unroll
    for (int i = 0; i < 4; i++) {
        x[i] = src[tid + i * 256];
        s += x[i]; s2 += x[i] * x[i];
    }
    block_reduce_2(s, s2);
    float mean = s * (1.f / DIMC);
    float var  = s2 * (1.f / DIMC) - mean * mean;
    float inv  = rsqrtf(var + 1e-5f);
    float* dst = g_ffin + (size_t)row * DIMC;
#pragma unroll
    for (int i = 0; i < 4; i++) {
        int d = tid + i * 256;
        float v = (x[i] - mean) * inv * g[d] + b[d];
        dst[d] = to_tf32(v * (1.f + g_emb2[sc_off + d]) + g_emb2[sh_off + d]);
    }
}

// ---------------- final residual add --------------------------------------
__global__ __launch_bounds__(256) void final_add_kernel(float* __restrict__ dout)
{
    int row = blockIdx.x;                // 0..MFF-1
    int tid = threadIdx.x;
    if (row < TENC) {
        float* p = dout + (size_t)NTOK * DIMC + (size_t)row * DIMC;
#pragma unroll
        for (int i = 0; i < 4; i++) {
            int d = tid + i * 256;
            p[d] += g_emb2[5120 + d] * g_ffout[(size_t)row * DIMC + d];
        }
    } else {
        float* p = dout + (size_t)(row - TENC) * DIMC;
#pragma unroll
        for (int i = 0; i < 4; i++) {
            int d = tid + i * 256;
            p[d] += g_emb2[2048 + d] * g_ffout[(size_t)row * DIMC + d];
        }
    }
}

// ---------------- host side ----------------
static void launch_gemm(const float* A, const float* B, const float* bias,
                        float* C, int M, int N, int K, int flags)
{
    dim3 grid(N / 128, M / 128);
    size_t smem = (size_t)2 * STAGE_F * sizeof(float);
    gemm_tc_kernel<<<grid, 256, smem>>>(A, B, bias, C, M, N, K, flags);
}

extern "C" void kernel_launch(void* const* d_in, const int* in_sizes, int n_in,
                              void* d_out, int out_size)
{
    const float* hs    = (const float*)d_in[0];
    const float* enc   = (const float*)d_in[1];
    const float* temb  = (const float*)d_in[2];
    const float* n1w   = (const float*)d_in[3];
    const float* n1b   = (const float*)d_in[4];
    const float* n1g   = (const float*)d_in[5];
    const float* n1bb  = (const float*)d_in[6];
    const float* wq    = (const float*)d_in[7];
    const float* wk    = (const float*)d_in[8];
    const float* wv    = (const float*)d_in[9];
    const float* nqg   = (const float*)d_in[10];
    const float* nqb   = (const float*)d_in[11];
    const float* nkg   = (const float*)d_in[12];
    const float* nkb   = (const float*)d_in[13];
    const float* wo    = (const float*)d_in[14];
    const float* bo    = (const float*)d_in[15];
    const float* n2w   = (const float*)d_in[16];
    const float* n2b   = (const float*)d_in[17];
    const float* n2g   = (const float*)d_in[18];
    const float* n2bb  = (const float*)d_in[19];
    const float* ffw1  = (const float*)d_in[20];
    const float* ffb1  = (const float*)d_in[21];
    const float* ffw2  = (const float*)d_in[22];
    const float* ffb2  = (const float*)d_in[23];
    (void)in_sizes; (void)n_in;

    float* out = (float*)d_out;
    float* out_hidden = out;                           // [NTOK, DIMC]
    float* out_enc    = out + (size_t)NTOK * DIMC;     // [TENC, DIMC]
    (void)out_size;

    float *p_x, *p_q, *p_k, *p_v, *p_ao, *p_o2, *p_ffin, *p_h1, *p_ffout, *p_wr;
    cudaGetSymbolAddress((void**)&p_x,    g_x);
    cudaGetSymbolAddress((void**)&p_q,    g_q);
    cudaGetSymbolAddress((void**)&p_k,    g_k);
    cudaGetSymbolAddress((void**)&p_v,    g_v);
    cudaGetSymbolAddress((void**)&p_ao,   g_ao);
    cudaGetSymbolAddress((void**)&p_o2,   g_o2);
    cudaGetSymbolAddress((void**)&p_ffin, g_ffin);
    cudaGetSymbolAddress((void**)&p_h1,   g_h1);
    cudaGetSymbolAddress((void**)&p_ffout,g_ffout);
    cudaGetSymbolAddress((void**)&p_wr,   g_wr);

    float* wq_r = p_wr;
    float* wk_r = p_wr + (size_t)1 * MEG;
    float* wv_r = p_wr + (size_t)2 * MEG;
    float* wo_r = p_wr + (size_t)3 * MEG;
    float* w1_r = p_wr + (size_t)4 * MEG;
    float* w2_r = p_wr + (size_t)8 * MEG;

    const int ATTN_SMEM = ATTN_SMEM_F * sizeof(float);     // 70656 B
    cudaFuncSetAttribute(attn_tc_kernel, cudaFuncAttributeMaxDynamicSharedMemorySize, ATTN_SMEM);
    const int GEMM_SMEM = 2 * STAGE_F * sizeof(float);     // 70656 B
    cudaFuncSetAttribute(gemm_tc_kernel, cudaFuncAttributeMaxDynamicSharedMemorySize, GEMM_SMEM);

    // 0. round weights to tf32 once
    round_w_kernel<<<MEG / 1024, 256>>>((const float4*)wq,   (float4*)wq_r, MEG / 4);
    round_w_kernel<<<MEG / 1024, 256>>>((const float4*)wk,   (float4*)wk_r, MEG / 4);
    round_w_kernel<<<MEG / 1024, 256>>>((const float4*)wv,   (float4*)wv_r, MEG / 4);
    round_w_kernel<<<MEG / 1024, 256>>>((const float4*)wo,   (float4*)wo_r, MEG / 4);
    round_w_kernel<<<4 * MEG / 1024, 256>>>((const float4*)ffw1, (float4*)w1_r, MEG);
    round_w_kernel<<<4 * MEG / 1024, 256>>>((const float4*)ffw2, (float4*)w2_r, MEG);

    // 1. modulation embeddings
    emb_kernel<<<48, 256>>>(temb, n1w, n1b, n2w, n2b);
    // 2. x = modulated LN of [enc ; gathered chunks] (tf32)
    build_x_kernel<<<MQ, 256>>>(hs, enc, n1g, n1bb);
    // 3. qkv projections (tensor cores); v rounded for PV mma
    launch_gemm(p_x, wq_r, nullptr, p_q, MQ, DIMC, DIMC, 0);
    launch_gemm(p_x, wk_r, nullptr, p_k, MQ, DIMC, DIMC, 0);
    launch_gemm(p_x, wv_r, nullptr, p_v, MQ, DIMC, DIMC, 2);
    // 4. per-head LN on q, k (tf32-rounded outputs)
    qkln_kernel<<<MQ * HEADS_ / 8, 256>>>(p_q, nqg, nqb);
    qkln_kernel<<<MQ * HEADS_ / 8, 256>>>(p_k, nkg, nkb);
    // 5. attention (tensor cores)
    attn_tc_kernel<<<dim3(LWIN / 128, HEADS_, WQN), 256, ATTN_SMEM>>>(p_q, p_k, p_v, p_ao);
    // 6. output projection
    launch_gemm(p_ao, wo_r, bo, p_o2, MQ, DIMC, DIMC, 0);
    // 7. residual + window blending
    combine_hidden_kernel<<<NTOK, 256>>>(hs, out_hidden);
    combine_enc_kernel<<<TENC, 256>>>(enc, out_enc);
    // 8. FFN (tensor cores; ffn1 output rounded for ffn2 A-operand)
    build_ffin_kernel<<<MFF, 256>>>(out, n2g, n2bb);
    launch_gemm(p_ffin, w1_r, ffb1, p_h1, MFF, 4096, DIMC, 1 | 2);
    launch_gemm(p_h1, w2_r, ffb2, p_ffout, MFF, DIMC, 4096, 0);
    // 9. final gated residual
    final_add_kernel<<<MFF, 256>>>(out);
}

// round 6
// speedup vs baseline: 3.4810x; 1.1277x over previous
#include <cuda_runtime.h>
#include <math.h>
#include <stdint.h>

// ---------------- constants ----------------
#define DIMC   1024
#define TEMBC  512
#define NTOK   3456     // NF*S = 24*144
#define TENC   128      // T
#define WQN    5        // number of windows
#define LWIN   1280     // T + CL*S
#define SROW   576      // STRIDE*S
#define MQ     6400     // WQN*LWIN
#define MFF    3584     // TENC + NTOK  == unique x rows
#define HEADS_ 16
#define HD_    64
#define QKVN   3072

#define MEG 1048576

// ---------------- device scratch ----------------
__device__ float g_emb1[6144];
__device__ float g_emb2[6144];
__device__ float g_x   [(size_t)MFF * DIMC];
__device__ float g_qkv [(size_t)MFF * QKVN];
__device__ float g_ao  [(size_t)MQ * DIMC];
__device__ float g_o2  [(size_t)MQ * DIMC];
__device__ float g_ffin[(size_t)MFF * DIMC];
__device__ float g_h1  [(size_t)MFF * 4096];
__device__ float g_wr  [(size_t)12 * MEG];   // wqkv(3M), wo(1M), w1(4M), w2(4M)

__constant__ float c_pyr[8] = {1.f,2.f,3.f,4.f,4.f,3.f,2.f,1.f};

// ---------------- helpers ----------------
__device__ __forceinline__ float to_tf32(float x) {
    uint32_t u;
    asm("cvt.rna.tf32.f32 %0, %1;" : "=r"(u) : "f"(x));
    return __uint_as_float(u);
}

__device__ __forceinline__ void block_reduce_2(float &s, float &s2) {
    __shared__ float ra[8], rb[8];
#pragma unroll
    for (int m = 16; m > 0; m >>= 1) {
        s  += __shfl_xor_sync(0xffffffffu, s,  m);
        s2 += __shfl_xor_sync(0xffffffffu, s2, m);
    }
    int wid = threadIdx.x >> 5;
    if ((threadIdx.x & 31) == 0) { ra[wid] = s; rb[wid] = s2; }
    __syncthreads();
    s  = ra[0]+ra[1]+ra[2]+ra[3]+ra[4]+ra[5]+ra[6]+ra[7];
    s2 = rb[0]+rb[1]+rb[2]+rb[3]+rb[4]+rb[5]+rb[6]+rb[7];
    __syncthreads();
}

__device__ __forceinline__ float gelu_tanh(float x) {
    float x3 = x * x * x;
    return 0.5f * x * (1.f + tanhf(0.79788456080286535588f * (x + 0.044715f * x3)));
}

__device__ __forceinline__ void mma_tf32(float* d, const uint32_t* a, const uint32_t* b) {
    asm volatile(
        "mma.sync.aligned.m16n8k8.row.col.f32.tf32.tf32.f32 "
        "{%0,%1,%2,%3}, {%4,%5,%6,%7}, {%8,%9}, {%0,%1,%2,%3};"
        : "+f"(d[0]), "+f"(d[1]), "+f"(d[2]), "+f"(d[3])
        : "r"(a[0]), "r"(a[1]), "r"(a[2]), "r"(a[3]), "r"(b[0]), "r"(b[1]));
}

// ---------------- weight rounding ----------------
__global__ __launch_bounds__(256) void round_w_kernel(const float4* __restrict__ src,
                                                      float4* __restrict__ dst, int n4)
{
    int i = blockIdx.x * 256 + threadIdx.x;
    if (i >= n4) return;
    float4 v = src[i];
    v.x = to_tf32(v.x); v.y = to_tf32(v.y); v.z = to_tf32(v.z); v.w = to_tf32(v.w);
    dst[i] = v;
}

// concat wq|wk|wv along N into [1024 x 3072], rounded
__global__ __launch_bounds__(256) void round_w_qkv_kernel(
    const float4* __restrict__ wq, const float4* __restrict__ wk,
    const float4* __restrict__ wv, float4* __restrict__ dst)
{
    int i = blockIdx.x * 256 + threadIdx.x;          // float4 idx in [0, MEG/4)
    int widx = blockIdx.y;
    const float4* src = widx == 0 ? wq : (widx == 1 ? wk : wv);
    float4 v = src[i];
    v.x = to_tf32(v.x); v.y = to_tf32(v.y); v.z = to_tf32(v.z); v.w = to_tf32(v.w);
    int e = i * 4;
    int k = e >> 10, col = e & 1023;
    dst[(k * QKVN + widx * 1024 + col) >> 2] = v;
}

// ---------------- emb = silu(temb) @ W + b ----------------
__global__ __launch_bounds__(256) void emb_kernel(
    const float* __restrict__ temb,
    const float* __restrict__ w1, const float* __restrict__ b1,
    const float* __restrict__ w2, const float* __restrict__ b2)
{
    __shared__ float st[TEMBC];
    int tid = threadIdx.x;
    for (int i = tid; i < TEMBC; i += 256) {
        float t = temb[i];
        st[i] = t / (1.f + expf(-t));
    }
    __syncthreads();
    int j = blockIdx.x * 256 + tid;  // 0..12287
    const float* w; const float* bb; float* out; int col;
    if (j < 6144) { w = w1; bb = b1; out = g_emb1; col = j; }
    else          { w = w2; bb = b2; out = g_emb2; col = j - 6144; }
    float acc = 0.f;
#pragma unroll 8
    for (int kk = 0; kk < TEMBC; kk++)
        acc += st[kk] * w[(size_t)kk * 6144 + col];
    out[col] = acc + bb[col];
}

// ---------------- build unique x rows: [LN(enc)(128) ; LN(hidden)(3456)] ------
__global__ __launch_bounds__(256) void build_x_kernel(
    const float* __restrict__ hs, const float* __restrict__ enc,
    const float* __restrict__ g, const float* __restrict__ b)
{
    int row = blockIdx.x;               // 0..MFF-1
    const float* src; int sc_off, sh_off;
    if (row < TENC) { src = enc + (size_t)row * DIMC; sc_off = 4096; sh_off = 3072; }
    else            { src = hs + (size_t)(row - TENC) * DIMC; sc_off = 1024; sh_off = 0; }
    int tid = threadIdx.x;
    float x[4]; float s = 0.f, s2 = 0.f;
#pragma unroll
    for (int i = 0; i < 4; i++) {
        x[i] = src[tid + i * 256];
        s += x[i]; s2 += x[i] * x[i];
    }
    block_reduce_2(s, s2);
    float mean = s * (1.f / DIMC);
    float var  = s2 * (1.f / DIMC) - mean * mean;
    float inv  = rsqrtf(var + 1e-5f);
    float* dst = g_x + (size_t)row * DIMC;
#pragma unroll
    for (int i = 0; i < 4; i++) {
        int d = tid + i * 256;
        float v = (x[i] - mean) * inv * g[d] + b[d];
        dst[d] = to_tf32(v * (1.f + g_emb1[sc_off + d]) + g_emb1[sh_off + d]);
    }
}

// ---------------- TF32 tensor-core GEMM ----------------
// flags: 1=gelu, 2=round-out-tf32, 4=ffn2-fused-final-add (C=out, RMW)
#define BM 128
#define BN 128
#define BK 32
#define ASTR 36
#define BSTR 132
#define STAGE_F (BM * ASTR + BK * BSTR)   // 8832 floats per stage

__global__ __launch_bounds__(256, 2) void gemm_tc_kernel(
    const float* __restrict__ A, const float* __restrict__ B,
    const float* __restrict__ bias, float* __restrict__ C,
    int M, int N, int K, int flags)
{
    extern __shared__ float sm[];
    float* As0 = sm;
    float* Bs0 = sm + (size_t)2 * BM * ASTR;

    int tid = threadIdx.x;
    int bm = blockIdx.y, bn = blockIdx.x;
    int lane = tid & 31, wid = tid >> 5;
    int wm = (wid & 1) * 64, wn = (wid >> 1) * 32;
    int gid = lane >> 2, tig = lane & 3;

    const float* Ag = A + (size_t)bm * BM * K;
    const float* Bg = B + (size_t)bn * BN;

    float acc[4][4][4];
#pragma unroll
    for (int a = 0; a < 4; a++)
#pragma unroll
        for (int b = 0; b < 4; b++)
#pragma unroll
            for (int c = 0; c < 4; c++) acc[a][b][c] = 0.f;

#define LOAD_TILE(kt, buf)                                                        \
    {                                                                             \
        float* ad = As0 + (buf) * BM * ASTR;                                      \
        const float* asrc = Ag + (kt) * BK;                                       \
        _Pragma("unroll")                                                         \
        for (int i = 0; i < 4; i++) {                                             \
            int c = tid + i * 256;                                                \
            int r = c >> 3, kc = (c & 7) << 2;                                    \
            uint32_t dsm = (uint32_t)__cvta_generic_to_shared(ad + r * ASTR + kc);\
            const float* s = asrc + (size_t)r * K + kc;                           \
            asm volatile("cp.async.cg.shared.global [%0], [%1], 16;"              \
                         :: "r"(dsm), "l"(s));                                    \
        }                                                                         \
        float* bd = Bs0 + (buf) * BK * BSTR;                                      \
        const float* bsrc = Bg + (size_t)(kt) * BK * N;                           \
        _Pragma("unroll")                                                         \
        for (int i = 0; i < 4; i++) {                                             \
            int c = tid + i * 256;                                                \
            int r = c >> 5, nc = (c & 31) << 2;                                   \
            uint32_t dsm = (uint32_t)__cvta_generic_to_shared(bd + r * BSTR + nc);\
            const float* s = bsrc + (size_t)r * N + nc;                           \
            asm volatile("cp.async.cg.shared.global [%0], [%1], 16;"              \
                         :: "r"(dsm), "l"(s));                                    \
        }                                                                         \
    }

    LOAD_TILE(0, 0);
    asm volatile("cp.async.commit_group;");

    int ktiles = K / BK;
    for (int t = 0; t < ktiles; t++) {
        int buf = t & 1;
        if (t + 1 < ktiles) {
            LOAD_TILE(t + 1, buf ^ 1);
            asm volatile("cp.async.commit_group;");
            asm volatile("cp.async.wait_group 1;");
        } else {
            asm volatile("cp.async.wait_group 0;");
        }
        __syncthreads();

        const float* Ab = As0 + buf * BM * ASTR;
        const float* Bb = Bs0 + buf * BK * BSTR;
#pragma unroll
        for (int ks = 0; ks < 4; ks++) {
            int k0 = ks * 8;
            uint32_t af[4][4], bf[4][2];
#pragma unroll
            for (int mt = 0; mt < 4; mt++) {
                const float* ap = Ab + (wm + mt * 16 + gid) * ASTR + k0 + tig;
                af[mt][0] = __float_as_uint(ap[0]);
                af[mt][1] = __float_as_uint(ap[8 * ASTR]);
                af[mt][2] = __float_as_uint(ap[4]);
                af[mt][3] = __float_as_uint(ap[8 * ASTR + 4]);
            }
#pragma unroll
            for (int nt = 0; nt < 4; nt++) {
                const float* bp = Bb + (k0 + tig) * BSTR + wn + nt * 8 + gid;
                bf[nt][0] = __float_as_uint(bp[0]);
                bf[nt][1] = __float_as_uint(bp[4 * BSTR]);
            }
#pragma unroll
            for (int mt = 0; mt < 4; mt++)
#pragma unroll
                for (int nt = 0; nt < 4; nt++)
                    mma_tf32(acc[mt][nt], af[mt], bf[nt]);
        }
        __syncthreads();
    }

    int act = flags & 1, rnd = flags & 2, fin = flags & 4;
#pragma unroll
    for (int mt = 0; mt < 4; mt++) {
        int row = bm * BM + wm + mt * 16 + gid;
#pragma unroll
        for (int nt = 0; nt < 4; nt++) {
            int col = bn * BN + wn + nt * 8 + tig * 2;
            float b0 = bias ? bias[col] : 0.f;
            float b1 = bias ? bias[col + 1] : 0.f;
            float v0 = acc[mt][nt][0] + b0, v1 = acc[mt][nt][1] + b1;
            float v2 = acc[mt][nt][2] + b0, v3 = acc[mt][nt][3] + b1;
            if (act) { v0 = gelu_tanh(v0); v1 = gelu_tanh(v1); v2 = gelu_tanh(v2); v3 = gelu_tanh(v3); }
            if (fin) {
                // ffn2: out += gate * v ; bm==0 tile is the enc segment (TENC==128)
                int goff   = (row < TENC) ? 5120 : 2048;
                int orow0  = (row < TENC) ? (NTOK + row)     : (row - TENC);
                int orow1  = (row < TENC) ? (NTOK + row + 8) : (row + 8 - TENC);
                float ga = g_emb2[goff + col], gb = g_emb2[goff + col + 1];
                float* p0 = C + (size_t)orow0 * N + col;
                float* p1 = C + (size_t)orow1 * N + col;
                p0[0] += ga * v0; p0[1] += gb * v1;
                p1[0] += ga * v2; p1[1] += gb * v3;
            } else {
                if (rnd) { v0 = to_tf32(v0); v1 = to_tf32(v1); v2 = to_tf32(v2); v3 = to_tf32(v3); }
                float2 lo = make_float2(v0, v1), hi = make_float2(v2, v3);
                *(float2*)(C + (size_t)row * N + col)       = lo;
                *(float2*)(C + (size_t)(row + 8) * N + col) = hi;
            }
        }
    }
}

// ---------------- per-head LN on q/k inside g_qkv (eps 1e-6, tf32 out) --------
__global__ __launch_bounds__(256) void qkln_kernel(
    float* __restrict__ buf, const float* __restrict__ g, const float* __restrict__ b)
{
    int seg  = blockIdx.x * 8 + (threadIdx.x >> 5);  // 0..MFF*16-1
    int lane = threadIdx.x & 31;
    float* p = buf + (size_t)(seg >> 4) * QKVN + (seg & 15) * HD_;
    float x0 = p[lane], x1 = p[lane + 32];
    float s = x0 + x1, s2 = x0 * x0 + x1 * x1;
#pragma unroll
    for (int m = 16; m > 0; m >>= 1) {
        s  += __shfl_xor_sync(0xffffffffu, s,  m);
        s2 += __shfl_xor_sync(0xffffffffu, s2, m);
    }
    float mean = s * (1.f / 64.f);
    float var  = s2 * (1.f / 64.f) - mean * mean;
    float inv  = rsqrtf(var + 1e-6f);
    p[lane]      = to_tf32((x0 - mean) * inv * g[lane]      + b[lane]);
    p[lane + 32] = to_tf32((x1 - mean) * inv * g[lane + 32] + b[lane + 32]);
}

// ---------------- TF32 tensor-core flash attention (dedup qkv rows) -----------
#define QSTR 68
#define KSTR 68
#define VSTR 72
#define ATTN_SMEM_F (128 * QSTR + 64 * KSTR + 64 * VSTR)

__global__ __launch_bounds__(256, 2) void attn_tc_kernel(
    const float* __restrict__ qkv, float* __restrict__ o)
{
    extern __shared__ float sm[];
    float* Qs = sm;
    float* Ks = sm + 128 * QSTR;
    float* Vs = Ks + 64 * KSTR;

    int qt = blockIdx.x, h = blockIdx.y, w = blockIdx.z;
    int tid = threadIdx.x, lane = tid & 31, wid = tid >> 5;
    int gid = lane >> 2, tig = lane & 3;
    int wq0 = wid * 16;
    const size_t obase = (size_t)w * LWIN * DIMC + (size_t)h * HD_;

    // unique-row base for this Q tile: tile 0 = enc rows, else hidden rows
    size_t qrow0 = (size_t)qt * 128 + (qt ? (size_t)w * SROW : 0);
    const float* qg = qkv + qrow0 * QKVN + h * HD_;

#pragma unroll
    for (int i = 0; i < 8; i++) {
        int e = tid + i * 256;
        int r = e >> 4, d4 = (e & 15) * 4;
        float4 t4 = *(const float4*)(qg + (size_t)r * QKVN + d4);
        float* dst = Qs + r * QSTR + d4;
        dst[0] = t4.x * 0.125f; dst[1] = t4.y * 0.125f;
        dst[2] = t4.z * 0.125f; dst[3] = t4.w * 0.125f;
    }

    float accO[8][4];
#pragma unroll
    for (int nt = 0; nt < 8; nt++)
#pragma unroll
        for (int i = 0; i < 4; i++) accO[nt][i] = 0.f;
    float m0 = -1e30f, m1 = -1e30f, l0 = 0.f, l1 = 0.f;

    for (int kt = 0; kt < 20; kt++) {
        size_t krow0 = (size_t)kt * 64 + (kt >= 2 ? (size_t)w * SROW : 0);
        const float* kg = qkv + krow0 * QKVN + 1024 + h * HD_;
        const float* vg = qkv + krow0 * QKVN + 2048 + h * HD_;
        __syncthreads();
#pragma unroll
        for (int i = 0; i < 4; i++) {
            int e = tid + i * 256;
            int r = e >> 4, d4 = (e & 15) * 4;
            float4 kk = *(const float4*)(kg + (size_t)r * QKVN + d4);
            float4 vv = *(const float4*)(vg + (size_t)r * QKVN + d4);
            float* kd = Ks + r * KSTR + d4;
            kd[0] = kk.x; kd[1] = kk.y; kd[2] = kk.z; kd[3] = kk.w;
            float* vd = Vs + r * VSTR + d4;
            vd[0] = vv.x; vd[1] = vv.y; vd[2] = vv.z; vd[3] = vv.w;
        }
        __syncthreads();

        float s[8][4];
#pragma unroll
        for (int nt = 0; nt < 8; nt++)
#pragma unroll
            for (int i = 0; i < 4; i++) s[nt][i] = 0.f;

#pragma unroll
        for (int ks = 0; ks < 8; ks++) {
            int k0 = ks * 8;
            uint32_t af[4];
            const float* ap = Qs + (wq0 + gid) * QSTR + k0 + tig;
            af[0] = __float_as_uint(ap[0]);
            af[1] = __float_as_uint(ap[8 * QSTR]);
            af[2] = __float_as_uint(ap[4]);
            af[3] = __float_as_uint(ap[8 * QSTR + 4]);
#pragma unroll
            for (int nt = 0; nt < 8; nt++) {
                uint32_t bf[2];
                const float* bp = Ks + (nt * 8 + gid) * KSTR + k0 + tig;
                bf[0] = __float_as_uint(bp[0]);
                bf[1] = __float_as_uint(bp[4]);
                mma_tf32(s[nt], af, bf);
            }
        }

        float mx0 = -1e30f, mx1 = -1e30f;
#pragma unroll
        for (int nt = 0; nt < 8; nt++) {
            mx0 = fmaxf(mx0, fmaxf(s[nt][0], s[nt][1]));
            mx1 = fmaxf(mx1, fmaxf(s[nt][2], s[nt][3]));
        }
        mx0 = fmaxf(mx0, __shfl_xor_sync(0xffffffffu, mx0, 1));
        mx0 = fmaxf(mx0, __shfl_xor_sync(0xffffffffu, mx0, 2));
        mx1 = fmaxf(mx1, __shfl_xor_sync(0xffffffffu, mx1, 1));
        mx1 = fmaxf(mx1, __shfl_xor_sync(0xffffffffu, mx1, 2));
        float mn0 = fmaxf(m0, mx0), mn1 = fmaxf(m1, mx1);
        float f0 = __expf(m0 - mn0), f1 = __expf(m1 - mn1);
        m0 = mn0; m1 = mn1;
        float sum0 = 0.f, sum1 = 0.f;
#pragma unroll
        for (int nt = 0; nt < 8; nt++) {
            s[nt][0] = to_tf32(__expf(s[nt][0] - mn0));
            s[nt][1] = to_tf32(__expf(s[nt][1] - mn0));
            s[nt][2] = to_tf32(__expf(s[nt][2] - mn1));
            s[nt][3] = to_tf32(__expf(s[nt][3] - mn1));
            sum0 += s[nt][0] + s[nt][1];
            sum1 += s[nt][2] + s[nt][3];
        }
        sum0 += __shfl_xor_sync(0xffffffffu, sum0, 1);
        sum0 += __shfl_xor_sync(0xffffffffu, sum0, 2);
        sum1 += __shfl_xor_sync(0xffffffffu, sum1, 1);
        sum1 += __shfl_xor_sync(0xffffffffu, sum1, 2);
        l0 = l0 * f0 + sum0;
        l1 = l1 * f1 + sum1;
#pragma unroll
        for (int nt = 0; nt < 8; nt++) {
            accO[nt][0] *= f0; accO[nt][1] *= f0;
            accO[nt][2] *= f1; accO[nt][3] *= f1;
        }

#pragma unroll
        for (int kc = 0; kc < 8; kc++) {
            int srcA = (lane & 28) + (tig >> 1);
            int srcB = srcA + 2;
            float w0a = __shfl_sync(0xffffffffu, s[kc][0], srcA);
            float w1a = __shfl_sync(0xffffffffu, s[kc][1], srcA);
            float w2a = __shfl_sync(0xffffffffu, s[kc][2], srcA);
            float w3a = __shfl_sync(0xffffffffu, s[kc][3], srcA);
            float w0b = __shfl_sync(0xffffffffu, s[kc][0], srcB);
            float w1b = __shfl_sync(0xffffffffu, s[kc][1], srcB);
            float w2b = __shfl_sync(0xffffffffu, s[kc][2], srcB);
            float w3b = __shfl_sync(0xffffffffu, s[kc][3], srcB);
            bool odd = tig & 1;
            uint32_t af[4];
            af[0] = __float_as_uint(odd ? w1a : w0a);
            af[1] = __float_as_uint(odd ? w3a : w2a);
            af[2] = __float_as_uint(odd ? w1b : w0b);
            af[3] = __float_as_uint(odd ? w3b : w2b);
#pragma unroll
            for (int nt = 0; nt < 8; nt++) {
                uint32_t bf[2];
                const float* bp = Vs + (kc * 8 + tig) * VSTR + nt * 8 + gid;
                bf[0] = __float_as_uint(bp[0]);
                bf[1] = __float_as_uint(bp[4 * VSTR]);
                mma_tf32(accO[nt], af, bf);
            }
        }
    }

    float il0 = 1.f / l0, il1 = 1.f / l1;
    int row0 = qt * 128 + wq0 + gid;
#pragma unroll
    for (int nt = 0; nt < 8; nt++) {
        int col = nt * 8 + tig * 2;
        float2 a = make_float2(to_tf32(accO[nt][0] * il0), to_tf32(accO[nt][1] * il0));
        float2 b = make_float2(to_tf32(accO[nt][2] * il1), to_tf32(accO[nt][3] * il1));
        *(float2*)(o + obase + (size_t)row0 * DIMC + col)       = a;
        *(float2*)(o + obase + (size_t)(row0 + 8) * DIMC + col) = b;
    }
}

// ------- combine hidden: residual + pyramid blend, then LN2 -> ffin -----------
__global__ __launch_bounds__(256) void combine_hidden_kernel(
    const float* __restrict__ hs, float* __restrict__ out,
    const float* __restrict__ g, const float* __restrict__ b)
{
    int gidx = blockIdx.x;               // 0..NTOK-1
    int tid  = threadIdx.x;
    int blk  = gidx / SROW;              // 0..5
    float acc[4] = {0.f, 0.f, 0.f, 0.f};
    float wsum = 0.f;
#pragma unroll
    for (int dw = -1; dw <= 0; dw++) {
        int w = blk + dw;
        if (w < 0 || w > 4) continue;
        int lv = gidx - w * SROW;
        float wt = c_pyr[lv / 144];
        wsum += wt;
        const float* op = g_o2 + ((size_t)w * LWIN + TENC + lv) * DIMC;
#pragma unroll
        for (int i = 0; i < 4; i++) acc[i] += wt * op[tid + i * 256];
    }
    float inv = 1.f / wsum;
    float r[4]; float s = 0.f, s2 = 0.f;
#pragma unroll
    for (int i = 0; i < 4; i++) {
        int d = tid + i * 256;
        r[i] = hs[(size_t)gidx * DIMC + d] + g_emb1[2048 + d] * acc[i] * inv;
        out[(size_t)gidx * DIMC + d] = r[i];
        s += r[i]; s2 += r[i] * r[i];
    }
    block_reduce_2(s, s2);
    float mean = s * (1.f / DIMC);
    float var  = s2 * (1.f / DIMC) - mean * mean;
    float inv2 = rsqrtf(var + 1e-5f);
    float* dst = g_ffin + (size_t)(TENC + gidx) * DIMC;
#pragma unroll
    for (int i = 0; i < 4; i++) {
        int d = tid + i * 256;
        float v = (r[i] - mean) * inv2 * g[d] + b[d];
        dst[d] = to_tf32(v * (1.f + g_emb2[1024 + d]) + g_emb2[d]);
    }
}

// ------- combine enc: residual + window mean, then LN2 -> ffin ----------------
__global__ __launch_bounds__(256) void combine_enc_kernel(
    const float* __restrict__ enc, float* __restrict__ out,
    const float* __restrict__ g, const float* __restrict__ b)
{
    int t = blockIdx.x; int tid = threadIdx.x;
    float r[4]; float s = 0.f, s2 = 0.f;
#pragma unroll
    for (int i = 0; i < 4; i++) {
        int d = tid + i * 256;
        float a = 0.f;
#pragma unroll
        for (int w = 0; w < WQN; w++)
            a += g_o2[((size_t)w * LWIN + t) * DIMC + d];
        r[i] = enc[(size_t)t * DIMC + d] + g_emb1[5120 + d] * a * 0.2f;
        out[(size_t)t * DIMC + d] = r[i];
        s += r[i]; s2 += r[i] * r[i];
    }
    block_reduce_2(s, s2);
    float mean = s * (1.f / DIMC);
    float var  = s2 * (1.f / DIMC) - mean * mean;
    float inv2 = rsqrtf(var + 1e-5f);
    float* dst = g_ffin + (size_t)t * DIMC;
#pragma unroll
    for (int i = 0; i < 4; i++) {
        int d = tid + i * 256;
        float v = (r[i] - mean) * inv2 * g[d] + b[d];
        dst[d] = to_tf32(v * (1.f + g_emb2[4096 + d]) + g_emb2[3072 + d]);
    }
}

// ---------------- host side ----------------
static void launch_gemm(const float* A, const float* B, const float* bias,
                        float* C, int M, int N, int K, int flags)
{
    dim3 grid(N / 128, M / 128);
    size_t smem = (size_t)2 * STAGE_F * sizeof(float);
    gemm_tc_kernel<<<grid, 256, smem>>>(A, B, bias, C, M, N, K, flags);
}

extern "C" void kernel_launch(void* const* d_in, const int* in_sizes, int n_in,
                              void* d_out, int out_size)
{
    const float* hs    = (const float*)d_in[0];
    const float* enc   = (const float*)d_in[1];
    const float* temb  = (const float*)d_in[2];
    const float* n1w   = (const float*)d_in[3];
    const float* n1b   = (const float*)d_in[4];
    const float* n1g   = (const float*)d_in[5];
    const float* n1bb  = (const float*)d_in[6];
    const float* wq    = (const float*)d_in[7];
    const float* wk    = (const float*)d_in[8];
    const float* wv    = (const float*)d_in[9];
    const float* nqg   = (const float*)d_in[10];
    const float* nqb   = (const float*)d_in[11];
    const float* nkg   = (const float*)d_in[12];
    const float* nkb   = (const float*)d_in[13];
    const float* wo    = (const float*)d_in[14];
    const float* bo    = (const float*)d_in[15];
    const float* n2w   = (const float*)d_in[16];
    const float* n2b   = (const float*)d_in[17];
    const float* n2g   = (const float*)d_in[18];
    const float* n2bb  = (const float*)d_in[19];
    const float* ffw1  = (const float*)d_in[20];
    const float* ffb1  = (const float*)d_in[21];
    const float* ffw2  = (const float*)d_in[22];
    const float* ffb2  = (const float*)d_in[23];
    (void)in_sizes; (void)n_in;

    float* out = (float*)d_out;
    float* out_hidden = out;
    float* out_enc    = out + (size_t)NTOK * DIMC;
    (void)out_size;

    float *p_x, *p_qkv, *p_ao, *p_o2, *p_ffin, *p_h1, *p_wr;
    cudaGetSymbolAddress((void**)&p_x,    g_x);
    cudaGetSymbolAddress((void**)&p_qkv,  g_qkv);
    cudaGetSymbolAddress((void**)&p_ao,   g_ao);
    cudaGetSymbolAddress((void**)&p_o2,   g_o2);
    cudaGetSymbolAddress((void**)&p_ffin, g_ffin);
    cudaGetSymbolAddress((void**)&p_h1,   g_h1);
    cudaGetSymbolAddress((void**)&p_wr,   g_wr);

    float* wqkv_r = p_wr;                         // 3 MEG
    float* wo_r   = p_wr + (size_t)3 * MEG;
    float* w1_r   = p_wr + (size_t)4 * MEG;
    float* w2_r   = p_wr + (size_t)8 * MEG;

    const int ATTN_SMEM = ATTN_SMEM_F * sizeof(float);
    cudaFuncSetAttribute(attn_tc_kernel, cudaFuncAttributeMaxDynamicSharedMemorySize, ATTN_SMEM);
    const int GEMM_SMEM = 2 * STAGE_F * sizeof(float);
    cudaFuncSetAttribute(gemm_tc_kernel, cudaFuncAttributeMaxDynamicSharedMemorySize, GEMM_SMEM);

    // 0. round weights to tf32 (qkv fused into [1024 x 3072])
    round_w_qkv_kernel<<<dim3(MEG / 1024, 3), 256>>>(
        (const float4*)wq, (const float4*)wk, (const float4*)wv, (float4*)wqkv_r);
    round_w_kernel<<<MEG / 1024, 256>>>((const float4*)wo, (float4*)wo_r, MEG / 4);
    round_w_kernel<<<4 * MEG / 1024, 256>>>((const float4*)ffw1, (float4*)w1_r, MEG);
    round_w_kernel<<<4 * MEG / 1024, 256>>>((const float4*)ffw2, (float4*)w2_r, MEG);

    // 1. modulation embeddings
    emb_kernel<<<48, 256>>>(temb, n1w, n1b, n2w, n2b);
    // 2. unique x rows (3584) = modulated LN
    build_x_kernel<<<MFF, 256>>>(hs, enc, n1g, n1bb);
    // 3. fused QKV projection on unique rows (rounded outputs)
    launch_gemm(p_x, wqkv_r, nullptr, p_qkv, MFF, QKVN, DIMC, 2);
    // 4. per-head LN on q, k
    qkln_kernel<<<MFF * HEADS_ / 8, 256>>>(p_qkv, nqg, nqb);
    qkln_kernel<<<MFF * HEADS_ / 8, 256>>>(p_qkv + 1024, nkg, nkb);
    // 5. attention (tensor cores, dedup row indexing)
    attn_tc_kernel<<<dim3(LWIN / 128, HEADS_, WQN), 256, ATTN_SMEM>>>(p_qkv, p_ao);
    // 6. output projection (full 6400 rows)
    launch_gemm(p_ao, wo_r, bo, p_o2, MQ, DIMC, DIMC, 0);
    // 7. residual + blending, fused with LN2 -> ffin
    combine_hidden_kernel<<<NTOK, 256>>>(hs, out_hidden, n2g, n2bb);
    combine_enc_kernel<<<TENC, 256>>>(enc, out_enc, n2g, n2bb);
    // 8. FFN; ffn2 fuses the final gated residual add into `out`
    launch_gemm(p_ffin, w1_r, ffb1, p_h1, MFF, 4096, DIMC, 1 | 2);
    launch_gemm(p_h1, w2_r, ffb2, out, MFF, DIMC, 4096, 4);
}

// round 7
// speedup vs baseline: 6.2474x; 1.7947x over previous
#include <cuda_runtime.h>
#include <cuda_bf16.h>
#include <math.h>
#include <stdint.h>

typedef __nv_bfloat16 bf16;

// ---------------- constants ----------------
#define DIMC   1024
#define TEMBC  512
#define NTOK   3456
#define TENC   128
#define WQN    5
#define LWIN   1280
#define SROW   576
#define MQ     6400
#define MFF    3584
#define HEADS_ 16
#define HD_    64
#define QKVN   3072
#define MEG    1048576

// ---------------- device scratch ----------------
__device__ float g_emb1[6144];
__device__ float g_emb2[6144];
__device__ bf16  g_x   [(size_t)MFF * DIMC];
__device__ bf16  g_qkv [(size_t)MFF * QKVN];
__device__ bf16  g_ao  [(size_t)MQ * DIMC];
__device__ float g_o2  [(size_t)MQ * DIMC];
__device__ bf16  g_ffin[(size_t)MFF * DIMC];
__device__ bf16  g_h1  [(size_t)MFF * 4096];
__device__ bf16  g_wt  [(size_t)12 * MEG];  // qkv^T(3M), wo^T(1M), w1^T(4M), w2^T(4M)

__constant__ float c_pyr[8] = {1.f,2.f,3.f,4.f,4.f,3.f,2.f,1.f};

// ---------------- helpers ----------------
__device__ __forceinline__ uint32_t pack_bf2(float lo, float hi) {
    uint32_t r;
    asm("cvt.rn.bf16x2.f32 %0, %1, %2;" : "=r"(r) : "f"(hi), "f"(lo));
    return r;
}

__device__ __forceinline__ void block_reduce_2(float &s, float &s2) {
    __shared__ float ra[8], rb[8];
#pragma unroll
    for (int m = 16; m > 0; m >>= 1) {
        s  += __shfl_xor_sync(0xffffffffu, s,  m);
        s2 += __shfl_xor_sync(0xffffffffu, s2, m);
    }
    int wid = threadIdx.x >> 5;
    if ((threadIdx.x & 31) == 0) { ra[wid] = s; rb[wid] = s2; }
    __syncthreads();
    s  = ra[0]+ra[1]+ra[2]+ra[3]+ra[4]+ra[5]+ra[6]+ra[7];
    s2 = rb[0]+rb[1]+rb[2]+rb[3]+rb[4]+rb[5]+rb[6]+rb[7];
    __syncthreads();
}

__device__ __forceinline__ float gelu_tanh(float x) {
    float x3 = x * x * x;
    return 0.5f * x * (1.f + tanhf(0.79788456080286535588f * (x + 0.044715f * x3)));
}

__device__ __forceinline__ void mma_bf16(float* d, const uint32_t* a, const uint32_t* b) {
    asm volatile(
        "mma.sync.aligned.m16n8k16.row.col.f32.bf16.bf16.f32 "
        "{%0,%1,%2,%3}, {%4,%5,%6,%7}, {%8,%9}, {%0,%1,%2,%3};"
        : "+f"(d[0]), "+f"(d[1]), "+f"(d[2]), "+f"(d[3])
        : "r"(a[0]), "r"(a[1]), "r"(a[2]), "r"(a[3]), "r"(b[0]), "r"(b[1]));
}

// ---------------- weight prep: transpose + round to bf16 ----------------
// W [K][N] f32  ->  WT [N][K] bf16.  grid (N/32, K/32), block (32,8)
__global__ __launch_bounds__(256) void round_wT_kernel(
    const float* __restrict__ W, bf16* __restrict__ WT, int K, int N)
{
    __shared__ float t[32][33];
    int n0 = blockIdx.x * 32, k0 = blockIdx.y * 32;
    int tx = threadIdx.x, ty = threadIdx.y;
#pragma unroll
    for (int j = 0; j < 4; j++)
        t[ty + 8 * j][tx] = W[(size_t)(k0 + ty + 8 * j) * N + n0 + tx];
    __syncthreads();
#pragma unroll
    for (int j = 0; j < 4; j++)
        WT[(size_t)(n0 + ty + 8 * j) * K + k0 + tx] =
            __float2bfloat16_rn(t[tx][ty + 8 * j]);
}

// ---------------- emb = silu(temb) @ W + b ----------------
__global__ __launch_bounds__(256) void emb_kernel(
    const float* __restrict__ temb,
    const float* __restrict__ w1, const float* __restrict__ b1,
    const float* __restrict__ w2, const float* __restrict__ b2)
{
    __shared__ float st[TEMBC];
    int tid = threadIdx.x;
    for (int i = tid; i < TEMBC; i += 256) {
        float t = temb[i];
        st[i] = t / (1.f + expf(-t));
    }
    __syncthreads();
    int j = blockIdx.x * 256 + tid;
    const float* w; const float* bb; float* out; int col;
    if (j < 6144) { w = w1; bb = b1; out = g_emb1; col = j; }
    else          { w = w2; bb = b2; out = g_emb2; col = j - 6144; }
    float acc = 0.f;
#pragma unroll 8
    for (int kk = 0; kk < TEMBC; kk++)
        acc += st[kk] * w[(size_t)kk * 6144 + col];
    out[col] = acc + bb[col];
}

// ---------------- build unique x rows (bf16 out) ----------------
__global__ __launch_bounds__(256) void build_x_kernel(
    const float* __restrict__ hs, const float* __restrict__ enc,
    const float* __restrict__ g, const float* __restrict__ b)
{
    int row = blockIdx.x;
    const float* src; int sc_off, sh_off;
    if (row < TENC) { src = enc + (size_t)row * DIMC; sc_off = 4096; sh_off = 3072; }
    else            { src = hs + (size_t)(row - TENC) * DIMC; sc_off = 1024; sh_off = 0; }
    int tid = threadIdx.x;
    float x[4]; float s = 0.f, s2 = 0.f;
#pragma unroll
    for (int i = 0; i < 4; i++) {
        x[i] = src[tid + i * 256];
        s += x[i]; s2 += x[i] * x[i];
    }
    block_reduce_2(s, s2);
    float mean = s * (1.f / DIMC);
    float var  = s2 * (1.f / DIMC) - mean * mean;
    float inv  = rsqrtf(var + 1e-5f);
    bf16* dst = g_x + (size_t)row * DIMC;
#pragma unroll
    for (int i = 0; i < 4; i++) {
        int d = tid + i * 256;
        float v = (x[i] - mean) * inv * g[d] + b[d];
        dst[d] = __float2bfloat16_rn(v * (1.f + g_emb1[sc_off + d]) + g_emb1[sh_off + d]);
    }
}

// ---------------- BF16 tensor-core GEMM: C = A(MxK) * WT(NxK)^T ---------------
// flags: 1=gelu, 2=bf16 out, 4=ffn2-fused-final-add (f32 RMW on C)
#define SSTR 72                       // bf16 smem stride
#define GEMM_SMEM_B (2 * 2 * 128 * SSTR * 2)   // 73728 B

__global__ __launch_bounds__(256, 2) void gemm_bf16_kernel(
    const bf16* __restrict__ A, const bf16* __restrict__ B,
    const float* __restrict__ bias, void* __restrict__ Cv,
    int M, int N, int K, int flags)
{
    extern __shared__ bf16 smb[];
    bf16* As0 = smb;
    bf16* Bs0 = smb + 2 * 128 * SSTR;

    int tid = threadIdx.x;
    int bm = blockIdx.y, bn = blockIdx.x;
    int lane = tid & 31, wid = tid >> 5;
    int wm = (wid & 1) * 64, wn = (wid >> 1) * 32;
    int gid = lane >> 2, tig = lane & 3;

    const bf16* Ag = A + (size_t)bm * 128 * K;
    const bf16* Bg = B + (size_t)bn * 128 * K;

    float acc[4][4][4];
#pragma unroll
    for (int a = 0; a < 4; a++)
#pragma unroll
        for (int b = 0; b < 4; b++)
#pragma unroll
            for (int c = 0; c < 4; c++) acc[a][b][c] = 0.f;

#define LOAD_TILE(kt, buf)                                                         \
    {                                                                              \
        bf16* ad = As0 + (buf) * 128 * SSTR;                                       \
        bf16* bd = Bs0 + (buf) * 128 * SSTR;                                       \
        _Pragma("unroll")                                                          \
        for (int i = 0; i < 4; i++) {                                              \
            int c = tid + i * 256;                                                 \
            int r = c >> 3, kc = (c & 7) << 3;                                     \
            uint32_t dsm = (uint32_t)__cvta_generic_to_shared(ad + r * SSTR + kc); \
            const bf16* s = Ag + (size_t)r * K + (kt) * 64 + kc;                   \
            asm volatile("cp.async.cg.shared.global [%0], [%1], 16;"               \
                         :: "r"(dsm), "l"(s));                                     \
        }                                                                          \
        _Pragma("unroll")                                                          \
        for (int i = 0; i < 4; i++) {                                              \
            int c = tid + i * 256;                                                 \
            int r = c >> 3, kc = (c & 7) << 3;                                     \
            uint32_t dsm = (uint32_t)__cvta_generic_to_shared(bd + r * SSTR + kc); \
            const bf16* s = Bg + (size_t)r * K + (kt) * 64 + kc;                   \
            asm volatile("cp.async.cg.shared.global [%0], [%1], 16;"               \
                         :: "r"(dsm), "l"(s));                                     \
        }                                                                          \
    }

    LOAD_TILE(0, 0);
    asm volatile("cp.async.commit_group;");

    int ktiles = K / 64;
    for (int t = 0; t < ktiles; t++) {
        int buf = t & 1;
        if (t + 1 < ktiles) {
            LOAD_TILE(t + 1, buf ^ 1);
            asm volatile("cp.async.commit_group;");
            asm volatile("cp.async.wait_group 1;");
        } else {
            asm volatile("cp.async.wait_group 0;");
        }
        __syncthreads();

        const uint32_t* Aw = (const uint32_t*)(As0 + buf * 128 * SSTR);
        const uint32_t* Bw = (const uint32_t*)(Bs0 + buf * 128 * SSTR);
#pragma unroll
        for (int ks = 0; ks < 4; ks++) {
            uint32_t af[4][4], bfr[4][2];
#pragma unroll
            for (int mt = 0; mt < 4; mt++) {
                int idx = (wm + mt * 16 + gid) * 36 + ks * 8 + tig;
                af[mt][0] = Aw[idx];
                af[mt][1] = Aw[idx + 288];
                af[mt][2] = Aw[idx + 4];
                af[mt][3] = Aw[idx + 292];
            }
#pragma unroll
            for (int nt = 0; nt < 4; nt++) {
                int idx = (wn + nt * 8 + gid) * 36 + ks * 8 + tig;
                bfr[nt][0] = Bw[idx];
                bfr[nt][1] = Bw[idx + 4];
            }
#pragma unroll
            for (int mt = 0; mt < 4; mt++)
#pragma unroll
                for (int nt = 0; nt < 4; nt++)
                    mma_bf16(acc[mt][nt], af[mt], bfr[nt]);
        }
        __syncthreads();
    }

    int act = flags & 1, outbf = flags & 2, fin = flags & 4;
#pragma unroll
    for (int mt = 0; mt < 4; mt++) {
        int row = bm * 128 + wm + mt * 16 + gid;
#pragma unroll
        for (int nt = 0; nt < 4; nt++) {
            int col = bn * 128 + wn + nt * 8 + tig * 2;
            float b0 = bias ? bias[col] : 0.f;
            float b1 = bias ? bias[col + 1] : 0.f;
            float v0 = acc[mt][nt][0] + b0, v1 = acc[mt][nt][1] + b1;
            float v2 = acc[mt][nt][2] + b0, v3 = acc[mt][nt][3] + b1;
            if (act) { v0 = gelu_tanh(v0); v1 = gelu_tanh(v1); v2 = gelu_tanh(v2); v3 = gelu_tanh(v3); }
            if (fin) {
                float* C = (float*)Cv;
                int goff  = (row < TENC) ? 5120 : 2048;
                int orow0 = (row < TENC) ? (NTOK + row)     : (row - TENC);
                int orow1 = (row < TENC) ? (NTOK + row + 8) : (row + 8 - TENC);
                float ga = g_emb2[goff + col], gb = g_emb2[goff + col + 1];
                float* p0 = C + (size_t)orow0 * N + col;
                float* p1 = C + (size_t)orow1 * N + col;
                p0[0] += ga * v0; p0[1] += gb * v1;
                p1[0] += ga * v2; p1[1] += gb * v3;
            } else if (outbf) {
                bf16* C = (bf16*)Cv;
                *(uint32_t*)(C + (size_t)row * N + col)       = pack_bf2(v0, v1);
                *(uint32_t*)(C + (size_t)(row + 8) * N + col) = pack_bf2(v2, v3);
            } else {
                float* C = (float*)Cv;
                *(float2*)(C + (size_t)row * N + col)       = make_float2(v0, v1);
                *(float2*)(C + (size_t)(row + 8) * N + col) = make_float2(v2, v3);
            }
        }
    }
}

// ---------------- per-head LN on q/k (bf16 in/out, optional scale) ------------
__global__ __launch_bounds__(256) void qkln_kernel(
    bf16* __restrict__ buf, const float* __restrict__ g,
    const float* __restrict__ b, float scale)
{
    int seg  = blockIdx.x * 8 + (threadIdx.x >> 5);
    int lane = threadIdx.x & 31;
    bf16* p = buf + (size_t)(seg >> 4) * QKVN + (seg & 15) * HD_;
    float x0 = __bfloat162float(p[lane]);
    float x1 = __bfloat162float(p[lane + 32]);
    float s = x0 + x1, s2 = x0 * x0 + x1 * x1;
#pragma unroll
    for (int m = 16; m > 0; m >>= 1) {
        s  += __shfl_xor_sync(0xffffffffu, s,  m);
        s2 += __shfl_xor_sync(0xffffffffu, s2, m);
    }
    float mean = s * (1.f / 64.f);
    float var  = s2 * (1.f / 64.f) - mean * mean;
    float inv  = rsqrtf(var + 1e-6f);
    p[lane]      = __float2bfloat16_rn(((x0 - mean) * inv * g[lane]      + b[lane])      * scale);
    p[lane + 32] = __float2bfloat16_rn(((x1 - mean) * inv * g[lane + 32] + b[lane + 32]) * scale);
}

// ---------------- BF16 flash attention ----------------
#define ATTN_SMEM_B ((128 + 64 + 64) * SSTR * 2)   // 36864 B

__global__ __launch_bounds__(256, 2) void attn_bf16_kernel(
    const bf16* __restrict__ qkv, bf16* __restrict__ o)
{
    extern __shared__ bf16 smb[];
    bf16* Qs = smb;                    // [128][SSTR]
    bf16* Ks = smb + 128 * SSTR;       // [64][SSTR]  row=kv token, col=d
    bf16* Vs = Ks + 64 * SSTR;         // [64][SSTR]  row=kv token, col=d

    int qt = blockIdx.x, h = blockIdx.y, w = blockIdx.z;
    int tid = threadIdx.x, lane = tid & 31, wid = tid >> 5;
    int gid = lane >> 2, tig = lane & 3;
    int wq0 = wid * 16;
    const size_t obase = (size_t)w * LWIN * DIMC + (size_t)h * HD_;

    size_t qrow0 = (size_t)qt * 128 + (qt ? (size_t)w * SROW : 0);
    const bf16* qg = qkv + qrow0 * QKVN + h * HD_;

#pragma unroll
    for (int i = 0; i < 4; i++) {
        int e = tid + i * 256;          // 1024 chunks of 16B
        int r = e >> 3, dc = (e & 7) << 3;
        *(uint4*)(Qs + r * SSTR + dc) = *(const uint4*)(qg + (size_t)r * QKVN + dc);
    }

    float accO[8][4];
#pragma unroll
    for (int nt = 0; nt < 8; nt++)
#pragma unroll
        for (int i = 0; i < 4; i++) accO[nt][i] = 0.f;
    float m0 = -1e30f, m1 = -1e30f, l0 = 0.f, l1 = 0.f;

    for (int kt = 0; kt < 20; kt++) {
        size_t krow0 = (size_t)kt * 64 + (kt >= 2 ? (size_t)w * SROW : 0);
        const bf16* kg = qkv + krow0 * QKVN + 1024 + h * HD_;
        const bf16* vg = qkv + krow0 * QKVN + 2048 + h * HD_;
        __syncthreads();
#pragma unroll
        for (int i = 0; i < 2; i++) {
            int e = tid + i * 256;      // 512 chunks each
            int r = e >> 3, dc = (e & 7) << 3;
            *(uint4*)(Ks + r * SSTR + dc) = *(const uint4*)(kg + (size_t)r * QKVN + dc);
            *(uint4*)(Vs + r * SSTR + dc) = *(const uint4*)(vg + (size_t)r * QKVN + dc);
        }
        __syncthreads();

        // S = Q K^T : 16 rows x 64 cols per warp
        float s[8][4];
#pragma unroll
        for (int nt = 0; nt < 8; nt++)
#pragma unroll
            for (int i = 0; i < 4; i++) s[nt][i] = 0.f;

        const uint32_t* Qw = (const uint32_t*)Qs;
        const uint32_t* Kw = (const uint32_t*)Ks;
#pragma unroll
        for (int ks = 0; ks < 4; ks++) {
            uint32_t af[4];
            int ai = (wq0 + gid) * 36 + ks * 8 + tig;
            af[0] = Qw[ai]; af[1] = Qw[ai + 288];
            af[2] = Qw[ai + 4]; af[3] = Qw[ai + 292];
#pragma unroll
            for (int nt = 0; nt < 8; nt++) {
                uint32_t bfr[2];
                int bi = (nt * 8 + gid) * 36 + ks * 8 + tig;
                bfr[0] = Kw[bi]; bfr[1] = Kw[bi + 4];
                mma_bf16(s[nt], af, bfr);
            }
        }

        // online softmax
        float mx0 = -1e30f, mx1 = -1e30f;
#pragma unroll
        for (int nt = 0; nt < 8; nt++) {
            mx0 = fmaxf(mx0, fmaxf(s[nt][0], s[nt][1]));
            mx1 = fmaxf(mx1, fmaxf(s[nt][2], s[nt][3]));
        }
        mx0 = fmaxf(mx0, __shfl_xor_sync(0xffffffffu, mx0, 1));
        mx0 = fmaxf(mx0, __shfl_xor_sync(0xffffffffu, mx0, 2));
        mx1 = fmaxf(mx1, __shfl_xor_sync(0xffffffffu, mx1, 1));
        mx1 = fmaxf(mx1, __shfl_xor_sync(0xffffffffu, mx1, 2));
        float mn0 = fmaxf(m0, mx0), mn1 = fmaxf(m1, mx1);
        float f0 = __expf(m0 - mn0), f1 = __expf(m1 - mn1);
        m0 = mn0; m1 = mn1;
        float sum0 = 0.f, sum1 = 0.f;
#pragma unroll
        for (int nt = 0; nt < 8; nt++) {
            s[nt][0] = __expf(s[nt][0] - mn0);
            s[nt][1] = __expf(s[nt][1] - mn0);
            s[nt][2] = __expf(s[nt][2] - mn1);
            s[nt][3] = __expf(s[nt][3] - mn1);
            sum0 += s[nt][0] + s[nt][1];
            sum1 += s[nt][2] + s[nt][3];
        }
        sum0 += __shfl_xor_sync(0xffffffffu, sum0, 1);
        sum0 += __shfl_xor_sync(0xffffffffu, sum0, 2);
        sum1 += __shfl_xor_sync(0xffffffffu, sum1, 1);
        sum1 += __shfl_xor_sync(0xffffffffu, sum1, 2);
        l0 = l0 * f0 + sum0;
        l1 = l1 * f1 + sum1;
#pragma unroll
        for (int nt = 0; nt < 8; nt++) {
            accO[nt][0] *= f0; accO[nt][1] *= f0;
            accO[nt][2] *= f1; accO[nt][3] *= f1;
        }

        // O += P V : P C-frags pack directly into bf16 A-frags.
        // V B-frags via ldmatrix.x4.trans from [kv][d] layout.
#pragma unroll
        for (int kc = 0; kc < 4; kc++) {
            uint32_t aP[4];
            aP[0] = pack_bf2(s[2 * kc][0],     s[2 * kc][1]);
            aP[1] = pack_bf2(s[2 * kc][2],     s[2 * kc][3]);
            aP[2] = pack_bf2(s[2 * kc + 1][0], s[2 * kc + 1][1]);
            aP[3] = pack_bf2(s[2 * kc + 1][2], s[2 * kc + 1][3]);
#pragma unroll
            for (int ntp = 0; ntp < 4; ntp++) {
                int row = kc * 16 + ((lane >> 3) & 1) * 8 + (lane & 7);
                int col = ntp * 16 + (lane >> 4) * 8;
                uint32_t smaddr = (uint32_t)__cvta_generic_to_shared(Vs + row * SSTR + col);
                uint32_t b0, b1, b2, b3;
                asm volatile(
                    "ldmatrix.sync.aligned.m8n8.x4.trans.shared.b16 {%0,%1,%2,%3}, [%4];"
                    : "=r"(b0), "=r"(b1), "=r"(b2), "=r"(b3) : "r"(smaddr));
                uint32_t blo[2] = {b0, b1}, bhi[2] = {b2, b3};
                mma_bf16(accO[2 * ntp],     aP, blo);
                mma_bf16(accO[2 * ntp + 1], aP, bhi);
            }
        }
    }

    float il0 = 1.f / l0, il1 = 1.f / l1;
    int row0 = qt * 128 + wq0 + gid;
#pragma unroll
    for (int nt = 0; nt < 8; nt++) {
        int col = nt * 8 + tig * 2;
        *(uint32_t*)(o + obase + (size_t)row0 * DIMC + col) =
            pack_bf2(accO[nt][0] * il0, accO[nt][1] * il0);
        *(uint32_t*)(o + obase + (size_t)(row0 + 8) * DIMC + col) =
            pack_bf2(accO[nt][2] * il1, accO[nt][3] * il1);
    }
}

// ------- combine hidden: residual + pyramid blend, then LN2 -> ffin -----------
__global__ __launch_bounds__(256) void combine_hidden_kernel(
    const float* __restrict__ hs, float* __restrict__ out,
    const float* __restrict__ g, const float* __restrict__ b)
{
    int gidx = blockIdx.x;
    int tid  = threadIdx.x;
    int blk  = gidx / SROW;
    float acc[4] = {0.f, 0.f, 0.f, 0.f};
    float wsum = 0.f;
#pragma unroll
    for (int dw = -1; dw <= 0; dw++) {
        int w = blk + dw;
        if (w < 0 || w > 4) continue;
        int lv = gidx - w * SROW;
        float wt = c_pyr[lv / 144];
        wsum += wt;
        const float* op = g_o2 + ((size_t)w * LWIN + TENC + lv) * DIMC;
#pragma unroll
        for (int i = 0; i < 4; i++) acc[i] += wt * op[tid + i * 256];
    }
    float inv = 1.f / wsum;
    float r[4]; float s = 0.f, s2 = 0.f;
#pragma unroll
    for (int i = 0; i < 4; i++) {
        int d = tid + i * 256;
        r[i] = hs[(size_t)gidx * DIMC + d] + g_emb1[2048 + d] * acc[i] * inv;
        out[(size_t)gidx * DIMC + d] = r[i];
        s += r[i]; s2 += r[i] * r[i];
    }
    block_reduce_2(s, s2);
    float mean = s * (1.f / DIMC);
    float var  = s2 * (1.f / DIMC) - mean * mean;
    float inv2 = rsqrtf(var + 1e-5f);
    bf16* dst = g_ffin + (size_t)(TENC + gidx) * DIMC;
#pragma unroll
    for (int i = 0; i < 4; i++) {
        int d = tid + i * 256;
        float v = (r[i] - mean) * inv2 * g[d] + b[d];
        dst[d] = __float2bfloat16_rn(v * (1.f + g_emb2[1024 + d]) + g_emb2[d]);
    }
}

// ------- combine enc: residual + window mean, then LN2 -> ffin ----------------
__global__ __launch_bounds__(256) void combine_enc_kernel(
    const float* __restrict__ enc, float* __restrict__ out,
    const float* __restrict__ g, const float* __restrict__ b)
{
    int t = blockIdx.x; int tid = threadIdx.x;
    float r[4]; float s = 0.f, s2 = 0.f;
#pragma unroll
    for (int i = 0; i < 4; i++) {
        int d = tid + i * 256;
        float a = 0.f;
#pragma unroll
        for (int w = 0; w < WQN; w++)
            a += g_o2[((size_t)w * LWIN + t) * DIMC + d];
        r[i] = enc[(size_t)t * DIMC + d] + g_emb1[5120 + d] * a * 0.2f;
        out[(size_t)t * DIMC + d] = r[i];
        s += r[i]; s2 += r[i] * r[i];
    }
    block_reduce_2(s, s2);
    float mean = s * (1.f / DIMC);
    float var  = s2 * (1.f / DIMC) - mean * mean;
    float inv2 = rsqrtf(var + 1e-5f);
    bf16* dst = g_ffin + (size_t)t * DIMC;
#pragma unroll
    for (int i = 0; i < 4; i++) {
        int d = tid + i * 256;
        float v = (r[i] - mean) * inv2 * g[d] + b[d];
        dst[d] = __float2bfloat16_rn(v * (1.f + g_emb2[4096 + d]) + g_emb2[3072 + d]);
    }
}

// ---------------- host side ----------------
static void launch_gemm(const bf16* A, const bf16* B, const float* bias,
                        void* C, int M, int N, int K, int flags)
{
    dim3 grid(N / 128, M / 128);
    gemm_bf16_kernel<<<grid, 256, GEMM_SMEM_B>>>(A, B, bias, C, M, N, K, flags);
}

extern "C" void kernel_launch(void* const* d_in, const int* in_sizes, int n_in,
                              void* d_out, int out_size)
{
    const float* hs    = (const float*)d_in[0];
    const float* enc   = (const float*)d_in[1];
    const float* temb  = (const float*)d_in[2];
    const float* n1w   = (const float*)d_in[3];
    const float* n1b   = (const float*)d_in[4];
    const float* n1g   = (const float*)d_in[5];
    const float* n1bb  = (const float*)d_in[6];
    const float* wq    = (const float*)d_in[7];
    const float* wk    = (const float*)d_in[8];
    const float* wv    = (const float*)d_in[9];
    const float* nqg   = (const float*)d_in[10];
    const float* nqb   = (const float*)d_in[11];
    const float* nkg   = (const float*)d_in[12];
    const float* nkb   = (const float*)d_in[13];
    const float* wo    = (const float*)d_in[14];
    const float* bo    = (const float*)d_in[15];
    const float* n2w   = (const float*)d_in[16];
    const float* n2b   = (const float*)d_in[17];
    const float* n2g   = (const float*)d_in[18];
    const float* n2bb  = (const float*)d_in[19];
    const float* ffw1  = (const float*)d_in[20];
    const float* ffb1  = (const float*)d_in[21];
    const float* ffw2  = (const float*)d_in[22];
    const float* ffb2  = (const float*)d_in[23];
    (void)in_sizes; (void)n_in;

    float* out = (float*)d_out;
    float* out_hidden = out;
    float* out_enc    = out + (size_t)NTOK * DIMC;
    (void)out_size;

    bf16 *p_x, *p_qkv, *p_ao, *p_ffin, *p_h1, *p_wt;
    float *p_o2;
    cudaGetSymbolAddress((void**)&p_x,    g_x);
    cudaGetSymbolAddress((void**)&p_qkv,  g_qkv);
    cudaGetSymbolAddress((void**)&p_ao,   g_ao);
    cudaGetSymbolAddress((void**)&p_o2,   g_o2);
    cudaGetSymbolAddress((void**)&p_ffin, g_ffin);
    cudaGetSymbolAddress((void**)&p_h1,   g_h1);
    cudaGetSymbolAddress((void**)&p_wt,   g_wt);

    bf16* wtqkv = p_wt;                       // [3072][1024]
    bf16* wtwo  = p_wt + (size_t)3 * MEG;     // [1024][1024]
    bf16* wtw1  = p_wt + (size_t)4 * MEG;     // [4096][1024]
    bf16* wtw2  = p_wt + (size_t)8 * MEG;     // [1024][4096]

    cudaFuncSetAttribute(attn_bf16_kernel, cudaFuncAttributeMaxDynamicSharedMemorySize, ATTN_SMEM_B);
    cudaFuncSetAttribute(gemm_bf16_kernel, cudaFuncAttributeMaxDynamicSharedMemorySize, GEMM_SMEM_B);

    // 0. weight prep: transpose + round to bf16
    dim3 tb(32, 8);
    round_wT_kernel<<<dim3(32, 32), tb>>>(wq,   wtqkv,                 1024, 1024);
    round_wT_kernel<<<dim3(32, 32), tb>>>(wk,   wtqkv + (size_t)MEG,   1024, 1024);
    round_wT_kernel<<<dim3(32, 32), tb>>>(wv,   wtqkv + (size_t)2*MEG, 1024, 1024);
    round_wT_kernel<<<dim3(32, 32), tb>>>(wo,   wtwo,                  1024, 1024);
    round_wT_kernel<<<dim3(128, 32), tb>>>(ffw1, wtw1,                 1024, 4096);
    round_wT_kernel<<<dim3(32, 128), tb>>>(ffw2, wtw2,                 4096, 1024);

    // 1. modulation embeddings
    emb_kernel<<<48, 256>>>(temb, n1w, n1b, n2w, n2b);
    // 2. unique x rows (bf16)
    build_x_kernel<<<MFF, 256>>>(hs, enc, n1g, n1bb);
    // 3. fused QKV projection -> bf16
    launch_gemm(p_x, wtqkv, nullptr, p_qkv, MFF, QKVN, DIMC, 2);
    // 4. per-head LN on q (x0.125 folded) and k
    qkln_kernel<<<MFF * HEADS_ / 8, 256>>>(p_qkv,        nqg, nqb, 0.125f);
    qkln_kernel<<<MFF * HEADS_ / 8, 256>>>(p_qkv + 1024, nkg, nkb, 1.0f);
    // 5. attention (bf16 tensor cores)
    attn_bf16_kernel<<<dim3(LWIN / 128, HEADS_, WQN), 256, ATTN_SMEM_B>>>(p_qkv, p_ao);
    // 6. output projection -> f32 g_o2
    launch_gemm(p_ao, wtwo, bo, p_o2, MQ, DIMC, DIMC, 0);
    // 7. residual + blending, fused LN2 -> ffin (bf16)
    combine_hidden_kernel<<<NTOK, 256>>>(hs, out_hidden, n2g, n2bb);
    combine_enc_kernel<<<TENC, 256>>>(enc, out_enc, n2g, n2bb);
    // 8. FFN: gelu->bf16 h1; ffn2 fuses final gated residual into out
    launch_gemm(p_ffin, wtw1, ffb1, p_h1, MFF, 4096, DIMC, 1 | 2);
    launch_gemm(p_h1, wtw2, ffb2, out, MFF, DIMC, 4096, 4);
}

// round 10
// speedup vs baseline: 6.4436x; 1.0314x over previous
#include <cuda_runtime.h>
#include <cuda_bf16.h>
#include <math.h>
#include <stdint.h>

typedef __nv_bfloat16 bf16;

// ---------------- constants ----------------
#define DIMC   1024
#define TEMBC  512
#define NTOK   3456
#define TENC   128
#define WQN    5
#define LWIN   1280
#define SROW   576
#define MQ     6400
#define MFF    3584
#define HEADS_ 16
#define HD_    64
#define QKVN   3072
#define MEG    1048576

// ---------------- device scratch ----------------
__device__ float g_emb1[6144];
__device__ float g_emb2[6144];
__device__ bf16  g_x   [(size_t)MFF * DIMC];   // x rows; later reused as blended ao
__device__ bf16  g_qkv [(size_t)MFF * QKVN];
__device__ bf16  g_ao  [(size_t)MQ * DIMC];
__device__ float g_o2  [(size_t)MFF * DIMC];
__device__ bf16  g_ffin[(size_t)MFF * DIMC];
__device__ bf16  g_h1  [(size_t)MFF * 4096];
__device__ bf16  g_wt  [(size_t)12 * MEG];     // qkv^T(3M), wo^T(1M), w1^T(4M), w2^T(4M)

__constant__ float c_pyr[8] = {1.f,2.f,3.f,4.f,4.f,3.f,2.f,1.f};

// ---------------- helpers ----------------
__device__ __forceinline__ uint32_t pack_bf2(float lo, float hi) {
    uint32_t r;
    asm("cvt.rn.bf16x2.f32 %0, %1, %2;" : "=r"(r) : "f"(hi), "f"(lo));
    return r;
}

__device__ __forceinline__ uint32_t smem_u32(const void* p) {
    return (uint32_t)__cvta_generic_to_shared(p);
}

__device__ __forceinline__ void block_reduce_2(float &s, float &s2) {
    __shared__ float ra[8], rb[8];
#pragma unroll
    for (int m = 16; m > 0; m >>= 1) {
        s  += __shfl_xor_sync(0xffffffffu, s,  m);
        s2 += __shfl_xor_sync(0xffffffffu, s2, m);
    }
    int wid = threadIdx.x >> 5;
    if ((threadIdx.x & 31) == 0) { ra[wid] = s; rb[wid] = s2; }
    __syncthreads();
    s  = ra[0]+ra[1]+ra[2]+ra[3]+ra[4]+ra[5]+ra[6]+ra[7];
    s2 = rb[0]+rb[1]+rb[2]+rb[3]+rb[4]+rb[5]+rb[6]+rb[7];
    __syncthreads();
}

__device__ __forceinline__ float gelu_tanh(float x) {
    float x3 = x * x * x;
    return 0.5f * x * (1.f + tanhf(0.79788456080286535588f * (x + 0.044715f * x3)));
}

__device__ __forceinline__ void mma_bf16(float* d, const uint32_t* a, const uint32_t* b) {
    asm volatile(
        "mma.sync.aligned.m16n8k16.row.col.f32.bf16.bf16.f32 "
        "{%0,%1,%2,%3}, {%4,%5,%6,%7}, {%8,%9}, {%0,%1,%2,%3};"
        : "+f"(d[0]), "+f"(d[1]), "+f"(d[2]), "+f"(d[3])
        : "r"(a[0]), "r"(a[1]), "r"(a[2]), "r"(a[3]), "r"(b[0]), "r"(b[1]));
}

// ---------------- weight prep: transpose + round to bf16 ----------------
__global__ __launch_bounds__(256) void round_wT_kernel(
    const float* __restrict__ W, bf16* __restrict__ WT, int K, int N)
{
    __shared__ float t[32][33];
    int n0 = blockIdx.x * 32, k0 = blockIdx.y * 32;
    int tx = threadIdx.x, ty = threadIdx.y;
#pragma unroll
    for (int j = 0; j < 4; j++)
        t[ty + 8 * j][tx] = W[(size_t)(k0 + ty + 8 * j) * N + n0 + tx];
    __syncthreads();
#pragma unroll
    for (int j = 0; j < 4; j++)
        WT[(size_t)(n0 + ty + 8 * j) * K + k0 + tx] =
            __float2bfloat16_rn(t[tx][ty + 8 * j]);
}

// ---------------- emb = silu(temb) @ W + b ----------------
__global__ __launch_bounds__(256) void emb_kernel(
    const float* __restrict__ temb,
    const float* __restrict__ w1, const float* __restrict__ b1,
    const float* __restrict__ w2, const float* __restrict__ b2)
{
    __shared__ float st[TEMBC];
    int tid = threadIdx.x;
    for (int i = tid; i < TEMBC; i += 256) {
        float t = temb[i];
        st[i] = t / (1.f + expf(-t));
    }
    __syncthreads();
    int j = blockIdx.x * 256 + tid;
    const float* w; const float* bb; float* out; int col;
    if (j < 6144) { w = w1; bb = b1; out = g_emb1; col = j; }
    else          { w = w2; bb = b2; out = g_emb2; col = j - 6144; }
    float acc = 0.f;
#pragma unroll 8
    for (int kk = 0; kk < TEMBC; kk++)
        acc += st[kk] * w[(size_t)kk * 6144 + col];
    out[col] = acc + bb[col];
}

// ---------------- build unique x rows (bf16 out) ----------------
__global__ __launch_bounds__(256) void build_x_kernel(
    const float* __restrict__ hs, const float* __restrict__ enc,
    const float* __restrict__ g, const float* __restrict__ b)
{
    int row = blockIdx.x;
    const float* src; int sc_off, sh_off;
    if (row < TENC) { src = enc + (size_t)row * DIMC; sc_off = 4096; sh_off = 3072; }
    else            { src = hs + (size_t)(row - TENC) * DIMC; sc_off = 1024; sh_off = 0; }
    int tid = threadIdx.x;
    float x[4]; float s = 0.f, s2 = 0.f;
#pragma unroll
    for (int i = 0; i < 4; i++) {
        x[i] = src[tid + i * 256];
        s += x[i]; s2 += x[i] * x[i];
    }
    block_reduce_2(s, s2);
    float mean = s * (1.f / DIMC);
    float var  = s2 * (1.f / DIMC) - mean * mean;
    float inv  = rsqrtf(var + 1e-5f);
    bf16* dst = g_x + (size_t)row * DIMC;
#pragma unroll
    for (int i = 0; i < 4; i++) {
        int d = tid + i * 256;
        float v = (x[i] - mean) * inv * g[d] + b[d];
        dst[d] = __float2bfloat16_rn(v * (1.f + g_emb1[sc_off + d]) + g_emb1[sh_off + d]);
    }
}

// ---------------- BF16 tensor-core GEMM: C = A(MxK) * WT(NxK)^T ---------------
// flags: 1=gelu, 2=bf16 out, 4=ffn2-fused-final-add (f32 RMW on C)
#define SSTR 72
#define GEMM_SMEM_B (2 * 2 * 128 * SSTR * 2)   // 73728 B

__global__ __launch_bounds__(256, 2) void gemm_bf16_kernel(
    const bf16* __restrict__ A, const bf16* __restrict__ B,
    const float* __restrict__ bias, void* __restrict__ Cv,
    int M, int N, int K, int flags)
{
    extern __shared__ bf16 smb[];
    bf16* As0 = smb;
    bf16* Bs0 = smb + 2 * 128 * SSTR;

    int tid = threadIdx.x;
    int bm = blockIdx.y, bn = blockIdx.x;
    int lane = tid & 31, wid = tid >> 5;
    int wm = (wid & 1) * 64, wn = (wid >> 1) * 32;
    int gid = lane >> 2, tig = lane & 3;

    const bf16* Ag = A + (size_t)bm * 128 * K;
    const bf16* Bg = B + (size_t)bn * 128 * K;

    float acc[4][4][4];
#pragma unroll
    for (int a = 0; a < 4; a++)
#pragma unroll
        for (int b = 0; b < 4; b++)
#pragma unroll
            for (int c = 0; c < 4; c++) acc[a][b][c] = 0.f;

#define LOAD_TILE(kt, buf)                                                         \
    {                                                                              \
        bf16* ad = As0 + (buf) * 128 * SSTR;                                       \
        bf16* bd = Bs0 + (buf) * 128 * SSTR;                                       \
        _Pragma("unroll")                                                          \
        for (int i = 0; i < 4; i++) {                                              \
            int c = tid + i * 256;                                                 \
            int r = c >> 3, kc = (c & 7) << 3;                                     \
            uint32_t dsm = (uint32_t)__cvta_generic_to_shared(ad + r * SSTR + kc); \
            const bf16* s = Ag + (size_t)r * K + (kt) * 64 + kc;                   \
            asm volatile("cp.async.cg.shared.global [%0], [%1], 16;"               \
                         :: "r"(dsm), "l"(s));                                     \
        }                                                                          \
        _Pragma("unroll")                                                          \
        for (int i = 0; i < 4; i++) {                                              \
            int c = tid + i * 256;                                                 \
            int r = c >> 3, kc = (c & 7) << 3;                                     \
            uint32_t dsm = (uint32_t)__cvta_generic_to_shared(bd + r * SSTR + kc); \
            const bf16* s = Bg + (size_t)r * K + (kt) * 64 + kc;                   \
            asm volatile("cp.async.cg.shared.global [%0], [%1], 16;"               \
                         :: "r"(dsm), "l"(s));                                     \
        }                                                                          \
    }

    LOAD_TILE(0, 0);
    asm volatile("cp.async.commit_group;");

    int ktiles = K / 64;
    for (int t = 0; t < ktiles; t++) {
        int buf = t & 1;
        if (t + 1 < ktiles) {
            LOAD_TILE(t + 1, buf ^ 1);
            asm volatile("cp.async.commit_group;");
            asm volatile("cp.async.wait_group 1;");
        } else {
            asm volatile("cp.async.wait_group 0;");
        }
        __syncthreads();

        const uint32_t* Aw = (const uint32_t*)(As0 + buf * 128 * SSTR);
        const uint32_t* Bw = (const uint32_t*)(Bs0 + buf * 128 * SSTR);
#pragma unroll
        for (int ks = 0; ks < 4; ks++) {
            uint32_t af[4][4], bfr[4][2];
#pragma unroll
            for (int mt = 0; mt < 4; mt++) {
                int idx = (wm + mt * 16 + gid) * 36 + ks * 8 + tig;
                af[mt][0] = Aw[idx];
                af[mt][1] = Aw[idx + 288];
                af[mt][2] = Aw[idx + 4];
                af[mt][3] = Aw[idx + 292];
            }
#pragma unroll
            for (int nt = 0; nt < 4; nt++) {
                int idx = (wn + nt * 8 + gid) * 36 + ks * 8 + tig;
                bfr[nt][0] = Bw[idx];
                bfr[nt][1] = Bw[idx + 4];
            }
#pragma unroll
            for (int mt = 0; mt < 4; mt++)
#pragma unroll
                for (int nt = 0; nt < 4; nt++)
                    mma_bf16(acc[mt][nt], af[mt], bfr[nt]);
        }
        __syncthreads();
    }

    int act = flags & 1, outbf = flags & 2, fin = flags & 4;
#pragma unroll
    for (int mt = 0; mt < 4; mt++) {
        int row = bm * 128 + wm + mt * 16 + gid;
#pragma unroll
        for (int nt = 0; nt < 4; nt++) {
            int col = bn * 128 + wn + nt * 8 + tig * 2;
            float b0 = bias ? bias[col] : 0.f;
            float b1 = bias ? bias[col + 1] : 0.f;
            float v0 = acc[mt][nt][0] + b0, v1 = acc[mt][nt][1] + b1;
            float v2 = acc[mt][nt][2] + b0, v3 = acc[mt][nt][3] + b1;
            if (act) { v0 = gelu_tanh(v0); v1 = gelu_tanh(v1); v2 = gelu_tanh(v2); v3 = gelu_tanh(v3); }
            if (fin) {
                float* C = (float*)Cv;
                int goff  = (row < TENC) ? 5120 : 2048;
                int orow0 = (row < TENC) ? (NTOK + row)     : (row - TENC);
                int orow1 = (row < TENC) ? (NTOK + row + 8) : (row + 8 - TENC);
                float ga = g_emb2[goff + col], gb = g_emb2[goff + col + 1];
                float* p0 = C + (size_t)orow0 * N + col;
                float* p1 = C + (size_t)orow1 * N + col;
                p0[0] += ga * v0; p0[1] += gb * v1;
                p1[0] += ga * v2; p1[1] += gb * v3;
            } else if (outbf) {
                bf16* C = (bf16*)Cv;
                *(uint32_t*)(C + (size_t)row * N + col)       = pack_bf2(v0, v1);
                *(uint32_t*)(C + (size_t)(row + 8) * N + col) = pack_bf2(v2, v3);
            } else {
                float* C = (float*)Cv;
                *(float2*)(C + (size_t)row * N + col)       = make_float2(v0, v1);
                *(float2*)(C + (size_t)(row + 8) * N + col) = make_float2(v2, v3);
            }
        }
    }
}

// ---------------- per-head LN on q/k (bf16 in/out, optional scale) ------------
__global__ __launch_bounds__(256) void qkln_kernel(
    bf16* __restrict__ buf, const float* __restrict__ g,
    const float* __restrict__ b, float scale)
{
    int seg  = blockIdx.x * 8 + (threadIdx.x >> 5);
    int lane = threadIdx.x & 31;
    bf16* p = buf + (size_t)(seg >> 4) * QKVN + (seg & 15) * HD_;
    float x0 = __bfloat162float(p[lane]);
    float x1 = __bfloat162float(p[lane + 32]);
    float s = x0 + x1, s2 = x0 * x0 + x1 * x1;
#pragma unroll
    for (int m = 16; m > 0; m >>= 1) {
        s  += __shfl_xor_sync(0xffffffffu, s,  m);
        s2 += __shfl_xor_sync(0xffffffffu, s2, m);
    }
    float mean = s * (1.f / 64.f);
    float var  = s2 * (1.f / 64.f) - mean * mean;
    float inv  = rsqrtf(var + 1e-6f);
    p[lane]      = __float2bfloat16_rn(((x0 - mean) * inv * g[lane]      + b[lane])      * scale);
    p[lane + 32] = __float2bfloat16_rn(((x1 - mean) * inv * g[lane + 32] + b[lane + 32]) * scale);
}

// ---------------- BF16 flash attention (mma.sync) ----------------
#define ATTN_SMEM_B ((128 + 64 + 64) * SSTR * 2)

__global__ __launch_bounds__(256, 2) void attn_bf16_kernel(
    const bf16* __restrict__ qkv, bf16* __restrict__ o)
{
    extern __shared__ bf16 smb[];
    bf16* Qs = smb;
    bf16* Ks = smb + 128 * SSTR;
    bf16* Vs = Ks + 64 * SSTR;

    int qt = blockIdx.x, h = blockIdx.y, w = blockIdx.z;
    int tid = threadIdx.x, lane = tid & 31, wid = tid >> 5;
    int gid = lane >> 2, tig = lane & 3;
    int wq0 = wid * 16;
    const size_t obase = (size_t)w * LWIN * DIMC + (size_t)h * HD_;

    size_t qrow0 = (size_t)qt * 128 + (qt ? (size_t)w * SROW : 0);
    const bf16* qg = qkv + qrow0 * QKVN + h * HD_;

#pragma unroll
    for (int i = 0; i < 4; i++) {
        int e = tid + i * 256;
        int r = e >> 3, dc = (e & 7) << 3;
        *(uint4*)(Qs + r * SSTR + dc) = *(const uint4*)(qg + (size_t)r * QKVN + dc);
    }

    float accO[8][4];
#pragma unroll
    for (int nt = 0; nt < 8; nt++)
#pragma unroll
        for (int i = 0; i < 4; i++) accO[nt][i] = 0.f;
    float m0 = -1e30f, m1 = -1e30f, l0 = 0.f, l1 = 0.f;

    for (int kt = 0; kt < 20; kt++) {
        size_t krow0 = (size_t)kt * 64 + (kt >= 2 ? (size_t)w * SROW : 0);
        const bf16* kg = qkv + krow0 * QKVN + 1024 + h * HD_;
        const bf16* vg = qkv + krow0 * QKVN + 2048 + h * HD_;
        __syncthreads();
#pragma unroll
        for (int i = 0; i < 2; i++) {
            int e = tid + i * 256;
            int r = e >> 3, dc = (e & 7) << 3;
            *(uint4*)(Ks + r * SSTR + dc) = *(const uint4*)(kg + (size_t)r * QKVN + dc);
            *(uint4*)(Vs + r * SSTR + dc) = *(const uint4*)(vg + (size_t)r * QKVN + dc);
        }
        __syncthreads();

        float s[8][4];
#pragma unroll
        for (int nt = 0; nt < 8; nt++)
#pragma unroll
            for (int i = 0; i < 4; i++) s[nt][i] = 0.f;

        const uint32_t* Qw = (const uint32_t*)Qs;
        const uint32_t* Kw = (const uint32_t*)Ks;
#pragma unroll
        for (int ks = 0; ks < 4; ks++) {
            uint32_t af[4];
            int ai = (wq0 + gid) * 36 + ks * 8 + tig;
            af[0] = Qw[ai]; af[1] = Qw[ai + 288];
            af[2] = Qw[ai + 4]; af[3] = Qw[ai + 292];
#pragma unroll
            for (int nt = 0; nt < 8; nt++) {
                uint32_t bfr[2];
                int bi = (nt * 8 + gid) * 36 + ks * 8 + tig;
                bfr[0] = Kw[bi]; bfr[1] = Kw[bi + 4];
                mma_bf16(s[nt], af, bfr);
            }
        }

        float mx0 = -1e30f, mx1 = -1e30f;
#pragma unroll
        for (int nt = 0; nt < 8; nt++) {
            mx0 = fmaxf(mx0, fmaxf(s[nt][0], s[nt][1]));
            mx1 = fmaxf(mx1, fmaxf(s[nt][2], s[nt][3]));
        }
        mx0 = fmaxf(mx0, __shfl_xor_sync(0xffffffffu, mx0, 1));
        mx0 = fmaxf(mx0, __shfl_xor_sync(0xffffffffu, mx0, 2));
        mx1 = fmaxf(mx1, __shfl_xor_sync(0xffffffffu, mx1, 1));
        mx1 = fmaxf(mx1, __shfl_xor_sync(0xffffffffu, mx1, 2));
        float mn0 = fmaxf(m0, mx0), mn1 = fmaxf(m1, mx1);
        float f0 = __expf(m0 - mn0), f1 = __expf(m1 - mn1);
        m0 = mn0; m1 = mn1;
        float sum0 = 0.f, sum1 = 0.f;
#pragma unroll
        for (int nt = 0; nt < 8; nt++) {
            s[nt][0] = __expf(s[nt][0] - mn0);
            s[nt][1] = __expf(s[nt][1] - mn0);
            s[nt][2] = __expf(s[nt][2] - mn1);
            s[nt][3] = __expf(s[nt][3] - mn1);
            sum0 += s[nt][0] + s[nt][1];
            sum1 += s[nt][2] + s[nt][3];
        }
        sum0 += __shfl_xor_sync(0xffffffffu, sum0, 1);
        sum0 += __shfl_xor_sync(0xffffffffu, sum0, 2);
        sum1 += __shfl_xor_sync(0xffffffffu, sum1, 1);
        sum1 += __shfl_xor_sync(0xffffffffu, sum1, 2);
        l0 = l0 * f0 + sum0;
        l1 = l1 * f1 + sum1;
#pragma unroll
        for (int nt = 0; nt < 8; nt++) {
            accO[nt][0] *= f0; accO[nt][1] *= f0;
            accO[nt][2] *= f1; accO[nt][3] *= f1;
        }

#pragma unroll
        for (int kc = 0; kc < 4; kc++) {
            uint32_t aP[4];
            aP[0] = pack_bf2(s[2 * kc][0],     s[2 * kc][1]);
            aP[1] = pack_bf2(s[2 * kc][2],     s[2 * kc][3]);
            aP[2] = pack_bf2(s[2 * kc + 1][0], s[2 * kc + 1][1]);
            aP[3] = pack_bf2(s[2 * kc + 1][2], s[2 * kc + 1][3]);
#pragma unroll
            for (int ntp = 0; ntp < 4; ntp++) {
                int row = kc * 16 + ((lane >> 3) & 1) * 8 + (lane & 7);
                int col = ntp * 16 + (lane >> 4) * 8;
                uint32_t smaddr = smem_u32(Vs + row * SSTR + col);
                uint32_t b0, b1, b2, b3;
                asm volatile(
                    "ldmatrix.sync.aligned.m8n8.x4.trans.shared.b16 {%0,%1,%2,%3}, [%4];"
                    : "=r"(b0), "=r"(b1), "=r"(b2), "=r"(b3) : "r"(smaddr));
                uint32_t blo[2] = {b0, b1}, bhi[2] = {b2, b3};
                mma_bf16(accO[2 * ntp],     aP, blo);
                mma_bf16(accO[2 * ntp + 1], aP, bhi);
            }
        }
    }

    float il0 = 1.f / l0, il1 = 1.f / l1;
    int row0 = qt * 128 + wq0 + gid;
#pragma unroll
    for (int nt = 0; nt < 8; nt++) {
        int col = nt * 8 + tig * 2;
        *(uint32_t*)(o + obase + (size_t)row0 * DIMC + col) =
            pack_bf2(accO[nt][0] * il0, accO[nt][1] * il0);
        *(uint32_t*)(o + obase + (size_t)(row0 + 8) * DIMC + col) =
            pack_bf2(accO[nt][2] * il1, accO[nt][3] * il1);
    }
}

// ------- blend attention outputs across windows (before wo) -------------------
// row<TENC: mean over 5 windows; else normalized pyramid blend. Out: g_x (bf16).
__global__ __launch_bounds__(256) void blend_ao_kernel()
{
    int row = blockIdx.x;            // 0..MFF-1
    int tid = threadIdx.x;
    bf16* dst = g_x + (size_t)row * DIMC;
    if (row < TENC) {
#pragma unroll
        for (int i = 0; i < 4; i++) {
            int d = tid + i * 256;
            float a = 0.f;
#pragma unroll
            for (int w = 0; w < WQN; w++)
                a += __bfloat162float(g_ao[((size_t)w * LWIN + row) * DIMC + d]);
            dst[d] = __float2bfloat16_rn(a * 0.2f);
        }
    } else {
        int gdx = row - TENC;
        int blk = gdx / SROW;
        float acc[4] = {0.f, 0.f, 0.f, 0.f};
        float wsum = 0.f;
#pragma unroll
        for (int dw = -1; dw <= 0; dw++) {
            int w = blk + dw;
            if (w < 0 || w > 4) continue;
            int lv = gdx - w * SROW;
            float wt = c_pyr[lv / 144];
            wsum += wt;
            const bf16* op = g_ao + ((size_t)w * LWIN + TENC + lv) * DIMC;
#pragma unroll
            for (int i = 0; i < 4; i++)
                acc[i] += wt * __bfloat162float(op[tid + i * 256]);
        }
        float inv = 1.f / wsum;
#pragma unroll
        for (int i = 0; i < 4; i++)
            dst[tid + i * 256] = __float2bfloat16_rn(acc[i] * inv);
    }
}

// ------- post-wo combine: residual + LN2 -> out and ffin ----------------------
__global__ __launch_bounds__(256) void combine_post_kernel(
    const float* __restrict__ hs, const float* __restrict__ enc,
    float* __restrict__ out, const float* __restrict__ g, const float* __restrict__ b)
{
    int row = blockIdx.x;            // 0..MFF-1 (o2 row)
    int tid = threadIdx.x;
    const float* o2 = g_o2 + (size_t)row * DIMC;
    const float* src; float* outp; int gate_off, sc_off, sh_off;
    if (row < TENC) {
        src = enc + (size_t)row * DIMC;
        outp = out + (size_t)(NTOK + row) * DIMC;
        gate_off = 5120; sc_off = 4096; sh_off = 3072;
    } else {
        int gdx = row - TENC;
        src = hs + (size_t)gdx * DIMC;
        outp = out + (size_t)gdx * DIMC;
        gate_off = 2048; sc_off = 1024; sh_off = 0;
    }
    float r[4]; float s = 0.f, s2 = 0.f;
#pragma unroll
    for (int i = 0; i < 4; i++) {
        int d = tid + i * 256;
        r[i] = src[d] + g_emb1[gate_off + d] * o2[d];
        outp[d] = r[i];
        s += r[i]; s2 += r[i] * r[i];
    }
    block_reduce_2(s, s2);
    float mean = s * (1.f / DIMC);
    float var  = s2 * (1.f / DIMC) - mean * mean;
    float inv2 = rsqrtf(var + 1e-5f);
    bf16* dst = g_ffin + (size_t)row * DIMC;
#pragma unroll
    for (int i = 0; i < 4; i++) {
        int d = tid + i * 256;
        float v = (r[i] - mean) * inv2 * g[d] + b[d];
        dst[d] = __float2bfloat16_rn(v * (1.f + g_emb2[sc_off + d]) + g_emb2[sh_off + d]);
    }
}

// ---------------- host side ----------------
static void launch_gemm(const bf16* A, const bf16* B, const float* bias,
                        void* C, int M, int N, int K, int flags)
{
    dim3 grid(N / 128, M / 128);
    gemm_bf16_kernel<<<grid, 256, GEMM_SMEM_B>>>(A, B, bias, C, M, N, K, flags);
}

extern "C" void kernel_launch(void* const* d_in, const int* in_sizes, int n_in,
                              void* d_out, int out_size)
{
    const float* hs    = (const float*)d_in[0];
    const float* enc   = (const float*)d_in[1];
    const float* temb  = (const float*)d_in[2];
    const float* n1w   = (const float*)d_in[3];
    const float* n1b   = (const float*)d_in[4];
    const float* n1g   = (const float*)d_in[5];
    const float* n1bb  = (const float*)d_in[6];
    const float* wq    = (const float*)d_in[7];
    const float* wk    = (const float*)d_in[8];
    const float* wv    = (const float*)d_in[9];
    const float* nqg   = (const float*)d_in[10];
    const float* nqb   = (const float*)d_in[11];
    const float* nkg   = (const float*)d_in[12];
    const float* nkb   = (const float*)d_in[13];
    const float* wo    = (const float*)d_in[14];
    const float* bo    = (const float*)d_in[15];
    const float* n2w   = (const float*)d_in[16];
    const float* n2b   = (const float*)d_in[17];
    const float* n2g   = (const float*)d_in[18];
    const float* n2bb  = (const float*)d_in[19];
    const float* ffw1  = (const float*)d_in[20];
    const float* ffb1  = (const float*)d_in[21];
    const float* ffw2  = (const float*)d_in[22];
    const float* ffb2  = (const float*)d_in[23];
    (void)in_sizes; (void)n_in;

    float* out = (float*)d_out;
    (void)out_size;

    bf16 *p_x, *p_qkv, *p_ao, *p_ffin, *p_h1, *p_wt;
    float *p_o2;
    cudaGetSymbolAddress((void**)&p_x,    g_x);
    cudaGetSymbolAddress((void**)&p_qkv,  g_qkv);
    cudaGetSymbolAddress((void**)&p_ao,   g_ao);
    cudaGetSymbolAddress((void**)&p_o2,   g_o2);
    cudaGetSymbolAddress((void**)&p_ffin, g_ffin);
    cudaGetSymbolAddress((void**)&p_h1,   g_h1);
    cudaGetSymbolAddress((void**)&p_wt,   g_wt);

    bf16* wtqkv = p_wt;
    bf16* wtwo  = p_wt + (size_t)3 * MEG;
    bf16* wtw1  = p_wt + (size_t)4 * MEG;
    bf16* wtw2  = p_wt + (size_t)8 * MEG;

    cudaFuncSetAttribute(attn_bf16_kernel, cudaFuncAttributeMaxDynamicSharedMemorySize, ATTN_SMEM_B);
    cudaFuncSetAttribute(gemm_bf16_kernel, cudaFuncAttributeMaxDynamicSharedMemorySize, GEMM_SMEM_B);

    // 0. weight prep
    dim3 tb(32, 8);
    round_wT_kernel<<<dim3(32, 32), tb>>>(wq,   wtqkv,                 1024, 1024);
    round_wT_kernel<<<dim3(32, 32), tb>>>(wk,   wtqkv + (size_t)MEG,   1024, 1024);
    round_wT_kernel<<<dim3(32, 32), tb>>>(wv,   wtqkv + (size_t)2*MEG, 1024, 1024);
    round_wT_kernel<<<dim3(32, 32), tb>>>(wo,   wtwo,                  1024, 1024);
    round_wT_kernel<<<dim3(128, 32), tb>>>(ffw1, wtw1,                 1024, 4096);
    round_wT_kernel<<<dim3(32, 128), tb>>>(ffw2, wtw2,                 4096, 1024);

    // 1. modulation embeddings
    emb_kernel<<<48, 256>>>(temb, n1w, n1b, n2w, n2b);
    // 2. unique x rows (bf16)
    build_x_kernel<<<MFF, 256>>>(hs, enc, n1g, n1bb);
    // 3. fused QKV projection -> bf16
    launch_gemm(p_x, wtqkv, nullptr, p_qkv, MFF, QKVN, DIMC, 2);
    // 4. per-head LN on q (x0.125 folded) and k
    qkln_kernel<<<MFF * HEADS_ / 8, 256>>>(p_qkv,        nqg, nqb, 0.125f);
    qkln_kernel<<<MFF * HEADS_ / 8, 256>>>(p_qkv + 1024, nkg, nkb, 1.0f);
    // 5. attention
    attn_bf16_kernel<<<dim3(LWIN / 128, HEADS_, WQN), 256, ATTN_SMEM_B>>>(p_qkv, p_ao);
    // 6. blend windows BEFORE wo (row-linear commute), then wo on 3584 rows
    blend_ao_kernel<<<MFF, 256>>>();
    launch_gemm(p_x, wtwo, bo, p_o2, MFF, DIMC, DIMC, 0);
    // 7. residual + LN2 -> out, ffin
    combine_post_kernel<<<MFF, 256>>>(hs, enc, out, n2g, n2bb);
    // 8. FFN; ffn2 fuses final gated residual into out
    launch_gemm(p_ffin, wtw1, ffb1, p_h1, MFF, 4096, DIMC, 1 | 2);
    launch_gemm(p_h1, wtw2, ffb2, out, MFF, DIMC, 4096, 4);
}

// round 11
// speedup vs baseline: 6.9848x; 1.0840x over previous
#include <cuda_runtime.h>
#include <cuda_bf16.h>
#include <math.h>
#include <stdint.h>

typedef __nv_bfloat16 bf16;

// ---------------- constants ----------------
#define DIMC   1024
#define TEMBC  512
#define NTOK   3456
#define TENC   128
#define WQN    5
#define LWIN   1280
#define SROW   576
#define MQ     6400
#define MFF    3584
#define HEADS_ 16
#define HD_    64
#define QKVN   3072
#define MEG    1048576

// ---------------- device scratch ----------------
__device__ float g_emb1[6144];
__device__ float g_emb2[6144];
__device__ bf16  g_x   [(size_t)MFF * DIMC];   // x rows; later reused as blended ao
__device__ bf16  g_qkv [(size_t)MFF * QKVN];
__device__ bf16  g_ao  [(size_t)MQ * DIMC];
__device__ float g_o2  [(size_t)MFF * DIMC];
__device__ bf16  g_ffin[(size_t)MFF * DIMC];
__device__ bf16  g_h1  [(size_t)MFF * 4096];
__device__ bf16  g_wt  [(size_t)12 * MEG];     // qkv^T(3M), wo^T(1M), w1^T(4M), w2^T(4M)

__constant__ float c_pyr[8] = {1.f,2.f,3.f,4.f,4.f,3.f,2.f,1.f};

// ---------------- helpers ----------------
__device__ __forceinline__ uint32_t pack_bf2(float lo, float hi) {
    uint32_t r;
    asm("cvt.rn.bf16x2.f32 %0, %1, %2;" : "=r"(r) : "f"(hi), "f"(lo));
    return r;
}

__device__ __forceinline__ uint32_t smem_u32(const void* p) {
    return (uint32_t)__cvta_generic_to_shared(p);
}

__device__ __forceinline__ void block_reduce_2(float &s, float &s2) {
    __shared__ float ra[8], rb[8];
#pragma unroll
    for (int m = 16; m > 0; m >>= 1) {
        s  += __shfl_xor_sync(0xffffffffu, s,  m);
        s2 += __shfl_xor_sync(0xffffffffu, s2, m);
    }
    int wid = threadIdx.x >> 5;
    if ((threadIdx.x & 31) == 0) { ra[wid] = s; rb[wid] = s2; }
    __syncthreads();
    s  = ra[0]+ra[1]+ra[2]+ra[3]+ra[4]+ra[5]+ra[6]+ra[7];
    s2 = rb[0]+rb[1]+rb[2]+rb[3]+rb[4]+rb[5]+rb[6]+rb[7];
    __syncthreads();
}

__device__ __forceinline__ float tanh_fast(float x) {
    float y;
    asm("tanh.approx.f32 %0, %1;" : "=f"(y) : "f"(x));
    return y;
}

__device__ __forceinline__ float gelu_tanh(float x) {
    float x3 = x * x * x;
    return 0.5f * x * (1.f + tanh_fast(0.79788456080286535588f * (x + 0.044715f * x3)));
}

__device__ __forceinline__ void mma_bf16(float* d, const uint32_t* a, const uint32_t* b) {
    asm volatile(
        "mma.sync.aligned.m16n8k16.row.col.f32.bf16.bf16.f32 "
        "{%0,%1,%2,%3}, {%4,%5,%6,%7}, {%8,%9}, {%0,%1,%2,%3};"
        : "+f"(d[0]), "+f"(d[1]), "+f"(d[2]), "+f"(d[3])
        : "r"(a[0]), "r"(a[1]), "r"(a[2]), "r"(a[3]), "r"(b[0]), "r"(b[1]));
}

// ---------------- weight prep: transpose + round to bf16 ----------------
// generic W [K][N] f32 -> WT [N][K] bf16
__global__ __launch_bounds__(256) void round_wT_kernel(
    const float* __restrict__ W, bf16* __restrict__ WT, int K, int N)
{
    __shared__ float t[32][33];
    int n0 = blockIdx.x * 32, k0 = blockIdx.y * 32;
    int tx = threadIdx.x, ty = threadIdx.y;
#pragma unroll
    for (int j = 0; j < 4; j++)
        t[ty + 8 * j][tx] = W[(size_t)(k0 + ty + 8 * j) * N + n0 + tx];
    __syncthreads();
#pragma unroll
    for (int j = 0; j < 4; j++)
        WT[(size_t)(n0 + ty + 8 * j) * K + k0 + tx] =
            __float2bfloat16_rn(t[tx][ty + 8 * j]);
}

// 4 square 1024x1024 weights in one launch (z selects weight)
__global__ __launch_bounds__(256) void round_wT4_kernel(
    const float* __restrict__ w0, const float* __restrict__ w1,
    const float* __restrict__ w2, const float* __restrict__ w3,
    bf16* __restrict__ dst)
{
    __shared__ float t[32][33];
    int z = blockIdx.z;
    const float* W = (z == 0) ? w0 : (z == 1) ? w1 : (z == 2) ? w2 : w3;
    bf16* WT = dst + (size_t)z * MEG;
    int n0 = blockIdx.x * 32, k0 = blockIdx.y * 32;
    int tx = threadIdx.x, ty = threadIdx.y;
#pragma unroll
    for (int j = 0; j < 4; j++)
        t[ty + 8 * j][tx] = W[(size_t)(k0 + ty + 8 * j) * 1024 + n0 + tx];
    __syncthreads();
#pragma unroll
    for (int j = 0; j < 4; j++)
        WT[(size_t)(n0 + ty + 8 * j) * 1024 + k0 + tx] =
            __float2bfloat16_rn(t[tx][ty + 8 * j]);
}

// ---------------- emb = silu(temb) @ W + b ----------------
__global__ __launch_bounds__(256) void emb_kernel(
    const float* __restrict__ temb,
    const float* __restrict__ w1, const float* __restrict__ b1,
    const float* __restrict__ w2, const float* __restrict__ b2)
{
    __shared__ float st[TEMBC];
    int tid = threadIdx.x;
    for (int i = tid; i < TEMBC; i += 256) {
        float t = temb[i];
        st[i] = t / (1.f + expf(-t));
    }
    __syncthreads();
    int j = blockIdx.x * 256 + tid;
    const float* w; const float* bb; float* out; int col;
    if (j < 6144) { w = w1; bb = b1; out = g_emb1; col = j; }
    else          { w = w2; bb = b2; out = g_emb2; col = j - 6144; }
    float acc = 0.f;
#pragma unroll 8
    for (int kk = 0; kk < TEMBC; kk++)
        acc += st[kk] * w[(size_t)kk * 6144 + col];
    out[col] = acc + bb[col];
}

// ---------------- build unique x rows (bf16 out) ----------------
__global__ __launch_bounds__(256) void build_x_kernel(
    const float* __restrict__ hs, const float* __restrict__ enc,
    const float* __restrict__ g, const float* __restrict__ b)
{
    int row = blockIdx.x;
    const float* src; int sc_off, sh_off;
    if (row < TENC) { src = enc + (size_t)row * DIMC; sc_off = 4096; sh_off = 3072; }
    else            { src = hs + (size_t)(row - TENC) * DIMC; sc_off = 1024; sh_off = 0; }
    int tid = threadIdx.x;
    float x[4]; float s = 0.f, s2 = 0.f;
#pragma unroll
    for (int i = 0; i < 4; i++) {
        x[i] = src[tid + i * 256];
        s += x[i]; s2 += x[i] * x[i];
    }
    block_reduce_2(s, s2);
    float mean = s * (1.f / DIMC);
    float var  = s2 * (1.f / DIMC) - mean * mean;
    float inv  = rsqrtf(var + 1e-5f);
    bf16* dst = g_x + (size_t)row * DIMC;
#pragma unroll
    for (int i = 0; i < 4; i++) {
        int d = tid + i * 256;
        float v = (x[i] - mean) * inv * g[d] + b[d];
        dst[d] = __float2bfloat16_rn(v * (1.f + g_emb1[sc_off + d]) + g_emb1[sh_off + d]);
    }
}

// ---------------- BF16 tensor-core GEMM: C = A(MxK) * WT(NxK)^T ---------------
// flags: 1=gelu, 2=bf16 out, 4=ffn2-fused-final-add (f32 RMW on C)
#define SSTR 72
#define ABUF_B 18432                   // 128*SSTR*2 bytes per stage buffer
#define GEMM_SMEM_B (2 * 2 * 128 * SSTR * 2)   // 73728 B

__global__ __launch_bounds__(256, 2) void gemm_bf16_kernel(
    const bf16* __restrict__ A, const bf16* __restrict__ B,
    const float* __restrict__ bias, void* __restrict__ Cv,
    int M, int N, int K, int flags)
{
    extern __shared__ bf16 smb[];
    bf16* As0 = smb;
    bf16* Bs0 = smb + 2 * 128 * SSTR;

    int tid = threadIdx.x;
    int bm = blockIdx.y, bn = blockIdx.x;
    int lane = tid & 31, wid = tid >> 5;
    int wm = (wid & 1) * 64, wn = (wid >> 1) * 32;
    int gid = lane >> 2, tig = lane & 3;

    const bf16* Ag = A + (size_t)bm * 128 * K;
    const bf16* Bg = B + (size_t)bn * 128 * K;

    // ldmatrix lane base addresses (bytes); row stride 144B => conflict-free
    uint32_t smbase = smem_u32(smb);
    uint32_t aBase0 = smbase + (uint32_t)((wm + (lane & 15)) * 144 + (lane >> 4) * 16);
    uint32_t bBase0 = smbase + 36864u +
                      (uint32_t)((wn + (lane & 7) + ((lane >> 4) << 3)) * 144 +
                                 ((lane >> 3) & 1) * 16);

    float acc[4][4][4];
#pragma unroll
    for (int a = 0; a < 4; a++)
#pragma unroll
        for (int b = 0; b < 4; b++)
#pragma unroll
            for (int c = 0; c < 4; c++) acc[a][b][c] = 0.f;

#define LOAD_TILE(kt, buf)                                                         \
    {                                                                              \
        bf16* ad = As0 + (buf) * 128 * SSTR;                                       \
        bf16* bd = Bs0 + (buf) * 128 * SSTR;                                       \
        _Pragma("unroll")                                                          \
        for (int i = 0; i < 4; i++) {                                              \
            int c = tid + i * 256;                                                 \
            int r = c >> 3, kc = (c & 7) << 3;                                     \
            uint32_t dsm = (uint32_t)__cvta_generic_to_shared(ad + r * SSTR + kc); \
            const bf16* s = Ag + (size_t)r * K + (kt) * 64 + kc;                   \
            asm volatile("cp.async.cg.shared.global [%0], [%1], 16;"               \
                         :: "r"(dsm), "l"(s));                                     \
        }                                                                          \
        _Pragma("unroll")                                                          \
        for (int i = 0; i < 4; i++) {                                              \
            int c = tid + i * 256;                                                 \
            int r = c >> 3, kc = (c & 7) << 3;                                     \
            uint32_t dsm = (uint32_t)__cvta_generic_to_shared(bd + r * SSTR + kc); \
            const bf16* s = Bg + (size_t)r * K + (kt) * 64 + kc;                   \
            asm volatile("cp.async.cg.shared.global [%0], [%1], 16;"               \
                         :: "r"(dsm), "l"(s));                                     \
        }                                                                          \
    }

    LOAD_TILE(0, 0);
    asm volatile("cp.async.commit_group;");

    int ktiles = K / 64;
    for (int t = 0; t < ktiles; t++) {
        int buf = t & 1;
        if (t + 1 < ktiles) {
            LOAD_TILE(t + 1, buf ^ 1);
            asm volatile("cp.async.commit_group;");
            asm volatile("cp.async.wait_group 1;");
        } else {
            asm volatile("cp.async.wait_group 0;");
        }
        __syncthreads();

        uint32_t aB = aBase0 + (uint32_t)buf * ABUF_B;
        uint32_t bB = bBase0 + (uint32_t)buf * ABUF_B;
#pragma unroll
        for (int ks = 0; ks < 4; ks++) {
            uint32_t af[4][4], bfr[2][4];
#pragma unroll
            for (int mt = 0; mt < 4; mt++)
                asm volatile(
                    "ldmatrix.sync.aligned.m8n8.x4.shared.b16 {%0,%1,%2,%3}, [%4];"
                    : "=r"(af[mt][0]), "=r"(af[mt][1]), "=r"(af[mt][2]), "=r"(af[mt][3])
                    : "r"(aB + mt * 2304 + ks * 32));
#pragma unroll
            for (int np = 0; np < 2; np++)
                asm volatile(
                    "ldmatrix.sync.aligned.m8n8.x4.shared.b16 {%0,%1,%2,%3}, [%4];"
                    : "=r"(bfr[np][0]), "=r"(bfr[np][1]), "=r"(bfr[np][2]), "=r"(bfr[np][3])
                    : "r"(bB + np * 2304 + ks * 32));
#pragma unroll
            for (int mt = 0; mt < 4; mt++) {
                mma_bf16(acc[mt][0], af[mt], &bfr[0][0]);
                mma_bf16(acc[mt][1], af[mt], &bfr[0][2]);
                mma_bf16(acc[mt][2], af[mt], &bfr[1][0]);
                mma_bf16(acc[mt][3], af[mt], &bfr[1][2]);
            }
        }
        __syncthreads();
    }

    int act = flags & 1, outbf = flags & 2, fin = flags & 4;
#pragma unroll
    for (int mt = 0; mt < 4; mt++) {
        int row = bm * 128 + wm + mt * 16 + gid;
#pragma unroll
        for (int nt = 0; nt < 4; nt++) {
            int col = bn * 128 + wn + nt * 8 + tig * 2;
            float b0 = bias ? bias[col] : 0.f;
            float b1 = bias ? bias[col + 1] : 0.f;
            float v0 = acc[mt][nt][0] + b0, v1 = acc[mt][nt][1] + b1;
            float v2 = acc[mt][nt][2] + b0, v3 = acc[mt][nt][3] + b1;
            if (act) { v0 = gelu_tanh(v0); v1 = gelu_tanh(v1); v2 = gelu_tanh(v2); v3 = gelu_tanh(v3); }
            if (fin) {
                float* C = (float*)Cv;
                int goff  = (row < TENC) ? 5120 : 2048;
                int orow0 = (row < TENC) ? (NTOK + row)     : (row - TENC);
                int orow1 = (row < TENC) ? (NTOK + row + 8) : (row + 8 - TENC);
                float ga = g_emb2[goff + col], gb = g_emb2[goff + col + 1];
                float* p0 = C + (size_t)orow0 * N + col;
                float* p1 = C + (size_t)orow1 * N + col;
                p0[0] += ga * v0; p0[1] += gb * v1;
                p1[0] += ga * v2; p1[1] += gb * v3;
            } else if (outbf) {
                bf16* C = (bf16*)Cv;
                *(uint32_t*)(C + (size_t)row * N + col)       = pack_bf2(v0, v1);
                *(uint32_t*)(C + (size_t)(row + 8) * N + col) = pack_bf2(v2, v3);
            } else {
                float* C = (float*)Cv;
                *(float2*)(C + (size_t)row * N + col)       = make_float2(v0, v1);
                *(float2*)(C + (size_t)(row + 8) * N + col) = make_float2(v2, v3);
            }
        }
    }
}

// ------- per-head LN on q and k in one launch (y: 0=q scale .125, 1=k) --------
__global__ __launch_bounds__(256) void qkln2_kernel(
    bf16* __restrict__ buf,
    const float* __restrict__ qg, const float* __restrict__ qb,
    const float* __restrict__ kg, const float* __restrict__ kb)
{
    int seg  = blockIdx.x * 8 + (threadIdx.x >> 5);
    int lane = threadIdx.x & 31;
    int isk  = blockIdx.y;
    const float* g = isk ? kg : qg;
    const float* b = isk ? kb : qb;
    float scale = isk ? 1.0f : 0.125f;
    bf16* p = buf + (size_t)(seg >> 4) * QKVN + isk * 1024 + (seg & 15) * HD_;
    float x0 = __bfloat162float(p[lane]);
    float x1 = __bfloat162float(p[lane + 32]);
    float s = x0 + x1, s2 = x0 * x0 + x1 * x1;
#pragma unroll
    for (int m = 16; m > 0; m >>= 1) {
        s  += __shfl_xor_sync(0xffffffffu, s,  m);
        s2 += __shfl_xor_sync(0xffffffffu, s2, m);
    }
    float mean = s * (1.f / 64.f);
    float var  = s2 * (1.f / 64.f) - mean * mean;
    float inv  = rsqrtf(var + 1e-6f);
    p[lane]      = __float2bfloat16_rn(((x0 - mean) * inv * g[lane]      + b[lane])      * scale);
    p[lane + 32] = __float2bfloat16_rn(((x1 - mean) * inv * g[lane + 32] + b[lane + 32]) * scale);
}

// ---------------- BF16 flash attention (mma.sync) ----------------
#define ATTN_SMEM_B ((128 + 64 + 64) * SSTR * 2)

__global__ __launch_bounds__(256, 2) void attn_bf16_kernel(
    const bf16* __restrict__ qkv, bf16* __restrict__ o)
{
    extern __shared__ bf16 smb[];
    bf16* Qs = smb;
    bf16* Ks = smb + 128 * SSTR;
    bf16* Vs = Ks + 64 * SSTR;

    int qt = blockIdx.x, h = blockIdx.y, w = blockIdx.z;
    int tid = threadIdx.x, lane = tid & 31, wid = tid >> 5;
    int gid = lane >> 2, tig = lane & 3;
    int wq0 = wid * 16;
    const size_t obase = (size_t)w * LWIN * DIMC + (size_t)h * HD_;

    size_t qrow0 = (size_t)qt * 128 + (qt ? (size_t)w * SROW : 0);
    const bf16* qg = qkv + qrow0 * QKVN + h * HD_;

#pragma unroll
    for (int i = 0; i < 4; i++) {
        int e = tid + i * 256;
        int r = e >> 3, dc = (e & 7) << 3;
        *(uint4*)(Qs + r * SSTR + dc) = *(const uint4*)(qg + (size_t)r * QKVN + dc);
    }

    float accO[8][4];
#pragma unroll
    for (int nt = 0; nt < 8; nt++)
#pragma unroll
        for (int i = 0; i < 4; i++) accO[nt][i] = 0.f;
    float m0 = -1e30f, m1 = -1e30f, l0 = 0.f, l1 = 0.f;

    for (int kt = 0; kt < 20; kt++) {
        size_t krow0 = (size_t)kt * 64 + (kt >= 2 ? (size_t)w * SROW : 0);
        const bf16* kg = qkv + krow0 * QKVN + 1024 + h * HD_;
        const bf16* vg = qkv + krow0 * QKVN + 2048 + h * HD_;
        __syncthreads();
#pragma unroll
        for (int i = 0; i < 2; i++) {
            int e = tid + i * 256;
            int r = e >> 3, dc = (e & 7) << 3;
            *(uint4*)(Ks + r * SSTR + dc) = *(const uint4*)(kg + (size_t)r * QKVN + dc);
            *(uint4*)(Vs + r * SSTR + dc) = *(const uint4*)(vg + (size_t)r * QKVN + dc);
        }
        __syncthreads();

        float s[8][4];
#pragma unroll
        for (int nt = 0; nt < 8; nt++)
#pragma unroll
            for (int i = 0; i < 4; i++) s[nt][i] = 0.f;

        const uint32_t* Qw = (const uint32_t*)Qs;
        const uint32_t* Kw = (const uint32_t*)Ks;
#pragma unroll
        for (int ks = 0; ks < 4; ks++) {
            uint32_t af[4];
            int ai = (wq0 + gid) * 36 + ks * 8 + tig;
            af[0] = Qw[ai]; af[1] = Qw[ai + 288];
            af[2] = Qw[ai + 4]; af[3] = Qw[ai + 292];
#pragma unroll
            for (int nt = 0; nt < 8; nt++) {
                uint32_t bfr[2];
                int bi = (nt * 8 + gid) * 36 + ks * 8 + tig;
                bfr[0] = Kw[bi]; bfr[1] = Kw[bi + 4];
                mma_bf16(s[nt], af, bfr);
            }
        }

        float mx0 = -1e30f, mx1 = -1e30f;
#pragma unroll
        for (int nt = 0; nt < 8; nt++) {
            mx0 = fmaxf(mx0, fmaxf(s[nt][0], s[nt][1]));
            mx1 = fmaxf(mx1, fmaxf(s[nt][2], s[nt][3]));
        }
        mx0 = fmaxf(mx0, __shfl_xor_sync(0xffffffffu, mx0, 1));
        mx0 = fmaxf(mx0, __shfl_xor_sync(0xffffffffu, mx0, 2));
        mx1 = fmaxf(mx1, __shfl_xor_sync(0xffffffffu, mx1, 1));
        mx1 = fmaxf(mx1, __shfl_xor_sync(0xffffffffu, mx1, 2));
        float mn0 = fmaxf(m0, mx0), mn1 = fmaxf(m1, mx1);
        float f0 = __expf(m0 - mn0), f1 = __expf(m1 - mn1);
        m0 = mn0; m1 = mn1;
        float sum0 = 0.f, sum1 = 0.f;
#pragma unroll
        for (int nt = 0; nt < 8; nt++) {
            s[nt][0] = __expf(s[nt][0] - mn0);
            s[nt][1] = __expf(s[nt][1] - mn0);
            s[nt][2] = __expf(s[nt][2] - mn1);
            s[nt][3] = __expf(s[nt][3] - mn1);
            sum0 += s[nt][0] + s[nt][1];
            sum1 += s[nt][2] + s[nt][3];
        }
        sum0 += __shfl_xor_sync(0xffffffffu, sum0, 1);
        sum0 += __shfl_xor_sync(0xffffffffu, sum0, 2);
        sum1 += __shfl_xor_sync(0xffffffffu, sum1, 1);
        sum1 += __shfl_xor_sync(0xffffffffu, sum1, 2);
        l0 = l0 * f0 + sum0;
        l1 = l1 * f1 + sum1;
#pragma unroll
        for (int nt = 0; nt < 8; nt++) {
            accO[nt][0] *= f0; accO[nt][1] *= f0;
            accO[nt][2] *= f1; accO[nt][3] *= f1;
        }

#pragma unroll
        for (int kc = 0; kc < 4; kc++) {
            uint32_t aP[4];
            aP[0] = pack_bf2(s[2 * kc][0],     s[2 * kc][1]);
            aP[1] = pack_bf2(s[2 * kc][2],     s[2 * kc][3]);
            aP[2] = pack_bf2(s[2 * kc + 1][0], s[2 * kc + 1][1]);
            aP[3] = pack_bf2(s[2 * kc + 1][2], s[2 * kc + 1][3]);
#pragma unroll
            for (int ntp = 0; ntp < 4; ntp++) {
                int row = kc * 16 + ((lane >> 3) & 1) * 8 + (lane & 7);
                int col = ntp * 16 + (lane >> 4) * 8;
                uint32_t smaddr = smem_u32(Vs + row * SSTR + col);
                uint32_t b0, b1, b2, b3;
                asm volatile(
                    "ldmatrix.sync.aligned.m8n8.x4.trans.shared.b16 {%0,%1,%2,%3}, [%4];"
                    : "=r"(b0), "=r"(b1), "=r"(b2), "=r"(b3) : "r"(smaddr));
                uint32_t blo[2] = {b0, b1}, bhi[2] = {b2, b3};
                mma_bf16(accO[2 * ntp],     aP, blo);
                mma_bf16(accO[2 * ntp + 1], aP, bhi);
            }
        }
    }

    float il0 = 1.f / l0, il1 = 1.f / l1;
    int row0 = qt * 128 + wq0 + gid;
#pragma unroll
    for (int nt = 0; nt < 8; nt++) {
        int col = nt * 8 + tig * 2;
        *(uint32_t*)(o + obase + (size_t)row0 * DIMC + col) =
            pack_bf2(accO[nt][0] * il0, accO[nt][1] * il0);
        *(uint32_t*)(o + obase + (size_t)(row0 + 8) * DIMC + col) =
            pack_bf2(accO[nt][2] * il1, accO[nt][3] * il1);
    }
}

// ------- blend attention outputs across windows (before wo) -------------------
__global__ __launch_bounds__(256) void blend_ao_kernel()
{
    int row = blockIdx.x;            // 0..MFF-1
    int tid = threadIdx.x;
    bf16* dst = g_x + (size_t)row * DIMC;
    if (row < TENC) {
#pragma unroll
        for (int i = 0; i < 4; i++) {
            int d = tid + i * 256;
            float a = 0.f;
#pragma unroll
            for (int w = 0; w < WQN; w++)
                a += __bfloat162float(g_ao[((size_t)w * LWIN + row) * DIMC + d]);
            dst[d] = __float2bfloat16_rn(a * 0.2f);
        }
    } else {
        int gdx = row - TENC;
        int blk = gdx / SROW;
        float acc[4] = {0.f, 0.f, 0.f, 0.f};
        float wsum = 0.f;
#pragma unroll
        for (int dw = -1; dw <= 0; dw++) {
            int w = blk + dw;
            if (w < 0 || w > 4) continue;
            int lv = gdx - w * SROW;
            float wt = c_pyr[lv / 144];
            wsum += wt;
            const bf16* op = g_ao + ((size_t)w * LWIN + TENC + lv) * DIMC;
#pragma unroll
            for (int i = 0; i < 4; i++)
                acc[i] += wt * __bfloat162float(op[tid + i * 256]);
        }
        float inv = 1.f / wsum;
#pragma unroll
        for (int i = 0; i < 4; i++)
            dst[tid + i * 256] = __float2bfloat16_rn(acc[i] * inv);
    }
}

// ------- post-wo combine: residual + LN2 -> out and ffin ----------------------
__global__ __launch_bounds__(256) void combine_post_kernel(
    const float* __restrict__ hs, const float* __restrict__ enc,
    float* __restrict__ out, const float* __restrict__ g, const float* __restrict__ b)
{
    int row = blockIdx.x;            // 0..MFF-1 (o2 row)
    int tid = threadIdx.x;
    const float* o2 = g_o2 + (size_t)row * DIMC;
    const float* src; float* outp; int gate_off, sc_off, sh_off;
    if (row < TENC) {
        src = enc + (size_t)row * DIMC;
        outp = out + (size_t)(NTOK + row) * DIMC;
        gate_off = 5120; sc_off = 4096; sh_off = 3072;
    } else {
        int gdx = row - TENC;
        src = hs + (size_t)gdx * DIMC;
        outp = out + (size_t)gdx * DIMC;
        gate_off = 2048; sc_off = 1024; sh_off = 0;
    }
    float r[4]; float s = 0.f, s2 = 0.f;
#pragma unroll
    for (int i = 0; i < 4; i++) {
        int d = tid + i * 256;
        r[i] = src[d] + g_emb1[gate_off + d] * o2[d];
        outp[d] = r[i];
        s += r[i]; s2 += r[i] * r[i];
    }
    block_reduce_2(s, s2);
    float mean = s * (1.f / DIMC);
    float var  = s2 * (1.f / DIMC) - mean * mean;
    float inv2 = rsqrtf(var + 1e-5f);
    bf16* dst = g_ffin + (size_t)row * DIMC;
#pragma unroll
    for (int i = 0; i < 4; i++) {
        int d = tid + i * 256;
        float v = (r[i] - mean) * inv2 * g[d] + b[d];
        dst[d] = __float2bfloat16_rn(v * (1.f + g_emb2[sc_off + d]) + g_emb2[sh_off + d]);
    }
}

// ---------------- host side ----------------
static void launch_gemm(const bf16* A, const bf16* B, const float* bias,
                        void* C, int M, int N, int K, int flags)
{
    dim3 grid(N / 128, M / 128);
    gemm_bf16_kernel<<<grid, 256, GEMM_SMEM_B>>>(A, B, bias, C, M, N, K, flags);
}

extern "C" void kernel_launch(void* const* d_in, const int* in_sizes, int n_in,
                              void* d_out, int out_size)
{
    const float* hs    = (const float*)d_in[0];
    const float* enc   = (const float*)d_in[1];
    const float* temb  = (const float*)d_in[2];
    const float* n1w   = (const float*)d_in[3];
    const float* n1b   = (const float*)d_in[4];
    const float* n1g   = (const float*)d_in[5];
    const float* n1bb  = (const float*)d_in[6];
    const float* wq    = (const float*)d_in[7];
    const float* wk    = (const float*)d_in[8];
    const float* wv    = (const float*)d_in[9];
    const float* nqg   = (const float*)d_in[10];
    const float* nqb   = (const float*)d_in[11];
    const float* nkg   = (const float*)d_in[12];
    const float* nkb   = (const float*)d_in[13];
    const float* wo    = (const float*)d_in[14];
    const float* bo    = (const float*)d_in[15];
    const float* n2w   = (const float*)d_in[16];
    const float* n2b   = (const float*)d_in[17];
    const float* n2g   = (const float*)d_in[18];
    const float* n2bb  = (const float*)d_in[19];
    const float* ffw1  = (const float*)d_in[20];
    const float* ffb1  = (const float*)d_in[21];
    const float* ffw2  = (const float*)d_in[22];
    const float* ffb2  = (const float*)d_in[23];
    (void)in_sizes; (void)n_in;

    float* out = (float*)d_out;
    (void)out_size;

    bf16 *p_x, *p_qkv, *p_ao, *p_ffin, *p_h1, *p_wt;
    float *p_o2;
    cudaGetSymbolAddress((void**)&p_x,    g_x);
    cudaGetSymbolAddress((void**)&p_qkv,  g_qkv);
    cudaGetSymbolAddress((void**)&p_ao,   g_ao);
    cudaGetSymbolAddress((void**)&p_o2,   g_o2);
    cudaGetSymbolAddress((void**)&p_ffin, g_ffin);
    cudaGetSymbolAddress((void**)&p_h1,   g_h1);
    cudaGetSymbolAddress((void**)&p_wt,   g_wt);

    bf16* wtqkv = p_wt;                       // [3072][1024] (wq^T|wk^T|wv^T)
    bf16* wtw1  = p_wt + (size_t)4 * MEG;     // [4096][1024]
    bf16* wtw2  = p_wt + (size_t)8 * MEG;     // [1024][4096]
    bf16* wtwo  = p_wt + (size_t)3 * MEG;     // [1024][1024]

    cudaFuncSetAttribute(attn_bf16_kernel, cudaFuncAttributeMaxDynamicSharedMemorySize, ATTN_SMEM_B);
    cudaFuncSetAttribute(gemm_bf16_kernel, cudaFuncAttributeMaxDynamicSharedMemorySize, GEMM_SMEM_B);

    // 0. weight prep (4 square transposes in one launch; 2 big ones separate)
    dim3 tb(32, 8);
    round_wT4_kernel<<<dim3(32, 32, 4), tb>>>(wq, wk, wv, wo, wtqkv);
    round_wT_kernel<<<dim3(128, 32), tb>>>(ffw1, wtw1, 1024, 4096);
    round_wT_kernel<<<dim3(32, 128), tb>>>(ffw2, wtw2, 4096, 1024);

    // 1. modulation embeddings
    emb_kernel<<<48, 256>>>(temb, n1w, n1b, n2w, n2b);
    // 2. unique x rows (bf16)
    build_x_kernel<<<MFF, 256>>>(hs, enc, n1g, n1bb);
    // 3. fused QKV projection -> bf16
    launch_gemm(p_x, wtqkv, nullptr, p_qkv, MFF, QKVN, DIMC, 2);
    // 4. per-head LN on q (x0.125 folded) and k, one launch
    qkln2_kernel<<<dim3(MFF * HEADS_ / 8, 2), 256>>>(p_qkv, nqg, nqb, nkg, nkb);
    // 5. attention
    attn_bf16_kernel<<<dim3(LWIN / 128, HEADS_, WQN), 256, ATTN_SMEM_B>>>(p_qkv, p_ao);
    // 6. blend windows BEFORE wo (row-linear commute), then wo on 3584 rows
    blend_ao_kernel<<<MFF, 256>>>();
    launch_gemm(p_x, wtwo, bo, p_o2, MFF, DIMC, DIMC, 0);
    // 7. residual + LN2 -> out, ffin
    combine_post_kernel<<<MFF, 256>>>(hs, enc, out, n2g, n2bb);
    // 8. FFN; ffn2 fuses final gated residual into out
    launch_gemm(p_ffin, wtw1, ffb1, p_h1, MFF, 4096, DIMC, 1 | 2);
    launch_gemm(p_h1, wtw2, ffb2, out, MFF, DIMC, 4096, 4);
}

// round 12
// speedup vs baseline: 7.4085x; 1.0607x over previous
#include <cuda_runtime.h>
#include <cuda_bf16.h>
#include <math.h>
#include <stdint.h>

typedef __nv_bfloat16 bf16;

// ---------------- constants ----------------
#define DIMC   1024
#define TEMBC  512
#define NTOK   3456
#define TENC   128
#define WQN    5
#define LWIN   1280
#define SROW   576
#define MQ     6400
#define MFF    3584
#define HEADS_ 16
#define HD_    64
#define QKVN   3072
#define MEG    1048576

// ---------------- device scratch ----------------
__device__ float g_emb1[6144];
__device__ float g_emb2[6144];
__device__ bf16  g_x   [(size_t)MFF * DIMC];   // x rows; later reused as blended ao
__device__ bf16  g_qkv [(size_t)MFF * QKVN];
__device__ bf16  g_ao  [(size_t)MQ * DIMC];
__device__ float g_o2  [(size_t)MFF * DIMC];
__device__ bf16  g_ffin[(size_t)MFF * DIMC];
__device__ bf16  g_h1  [(size_t)MFF * 4096];
__device__ bf16  g_wt  [(size_t)12 * MEG];     // qkv^T(3M), wo^T(1M), w1^T(4M), w2^T(4M)

__constant__ float c_pyr[8] = {1.f,2.f,3.f,4.f,4.f,3.f,2.f,1.f};

// ---------------- helpers ----------------
__device__ __forceinline__ uint32_t pack_bf2(float lo, float hi) {
    uint32_t r;
    asm("cvt.rn.bf16x2.f32 %0, %1, %2;" : "=r"(r) : "f"(hi), "f"(lo));
    return r;
}

__device__ __forceinline__ uint32_t smem_u32(const void* p) {
    return (uint32_t)__cvta_generic_to_shared(p);
}

__device__ __forceinline__ void block_reduce_2(float &s, float &s2) {
    __shared__ float ra[8], rb[8];
#pragma unroll
    for (int m = 16; m > 0; m >>= 1) {
        s  += __shfl_xor_sync(0xffffffffu, s,  m);
        s2 += __shfl_xor_sync(0xffffffffu, s2, m);
    }
    int wid = threadIdx.x >> 5;
    if ((threadIdx.x & 31) == 0) { ra[wid] = s; rb[wid] = s2; }
    __syncthreads();
    s  = ra[0]+ra[1]+ra[2]+ra[3]+ra[4]+ra[5]+ra[6]+ra[7];
    s2 = rb[0]+rb[1]+rb[2]+rb[3]+rb[4]+rb[5]+rb[6]+rb[7];
    __syncthreads();
}

__device__ __forceinline__ float tanh_fast(float x) {
    float y;
    asm("tanh.approx.f32 %0, %1;" : "=f"(y) : "f"(x));
    return y;
}

__device__ __forceinline__ float gelu_tanh(float x) {
    float x3 = x * x * x;
    return 0.5f * x * (1.f + tanh_fast(0.79788456080286535588f * (x + 0.044715f * x3)));
}

__device__ __forceinline__ void mma_bf16(float* d, const uint32_t* a, const uint32_t* b) {
    asm volatile(
        "mma.sync.aligned.m16n8k16.row.col.f32.bf16.bf16.f32 "
        "{%0,%1,%2,%3}, {%4,%5,%6,%7}, {%8,%9}, {%0,%1,%2,%3};"
        : "+f"(d[0]), "+f"(d[1]), "+f"(d[2]), "+f"(d[3])
        : "r"(a[0]), "r"(a[1]), "r"(a[2]), "r"(a[3]), "r"(b[0]), "r"(b[1]));
}

// ---------------- weight prep: transpose + round to bf16 ----------------
// 4 square 1024x1024 weights in one launch (z selects weight)
__global__ __launch_bounds__(256) void round_wT4_kernel(
    const float* __restrict__ w0, const float* __restrict__ w1,
    const float* __restrict__ w2, const float* __restrict__ w3,
    bf16* __restrict__ dst)
{
    __shared__ float t[32][33];
    int z = blockIdx.z;
    const float* W = (z == 0) ? w0 : (z == 1) ? w1 : (z == 2) ? w2 : w3;
    bf16* WT = dst + (size_t)z * MEG;
    int n0 = blockIdx.x * 32, k0 = blockIdx.y * 32;
    int tx = threadIdx.x, ty = threadIdx.y;
#pragma unroll
    for (int j = 0; j < 4; j++)
        t[ty + 8 * j][tx] = W[(size_t)(k0 + ty + 8 * j) * 1024 + n0 + tx];
    __syncthreads();
#pragma unroll
    for (int j = 0; j < 4; j++)
        WT[(size_t)(n0 + ty + 8 * j) * 1024 + k0 + tx] =
            __float2bfloat16_rn(t[tx][ty + 8 * j]);
}

// ffn1 [1024][4096] + ffn2 [4096][1024] in one launch (z selects; z=1 remaps)
__global__ __launch_bounds__(256) void round_wT2_kernel(
    const float* __restrict__ w1, bf16* __restrict__ wt1,
    const float* __restrict__ w2, bf16* __restrict__ wt2)
{
    __shared__ float t[32][33];
    const float* W; bf16* WT; int K, N, n0, k0;
    if (blockIdx.z == 0) {
        W = w1; WT = wt1; K = 1024; N = 4096;
        n0 = blockIdx.x * 32; k0 = blockIdx.y * 32;
    } else {
        W = w2; WT = wt2; K = 4096; N = 1024;
        int lin = blockIdx.x * 32 + blockIdx.y;   // 0..4095
        n0 = (lin & 31) * 32; k0 = (lin >> 5) * 32;
    }
    int tx = threadIdx.x, ty = threadIdx.y;
#pragma unroll
    for (int j = 0; j < 4; j++)
        t[ty + 8 * j][tx] = W[(size_t)(k0 + ty + 8 * j) * N + n0 + tx];
    __syncthreads();
#pragma unroll
    for (int j = 0; j < 4; j++)
        WT[(size_t)(n0 + ty + 8 * j) * K + k0 + tx] =
            __float2bfloat16_rn(t[tx][ty + 8 * j]);
}

// ---------------- emb = silu(temb) @ W + b  (high-occupancy version) ----------
// grid 384 blocks; block owns 32 output columns; 8 warps split K=512 into
// 64-row chunks; lane -> column keeps weight reads coalesced.
__global__ __launch_bounds__(256) void emb2_kernel(
    const float* __restrict__ temb,
    const float* __restrict__ w1, const float* __restrict__ b1,
    const float* __restrict__ w2, const float* __restrict__ b2)
{
    __shared__ float st[TEMBC];
    __shared__ float part[8][32];
    int tid = threadIdx.x, lane = tid & 31, wid = tid >> 5;
    for (int i = tid; i < TEMBC; i += 256) {
        float t = temb[i];
        st[i] = t / (1.f + expf(-t));
    }
    __syncthreads();

    int colg = blockIdx.x * 32;          // global column group 0..12287
    const float* w; const float* bb; float* out; int col;
    if (colg < 6144) { w = w1; bb = b1; out = g_emb1; col = colg + lane; }
    else             { w = w2; bb = b2; out = g_emb2; col = colg - 6144 + lane; }

    float acc = 0.f;
    int k0 = wid * 64;
#pragma unroll 16
    for (int kk = 0; kk < 64; kk++)
        acc += st[k0 + kk] * w[(size_t)(k0 + kk) * 6144 + col];
    part[wid][lane] = acc;
    __syncthreads();
    if (wid == 0) {
        float s = 0.f;
#pragma unroll
        for (int i = 0; i < 8; i++) s += part[i][lane];
        out[col] = s + bb[col];
    }
}

// ---------------- build unique x rows (bf16 out) ----------------
__global__ __launch_bounds__(256) void build_x_kernel(
    const float* __restrict__ hs, const float* __restrict__ enc,
    const float* __restrict__ g, const float* __restrict__ b)
{
    int row = blockIdx.x;
    const float* src; int sc_off, sh_off;
    if (row < TENC) { src = enc + (size_t)row * DIMC; sc_off = 4096; sh_off = 3072; }
    else            { src = hs + (size_t)(row - TENC) * DIMC; sc_off = 1024; sh_off = 0; }
    int tid = threadIdx.x;
    float x[4]; float s = 0.f, s2 = 0.f;
#pragma unroll
    for (int i = 0; i < 4; i++) {
        x[i] = src[tid + i * 256];
        s += x[i]; s2 += x[i] * x[i];
    }
    block_reduce_2(s, s2);
    float mean = s * (1.f / DIMC);
    float var  = s2 * (1.f / DIMC) - mean * mean;
    float inv  = rsqrtf(var + 1e-5f);
    bf16* dst = g_x + (size_t)row * DIMC;
#pragma unroll
    for (int i = 0; i < 4; i++) {
        int d = tid + i * 256;
        float v = (x[i] - mean) * inv * g[d] + b[d];
        dst[d] = __float2bfloat16_rn(v * (1.f + g_emb1[sc_off + d]) + g_emb1[sh_off + d]);
    }
}

// ---------------- BF16 tensor-core GEMM: C = A(MxK) * WT(NxK)^T ---------------
// flags: 1=gelu, 2=bf16 out, 4=ffn2-fused-final-add (f32 RMW on C)
#define SSTR 72
#define ABUF_B 18432                   // 128*SSTR*2 bytes per stage buffer
#define GEMM_SMEM_B (2 * 2 * 128 * SSTR * 2)   // 73728 B

__global__ __launch_bounds__(256, 2) void gemm_bf16_kernel(
    const bf16* __restrict__ A, const bf16* __restrict__ B,
    const float* __restrict__ bias, void* __restrict__ Cv,
    int M, int N, int K, int flags)
{
    extern __shared__ bf16 smb[];
    bf16* As0 = smb;
    bf16* Bs0 = smb + 2 * 128 * SSTR;

    int tid = threadIdx.x;
    int bm = blockIdx.y, bn = blockIdx.x;
    int lane = tid & 31, wid = tid >> 5;
    int wm = (wid & 1) * 64, wn = (wid >> 1) * 32;
    int gid = lane >> 2, tig = lane & 3;

    const bf16* Ag = A + (size_t)bm * 128 * K;
    const bf16* Bg = B + (size_t)bn * 128 * K;

    uint32_t smbase = smem_u32(smb);
    uint32_t aBase0 = smbase + (uint32_t)((wm + (lane & 15)) * 144 + (lane >> 4) * 16);
    uint32_t bBase0 = smbase + 36864u +
                      (uint32_t)((wn + (lane & 7) + ((lane >> 4) << 3)) * 144 +
                                 ((lane >> 3) & 1) * 16);

    float acc[4][4][4];
#pragma unroll
    for (int a = 0; a < 4; a++)
#pragma unroll
        for (int b = 0; b < 4; b++)
#pragma unroll
            for (int c = 0; c < 4; c++) acc[a][b][c] = 0.f;

#define LOAD_TILE(kt, buf)                                                         \
    {                                                                              \
        bf16* ad = As0 + (buf) * 128 * SSTR;                                       \
        bf16* bd = Bs0 + (buf) * 128 * SSTR;                                       \
        _Pragma("unroll")                                                          \
        for (int i = 0; i < 4; i++) {                                              \
            int c = tid + i * 256;                                                 \
            int r = c >> 3, kc = (c & 7) << 3;                                     \
            uint32_t dsm = (uint32_t)__cvta_generic_to_shared(ad + r * SSTR + kc); \
            const bf16* s = Ag + (size_t)r * K + (kt) * 64 + kc;                   \
            asm volatile("cp.async.cg.shared.global [%0], [%1], 16;"               \
                         :: "r"(dsm), "l"(s));                                     \
        }                                                                          \
        _Pragma("unroll")                                                          \
        for (int i = 0; i < 4; i++) {                                              \
            int c = tid + i * 256;                                                 \
            int r = c >> 3, kc = (c & 7) << 3;                                     \
            uint32_t dsm = (uint32_t)__cvta_generic_to_shared(bd + r * SSTR + kc); \
            const bf16* s = Bg + (size_t)r * K + (kt) * 64 + kc;                   \
            asm volatile("cp.async.cg.shared.global [%0], [%1], 16;"               \
                         :: "r"(dsm), "l"(s));                                     \
        }                                                                          \
    }

    LOAD_TILE(0, 0);
    asm volatile("cp.async.commit_group;");

    int ktiles = K / 64;
    for (int t = 0; t < ktiles; t++) {
        int buf = t & 1;
        if (t + 1 < ktiles) {
            LOAD_TILE(t + 1, buf ^ 1);
            asm volatile("cp.async.commit_group;");
            asm volatile("cp.async.wait_group 1;");
        } else {
            asm volatile("cp.async.wait_group 0;");
        }
        __syncthreads();

        uint32_t aB = aBase0 + (uint32_t)buf * ABUF_B;
        uint32_t bB = bBase0 + (uint32_t)buf * ABUF_B;
#pragma unroll
        for (int ks = 0; ks < 4; ks++) {
            uint32_t af[4][4], bfr[2][4];
#pragma unroll
            for (int mt = 0; mt < 4; mt++)
                asm volatile(
                    "ldmatrix.sync.aligned.m8n8.x4.shared.b16 {%0,%1,%2,%3}, [%4];"
                    : "=r"(af[mt][0]), "=r"(af[mt][1]), "=r"(af[mt][2]), "=r"(af[mt][3])
                    : "r"(aB + mt * 2304 + ks * 32));
#pragma unroll
            for (int np = 0; np < 2; np++)
                asm volatile(
                    "ldmatrix.sync.aligned.m8n8.x4.shared.b16 {%0,%1,%2,%3}, [%4];"
                    : "=r"(bfr[np][0]), "=r"(bfr[np][1]), "=r"(bfr[np][2]), "=r"(bfr[np][3])
                    : "r"(bB + np * 2304 + ks * 32));
#pragma unroll
            for (int mt = 0; mt < 4; mt++) {
                mma_bf16(acc[mt][0], af[mt], &bfr[0][0]);
                mma_bf16(acc[mt][1], af[mt], &bfr[0][2]);
                mma_bf16(acc[mt][2], af[mt], &bfr[1][0]);
                mma_bf16(acc[mt][3], af[mt], &bfr[1][2]);
            }
        }
        __syncthreads();
    }

    int act = flags & 1, outbf = flags & 2, fin = flags & 4;
#pragma unroll
    for (int mt = 0; mt < 4; mt++) {
        int row = bm * 128 + wm + mt * 16 + gid;
#pragma unroll
        for (int nt = 0; nt < 4; nt++) {
            int col = bn * 128 + wn + nt * 8 + tig * 2;
            float b0 = bias ? bias[col] : 0.f;
            float b1 = bias ? bias[col + 1] : 0.f;
            float v0 = acc[mt][nt][0] + b0, v1 = acc[mt][nt][1] + b1;
            float v2 = acc[mt][nt][2] + b0, v3 = acc[mt][nt][3] + b1;
            if (act) { v0 = gelu_tanh(v0); v1 = gelu_tanh(v1); v2 = gelu_tanh(v2); v3 = gelu_tanh(v3); }
            if (fin) {
                float* C = (float*)Cv;
                int goff  = (row < TENC) ? 5120 : 2048;
                int orow0 = (row < TENC) ? (NTOK + row)     : (row - TENC);
                int orow1 = (row < TENC) ? (NTOK + row + 8) : (row + 8 - TENC);
                float ga = g_emb2[goff + col], gb = g_emb2[goff + col + 1];
                float* p0 = C + (size_t)orow0 * N + col;
                float* p1 = C + (size_t)orow1 * N + col;
                p0[0] += ga * v0; p0[1] += gb * v1;
                p1[0] += ga * v2; p1[1] += gb * v3;
            } else if (outbf) {
                bf16* C = (bf16*)Cv;
                *(uint32_t*)(C + (size_t)row * N + col)       = pack_bf2(v0, v1);
                *(uint32_t*)(C + (size_t)(row + 8) * N + col) = pack_bf2(v2, v3);
            } else {
                float* C = (float*)Cv;
                *(float2*)(C + (size_t)row * N + col)       = make_float2(v0, v1);
                *(float2*)(C + (size_t)(row + 8) * N + col) = make_float2(v2, v3);
            }
        }
    }
}

// ------- per-head LN on q and k in one launch (y: 0=q scale .125, 1=k) --------
__global__ __launch_bounds__(256) void qkln2_kernel(
    bf16* __restrict__ buf,
    const float* __restrict__ qg, const float* __restrict__ qb,
    const float* __restrict__ kg, const float* __restrict__ kb)
{
    int seg  = blockIdx.x * 8 + (threadIdx.x >> 5);
    int lane = threadIdx.x & 31;
    int isk  = blockIdx.y;
    const float* g = isk ? kg : qg;
    const float* b = isk ? kb : qb;
    float scale = isk ? 1.0f : 0.125f;
    bf16* p = buf + (size_t)(seg >> 4) * QKVN + isk * 1024 + (seg & 15) * HD_;
    float x0 = __bfloat162float(p[lane]);
    float x1 = __bfloat162float(p[lane + 32]);
    float s = x0 + x1, s2 = x0 * x0 + x1 * x1;
#pragma unroll
    for (int m = 16; m > 0; m >>= 1) {
        s  += __shfl_xor_sync(0xffffffffu, s,  m);
        s2 += __shfl_xor_sync(0xffffffffu, s2, m);
    }
    float mean = s * (1.f / 64.f);
    float var  = s2 * (1.f / 64.f) - mean * mean;
    float inv  = rsqrtf(var + 1e-6f);
    p[lane]      = __float2bfloat16_rn(((x0 - mean) * inv * g[lane]      + b[lane])      * scale);
    p[lane + 32] = __float2bfloat16_rn(((x1 - mean) * inv * g[lane + 32] + b[lane + 32]) * scale);
}

// ---------------- BF16 flash attention (mma.sync) ----------------
#define ATTN_SMEM_B ((128 + 64 + 64) * SSTR * 2)

__global__ __launch_bounds__(256, 2) void attn_bf16_kernel(
    const bf16* __restrict__ qkv, bf16* __restrict__ o)
{
    extern __shared__ bf16 smb[];
    bf16* Qs = smb;
    bf16* Ks = smb + 128 * SSTR;
    bf16* Vs = Ks + 64 * SSTR;

    int qt = blockIdx.x, h = blockIdx.y, w = blockIdx.z;
    int tid = threadIdx.x, lane = tid & 31, wid = tid >> 5;
    int gid = lane >> 2, tig = lane & 3;
    int wq0 = wid * 16;
    const size_t obase = (size_t)w * LWIN * DIMC + (size_t)h * HD_;

    size_t qrow0 = (size_t)qt * 128 + (qt ? (size_t)w * SROW : 0);
    const bf16* qg = qkv + qrow0 * QKVN + h * HD_;

#pragma unroll
    for (int i = 0; i < 4; i++) {
        int e = tid + i * 256;
        int r = e >> 3, dc = (e & 7) << 3;
        *(uint4*)(Qs + r * SSTR + dc) = *(const uint4*)(qg + (size_t)r * QKVN + dc);
    }

    float accO[8][4];
#pragma unroll
    for (int nt = 0; nt < 8; nt++)
#pragma unroll
        for (int i = 0; i < 4; i++) accO[nt][i] = 0.f;
    float m0 = -1e30f, m1 = -1e30f, l0 = 0.f, l1 = 0.f;

    for (int kt = 0; kt < 20; kt++) {
        size_t krow0 = (size_t)kt * 64 + (kt >= 2 ? (size_t)w * SROW : 0);
        const bf16* kg = qkv + krow0 * QKVN + 1024 + h * HD_;
        const bf16* vg = qkv + krow0 * QKVN + 2048 + h * HD_;
        __syncthreads();
#pragma unroll
        for (int i = 0; i < 2; i++) {
            int e = tid + i * 256;
            int r = e >> 3, dc = (e & 7) << 3;
            *(uint4*)(Ks + r * SSTR + dc) = *(const uint4*)(kg + (size_t)r * QKVN + dc);
            *(uint4*)(Vs + r * SSTR + dc) = *(const uint4*)(vg + (size_t)r * QKVN + dc);
        }
        __syncthreads();

        float s[8][4];
#pragma unroll
        for (int nt = 0; nt < 8; nt++)
#pragma unroll
            for (int i = 0; i < 4; i++) s[nt][i] = 0.f;

        const uint32_t* Qw = (const uint32_t*)Qs;
        const uint32_t* Kw = (const uint32_t*)Ks;
#pragma unroll
        for (int ks = 0; ks < 4; ks++) {
            uint32_t af[4];
            int ai = (wq0 + gid) * 36 + ks * 8 + tig;
            af[0] = Qw[ai]; af[1] = Qw[ai + 288];
            af[2] = Qw[ai + 4]; af[3] = Qw[ai + 292];
#pragma unroll
            for (int nt = 0; nt < 8; nt++) {
                uint32_t bfr[2];
                int bi = (nt * 8 + gid) * 36 + ks * 8 + tig;
                bfr[0] = Kw[bi]; bfr[1] = Kw[bi + 4];
                mma_bf16(s[nt], af, bfr);
            }
        }

        float mx0 = -1e30f, mx1 = -1e30f;
#pragma unroll
        for (int nt = 0; nt < 8; nt++) {
            mx0 = fmaxf(mx0, fmaxf(s[nt][0], s[nt][1]));
            mx1 = fmaxf(mx1, fmaxf(s[nt][2], s[nt][3]));
        }
        mx0 = fmaxf(mx0, __shfl_xor_sync(0xffffffffu, mx0, 1));
        mx0 = fmaxf(mx0, __shfl_xor_sync(0xffffffffu, mx0, 2));
        mx1 = fmaxf(mx1, __shfl_xor_sync(0xffffffffu, mx1, 1));
        mx1 = fmaxf(mx1, __shfl_xor_sync(0xffffffffu, mx1, 2));
        float mn0 = fmaxf(m0, mx0), mn1 = fmaxf(m1, mx1);
        float f0 = __expf(m0 - mn0), f1 = __expf(m1 - mn1);
        m0 = mn0; m1 = mn1;
        float sum0 = 0.f, sum1 = 0.f;
#pragma unroll
        for (int nt = 0; nt < 8; nt++) {
            s[nt][0] = __expf(s[nt][0] - mn0);
            s[nt][1] = __expf(s[nt][1] - mn0);
            s[nt][2] = __expf(s[nt][2] - mn1);
            s[nt][3] = __expf(s[nt][3] - mn1);
            sum0 += s[nt][0] + s[nt][1];
            sum1 += s[nt][2] + s[nt][3];
        }
        sum0 += __shfl_xor_sync(0xffffffffu, sum0, 1);
        sum0 += __shfl_xor_sync(0xffffffffu, sum0, 2);
        sum1 += __shfl_xor_sync(0xffffffffu, sum1, 1);
        sum1 += __shfl_xor_sync(0xffffffffu, sum1, 2);
        l0 = l0 * f0 + sum0;
        l1 = l1 * f1 + sum1;
#pragma unroll
        for (int nt = 0; nt < 8; nt++) {
            accO[nt][0] *= f0; accO[nt][1] *= f0;
            accO[nt][2] *= f1; accO[nt][3] *= f1;
        }

#pragma unroll
        for (int kc = 0; kc < 4; kc++) {
            uint32_t aP[4];
            aP[0] = pack_bf2(s[2 * kc][0],     s[2 * kc][1]);
            aP[1] = pack_bf2(s[2 * kc][2],     s[2 * kc][3]);
            aP[2] = pack_bf2(s[2 * kc + 1][0], s[2 * kc + 1][1]);
            aP[3] = pack_bf2(s[2 * kc + 1][2], s[2 * kc + 1][3]);
#pragma unroll
            for (int ntp = 0; ntp < 4; ntp++) {
                int row = kc * 16 + ((lane >> 3) & 1) * 8 + (lane & 7);
                int col = ntp * 16 + (lane >> 4) * 8;
                uint32_t smaddr = smem_u32(Vs + row * SSTR + col);
                uint32_t b0, b1, b2, b3;
                asm volatile(
                    "ldmatrix.sync.aligned.m8n8.x4.trans.shared.b16 {%0,%1,%2,%3}, [%4];"
                    : "=r"(b0), "=r"(b1), "=r"(b2), "=r"(b3) : "r"(smaddr));
                uint32_t blo[2] = {b0, b1}, bhi[2] = {b2, b3};
                mma_bf16(accO[2 * ntp],     aP, blo);
                mma_bf16(accO[2 * ntp + 1], aP, bhi);
            }
        }
    }

    float il0 = 1.f / l0, il1 = 1.f / l1;
    int row0 = qt * 128 + wq0 + gid;
#pragma unroll
    for (int nt = 0; nt < 8; nt++) {
        int col = nt * 8 + tig * 2;
        *(uint32_t*)(o + obase + (size_t)row0 * DIMC + col) =
            pack_bf2(accO[nt][0] * il0, accO[nt][1] * il0);
        *(uint32_t*)(o + obase + (size_t)(row0 + 8) * DIMC + col) =
            pack_bf2(accO[nt][2] * il1, accO[nt][3] * il1);
    }
}

// ------- blend attention outputs across windows (before wo) -------------------
__global__ __launch_bounds__(256) void blend_ao_kernel()
{
    int row = blockIdx.x;            // 0..MFF-1
    int tid = threadIdx.x;
    bf16* dst = g_x + (size_t)row * DIMC;
    if (row < TENC) {
#pragma unroll
        for (int i = 0; i < 4; i++) {
            int d = tid + i * 256;
            float a = 0.f;
#pragma unroll
            for (int w = 0; w < WQN; w++)
                a += __bfloat162float(g_ao[((size_t)w * LWIN + row) * DIMC + d]);
            dst[d] = __float2bfloat16_rn(a * 0.2f);
        }
    } else {
        int gdx = row - TENC;
        int blk = gdx / SROW;
        float acc[4] = {0.f, 0.f, 0.f, 0.f};
        float wsum = 0.f;
#pragma unroll
        for (int dw = -1; dw <= 0; dw++) {
            int w = blk + dw;
            if (w < 0 || w > 4) continue;
            int lv = gdx - w * SROW;
            float wt = c_pyr[lv / 144];
            wsum += wt;
            const bf16* op = g_ao + ((size_t)w * LWIN + TENC + lv) * DIMC;
#pragma unroll
            for (int i = 0; i < 4; i++)
                acc[i] += wt * __bfloat162float(op[tid + i * 256]);
        }
        float inv = 1.f / wsum;
#pragma unroll
        for (int i = 0; i < 4; i++)
            dst[tid + i * 256] = __float2bfloat16_rn(acc[i] * inv);
    }
}

// ------- post-wo combine: residual + LN2 -> out and ffin ----------------------
__global__ __launch_bounds__(256) void combine_post_kernel(
    const float* __restrict__ hs, const float* __restrict__ enc,
    float* __restrict__ out, const float* __restrict__ g, const float* __restrict__ b)
{
    int row = blockIdx.x;            // 0..MFF-1 (o2 row)
    int tid = threadIdx.x;
    const float* o2 = g_o2 + (size_t)row * DIMC;
    const float* src; float* outp; int gate_off, sc_off, sh_off;
    if (row < TENC) {
        src = enc + (size_t)row * DIMC;
        outp = out + (size_t)(NTOK + row) * DIMC;
        gate_off = 5120; sc_off = 4096; sh_off = 3072;
    } else {
        int gdx = row - TENC;
        src = hs + (size_t)gdx * DIMC;
        outp = out + (size_t)gdx * DIMC;
        gate_off = 2048; sc_off = 1024; sh_off = 0;
    }
    float r[4]; float s = 0.f, s2 = 0.f;
#pragma unroll
    for (int i = 0; i < 4; i++) {
        int d = tid + i * 256;
        r[i] = src[d] + g_emb1[gate_off + d] * o2[d];
        outp[d] = r[i];
        s += r[i]; s2 += r[i] * r[i];
    }
    block_reduce_2(s, s2);
    float mean = s * (1.f / DIMC);
    float var  = s2 * (1.f / DIMC) - mean * mean;
    float inv2 = rsqrtf(var + 1e-5f);
    bf16* dst = g_ffin + (size_t)row * DIMC;
#pragma unroll
    for (int i = 0; i < 4; i++) {
        int d = tid + i * 256;
        float v = (r[i] - mean) * inv2 * g[d] + b[d];
        dst[d] = __float2bfloat16_rn(v * (1.f + g_emb2[sc_off + d]) + g_emb2[sh_off + d]);
    }
}

// ---------------- host side ----------------
static void launch_gemm(const bf16* A, const bf16* B, const float* bias,
                        void* C, int M, int N, int K, int flags)
{
    dim3 grid(N / 128, M / 128);
    gemm_bf16_kernel<<<grid, 256, GEMM_SMEM_B>>>(A, B, bias, C, M, N, K, flags);
}

extern "C" void kernel_launch(void* const* d_in, const int* in_sizes, int n_in,
                              void* d_out, int out_size)
{
    const float* hs    = (const float*)d_in[0];
    const float* enc   = (const float*)d_in[1];
    const float* temb  = (const float*)d_in[2];
    const float* n1w   = (const float*)d_in[3];
    const float* n1b   = (const float*)d_in[4];
    const float* n1g   = (const float*)d_in[5];
    const float* n1bb  = (const float*)d_in[6];
    const float* wq    = (const float*)d_in[7];
    const float* wk    = (const float*)d_in[8];
    const float* wv    = (const float*)d_in[9];
    const float* nqg   = (const float*)d_in[10];
    const float* nqb   = (const float*)d_in[11];
    const float* nkg   = (const float*)d_in[12];
    const float* nkb   = (const float*)d_in[13];
    const float* wo    = (const float*)d_in[14];
    const float* bo    = (const float*)d_in[15];
    const float* n2w   = (const float*)d_in[16];
    const float* n2b   = (const float*)d_in[17];
    const float* n2g   = (const float*)d_in[18];
    const float* n2bb  = (const float*)d_in[19];
    const float* ffw1  = (const float*)d_in[20];
    const float* ffb1  = (const float*)d_in[21];
    const float* ffw2  = (const float*)d_in[22];
    const float* ffb2  = (const float*)d_in[23];
    (void)in_sizes; (void)n_in;

    float* out = (float*)d_out;
    (void)out_size;

    bf16 *p_x, *p_qkv, *p_ao, *p_ffin, *p_h1, *p_wt;
    float *p_o2;
    cudaGetSymbolAddress((void**)&p_x,    g_x);
    cudaGetSymbolAddress((void**)&p_qkv,  g_qkv);
    cudaGetSymbolAddress((void**)&p_ao,   g_ao);
    cudaGetSymbolAddress((void**)&p_o2,   g_o2);
    cudaGetSymbolAddress((void**)&p_ffin, g_ffin);
    cudaGetSymbolAddress((void**)&p_h1,   g_h1);
    cudaGetSymbolAddress((void**)&p_wt,   g_wt);

    bf16* wtqkv = p_wt;                       // [3072][1024] (wq^T|wk^T|wv^T)
    bf16* wtwo  = p_wt + (size_t)3 * MEG;     // [1024][1024]
    bf16* wtw1  = p_wt + (size_t)4 * MEG;     // [4096][1024]
    bf16* wtw2  = p_wt + (size_t)8 * MEG;     // [1024][4096]

    cudaFuncSetAttribute(attn_bf16_kernel, cudaFuncAttributeMaxDynamicSharedMemorySize, ATTN_SMEM_B);
    cudaFuncSetAttribute(gemm_bf16_kernel, cudaFuncAttributeMaxDynamicSharedMemorySize, GEMM_SMEM_B);

    // 0. weight prep (4 square transposes in 1 launch; ffn pair in 1 launch)
    dim3 tb(32, 8);
    round_wT4_kernel<<<dim3(32, 32, 4), tb>>>(wq, wk, wv, wo, wtqkv);
    round_wT2_kernel<<<dim3(128, 32, 2), tb>>>(ffw1, wtw1, ffw2, wtw2);

    // 1. modulation embeddings (high-occupancy)
    emb2_kernel<<<384, 256>>>(temb, n1w, n1b, n2w, n2b);
    // 2. unique x rows (bf16)
    build_x_kernel<<<MFF, 256>>>(hs, enc, n1g, n1bb);
    // 3. fused QKV projection -> bf16
    launch_gemm(p_x, wtqkv, nullptr, p_qkv, MFF, QKVN, DIMC, 2);
    // 4. per-head LN on q (x0.125 folded) and k, one launch
    qkln2_kernel<<<dim3(MFF * HEADS_ / 8, 2), 256>>>(p_qkv, nqg, nqb, nkg, nkb);
    // 5. attention
    attn_bf16_kernel<<<dim3(LWIN / 128, HEADS_, WQN), 256, ATTN_SMEM_B>>>(p_qkv, p_ao);
    // 6. blend windows BEFORE wo (row-linear commute), then wo on 3584 rows
    blend_ao_kernel<<<MFF, 256>>>();
    launch_gemm(p_x, wtwo, bo, p_o2, MFF, DIMC, DIMC, 0);
    // 7. residual + LN2 -> out, ffin
    combine_post_kernel<<<MFF, 256>>>(hs, enc, out, n2g, n2bb);
    // 8. FFN; ffn2 fuses final gated residual into out
    launch_gemm(p_ffin, wtw1, ffb1, p_h1, MFF, 4096, DIMC, 1 | 2);
    launch_gemm(p_h1, wtw2, ffb2, out, MFF, DIMC, 4096, 4);
}

// round 13
// speedup vs baseline: 7.5496x; 1.0190x over previous
#include <cuda_runtime.h>
#include <cuda_bf16.h>
#include <math.h>
#include <stdint.h>

typedef __nv_bfloat16 bf16;

// ---------------- constants ----------------
#define DIMC   1024
#define TEMBC  512
#define NTOK   3456
#define TENC   128
#define WQN    5
#define LWIN   1280
#define SROW   576
#define MQ     6400
#define MFF    3584
#define HEADS_ 16
#define HD_    64
#define QKVN   3072
#define MEG    1048576

// ---------------- device scratch ----------------
__device__ float g_emb1[6144];
__device__ float g_emb2[6144];
__device__ bf16  g_x   [(size_t)MFF * DIMC];   // x rows; later reused as blended ao
__device__ bf16  g_qkv [(size_t)MFF * QKVN];
__device__ bf16  g_ao  [(size_t)MQ * DIMC];
__device__ float g_o2  [(size_t)MFF * DIMC];
__device__ bf16  g_ffin[(size_t)MFF * DIMC];
__device__ bf16  g_h1  [(size_t)MFF * 4096];
__device__ bf16  g_wt  [(size_t)12 * MEG];     // qkv^T(3M), wo^T(1M), w1^T(4M), w2^T(4M)

__constant__ float c_pyr[8] = {1.f,2.f,3.f,4.f,4.f,3.f,2.f,1.f};

// ---------------- helpers ----------------
__device__ __forceinline__ uint32_t pack_bf2(float lo, float hi) {
    uint32_t r;
    asm("cvt.rn.bf16x2.f32 %0, %1, %2;" : "=r"(r) : "f"(hi), "f"(lo));
    return r;
}

__device__ __forceinline__ uint32_t smem_u32(const void* p) {
    return (uint32_t)__cvta_generic_to_shared(p);
}

__device__ __forceinline__ void block_reduce_2(float &s, float &s2) {
    __shared__ float ra[8], rb[8];
#pragma unroll
    for (int m = 16; m > 0; m >>= 1) {
        s  += __shfl_xor_sync(0xffffffffu, s,  m);
        s2 += __shfl_xor_sync(0xffffffffu, s2, m);
    }
    int wid = threadIdx.x >> 5;
    if ((threadIdx.x & 31) == 0) { ra[wid] = s; rb[wid] = s2; }
    __syncthreads();
    s  = ra[0]+ra[1]+ra[2]+ra[3]+ra[4]+ra[5]+ra[6]+ra[7];
    s2 = rb[0]+rb[1]+rb[2]+rb[3]+rb[4]+rb[5]+rb[6]+rb[7];
    __syncthreads();
}

__device__ __forceinline__ float tanh_fast(float x) {
    float y;
    asm("tanh.approx.f32 %0, %1;" : "=f"(y) : "f"(x));
    return y;
}

__device__ __forceinline__ float gelu_tanh(float x) {
    float x3 = x * x * x;
    return 0.5f * x * (1.f + tanh_fast(0.79788456080286535588f * (x + 0.044715f * x3)));
}

__device__ __forceinline__ void mma_bf16(float* d, const uint32_t* a, const uint32_t* b) {
    asm volatile(
        "mma.sync.aligned.m16n8k16.row.col.f32.bf16.bf16.f32 "
        "{%0,%1,%2,%3}, {%4,%5,%6,%7}, {%8,%9}, {%0,%1,%2,%3};"
        : "+f"(d[0]), "+f"(d[1]), "+f"(d[2]), "+f"(d[3])
        : "r"(a[0]), "r"(a[1]), "r"(a[2]), "r"(a[3]), "r"(b[0]), "r"(b[1]));
}

// ---------------- weight prep: transpose + round to bf16 ----------------
// 4 square 1024x1024 weights in one launch (z selects weight)
__global__ __launch_bounds__(256) void round_wT4_kernel(
    const float* __restrict__ w0, const float* __restrict__ w1,
    const float* __restrict__ w2, const float* __restrict__ w3,
    bf16* __restrict__ dst)
{
    __shared__ float t[32][33];
    int z = blockIdx.z;
    const float* W = (z == 0) ? w0 : (z == 1) ? w1 : (z == 2) ? w2 : w3;
    bf16* WT = dst + (size_t)z * MEG;
    int n0 = blockIdx.x * 32, k0 = blockIdx.y * 32;
    int tx = threadIdx.x, ty = threadIdx.y;
#pragma unroll
    for (int j = 0; j < 4; j++)
        t[ty + 8 * j][tx] = W[(size_t)(k0 + ty + 8 * j) * 1024 + n0 + tx];
    __syncthreads();
#pragma unroll
    for (int j = 0; j < 4; j++)
        WT[(size_t)(n0 + ty + 8 * j) * 1024 + k0 + tx] =
            __float2bfloat16_rn(t[tx][ty + 8 * j]);
}

// ffn1 [1024][4096] + ffn2 [4096][1024] in one launch (z selects; z=1 remaps)
__global__ __launch_bounds__(256) void round_wT2_kernel(
    const float* __restrict__ w1, bf16* __restrict__ wt1,
    const float* __restrict__ w2, bf16* __restrict__ wt2)
{
    __shared__ float t[32][33];
    const float* W; bf16* WT; int K, N, n0, k0;
    if (blockIdx.z == 0) {
        W = w1; WT = wt1; K = 1024; N = 4096;
        n0 = blockIdx.x * 32; k0 = blockIdx.y * 32;
    } else {
        W = w2; WT = wt2; K = 4096; N = 1024;
        int lin = blockIdx.x * 32 + blockIdx.y;   // 0..4095
        n0 = (lin & 31) * 32; k0 = (lin >> 5) * 32;
    }
    int tx = threadIdx.x, ty = threadIdx.y;
#pragma unroll
    for (int j = 0; j < 4; j++)
        t[ty + 8 * j][tx] = W[(size_t)(k0 + ty + 8 * j) * N + n0 + tx];
    __syncthreads();
#pragma unroll
    for (int j = 0; j < 4; j++)
        WT[(size_t)(n0 + ty + 8 * j) * K + k0 + tx] =
            __float2bfloat16_rn(t[tx][ty + 8 * j]);
}

// ---------------- emb = silu(temb) @ W + b  (high-occupancy) ----------------
__global__ __launch_bounds__(256) void emb2_kernel(
    const float* __restrict__ temb,
    const float* __restrict__ w1, const float* __restrict__ b1,
    const float* __restrict__ w2, const float* __restrict__ b2)
{
    __shared__ float st[TEMBC];
    __shared__ float part[8][32];
    int tid = threadIdx.x, lane = tid & 31, wid = tid >> 5;
    for (int i = tid; i < TEMBC; i += 256) {
        float t = temb[i];
        st[i] = t / (1.f + expf(-t));
    }
    __syncthreads();

    int colg = blockIdx.x * 32;
    const float* w; const float* bb; float* out; int col;
    if (colg < 6144) { w = w1; bb = b1; out = g_emb1; col = colg + lane; }
    else             { w = w2; bb = b2; out = g_emb2; col = colg - 6144 + lane; }

    float acc = 0.f;
    int k0 = wid * 64;
#pragma unroll 16
    for (int kk = 0; kk < 64; kk++)
        acc += st[k0 + kk] * w[(size_t)(k0 + kk) * 6144 + col];
    part[wid][lane] = acc;
    __syncthreads();
    if (wid == 0) {
        float s = 0.f;
#pragma unroll
        for (int i = 0; i < 8; i++) s += part[i][lane];
        out[col] = s + bb[col];
    }
}

// ---------------- build unique x rows (bf16 out) ----------------
__global__ __launch_bounds__(256) void build_x_kernel(
    const float* __restrict__ hs, const float* __restrict__ enc,
    const float* __restrict__ g, const float* __restrict__ b)
{
    int row = blockIdx.x;
    const float* src; int sc_off, sh_off;
    if (row < TENC) { src = enc + (size_t)row * DIMC; sc_off = 4096; sh_off = 3072; }
    else            { src = hs + (size_t)(row - TENC) * DIMC; sc_off = 1024; sh_off = 0; }
    int tid = threadIdx.x;
    float x[4]; float s = 0.f, s2 = 0.f;
#pragma unroll
    for (int i = 0; i < 4; i++) {
        x[i] = src[tid + i * 256];
        s += x[i]; s2 += x[i] * x[i];
    }
    block_reduce_2(s, s2);
    float mean = s * (1.f / DIMC);
    float var  = s2 * (1.f / DIMC) - mean * mean;
    float inv  = rsqrtf(var + 1e-5f);
    bf16* dst = g_x + (size_t)row * DIMC;
#pragma unroll
    for (int i = 0; i < 4; i++) {
        int d = tid + i * 256;
        float v = (x[i] - mean) * inv * g[d] + b[d];
        dst[d] = __float2bfloat16_rn(v * (1.f + g_emb1[sc_off + d]) + g_emb1[sh_off + d]);
    }
}

// ---------------- BF16 tensor-core GEMM, 3-stage cp.async ring ----------------
// flags: 1=gelu, 2=bf16 out, 4=ffn2-fused-final-add (f32 RMW on C)
#define SSTR 72
#define STAGE_B 18432                  // 128*SSTR*2 bytes per operand stage
#define GEMM_SMEM_B (6 * STAGE_B)      // 110592 B (3 stages x A,B)

__global__ __launch_bounds__(256, 2) void gemm_bf16_kernel(
    const bf16* __restrict__ A, const bf16* __restrict__ B,
    const float* __restrict__ bias, void* __restrict__ Cv,
    int M, int N, int K, int flags)
{
    extern __shared__ bf16 smb[];
    bf16* As0 = smb;                       // 3 stages of A
    bf16* Bs0 = smb + 3 * 128 * SSTR;      // 3 stages of B

    int tid = threadIdx.x;
    int bm = blockIdx.y, bn = blockIdx.x;
    int lane = tid & 31, wid = tid >> 5;
    int wm = (wid & 1) * 64, wn = (wid >> 1) * 32;
    int gid = lane >> 2, tig = lane & 3;

    const bf16* Ag = A + (size_t)bm * 128 * K;
    const bf16* Bg = B + (size_t)bn * 128 * K;

    uint32_t smbase = smem_u32(smb);
    uint32_t aBase0 = smbase + (uint32_t)((wm + (lane & 15)) * 144 + (lane >> 4) * 16);
    uint32_t bBase0 = smbase + 3u * STAGE_B +
                      (uint32_t)((wn + (lane & 7) + ((lane >> 4) << 3)) * 144 +
                                 ((lane >> 3) & 1) * 16);

    float acc[4][4][4];
#pragma unroll
    for (int a = 0; a < 4; a++)
#pragma unroll
        for (int b = 0; b < 4; b++)
#pragma unroll
            for (int c = 0; c < 4; c++) acc[a][b][c] = 0.f;

#define LOAD_TILE(kt, buf)                                                         \
    {                                                                              \
        bf16* ad = As0 + (buf) * 128 * SSTR;                                       \
        bf16* bd = Bs0 + (buf) * 128 * SSTR;                                       \
        _Pragma("unroll")                                                          \
        for (int i = 0; i < 4; i++) {                                              \
            int c = tid + i * 256;                                                 \
            int r = c >> 3, kc = (c & 7) << 3;                                     \
            uint32_t dsm = (uint32_t)__cvta_generic_to_shared(ad + r * SSTR + kc); \
            const bf16* s = Ag + (size_t)r * K + (kt) * 64 + kc;                   \
            asm volatile("cp.async.cg.shared.global [%0], [%1], 16;"               \
                         :: "r"(dsm), "l"(s));                                     \
        }                                                                          \
        _Pragma("unroll")                                                          \
        for (int i = 0; i < 4; i++) {                                              \
            int c = tid + i * 256;                                                 \
            int r = c >> 3, kc = (c & 7) << 3;                                     \
            uint32_t dsm = (uint32_t)__cvta_generic_to_shared(bd + r * SSTR + kc); \
            const bf16* s = Bg + (size_t)r * K + (kt) * 64 + kc;                   \
            asm volatile("cp.async.cg.shared.global [%0], [%1], 16;"               \
                         :: "r"(dsm), "l"(s));                                     \
        }                                                                          \
    }

    int ktiles = K / 64;
    LOAD_TILE(0, 0);
    asm volatile("cp.async.commit_group;");
    LOAD_TILE(1, 1);
    asm volatile("cp.async.commit_group;");

    int buf = 0;
    for (int t = 0; t < ktiles; t++) {
        if (t + 1 < ktiles) asm volatile("cp.async.wait_group 1;");
        else                asm volatile("cp.async.wait_group 0;");
        __syncthreads();
        if (t + 2 < ktiles) {
            int nb = buf;                      // (t+2)%3 == t%3's previous slot: reuse ring
            nb = buf;                          // buffer being freed is (t-1)%3 == (t+2)%3
            nb = (t + 2) % 3;
            LOAD_TILE(t + 2, nb);
            asm volatile("cp.async.commit_group;");
        }

        uint32_t aB = aBase0 + (uint32_t)buf * STAGE_B;
        uint32_t bB = bBase0 + (uint32_t)buf * STAGE_B;
#pragma unroll
        for (int ks = 0; ks < 4; ks++) {
            uint32_t af[4][4], bfr[2][4];
#pragma unroll
            for (int mt = 0; mt < 4; mt++)
                asm volatile(
                    "ldmatrix.sync.aligned.m8n8.x4.shared.b16 {%0,%1,%2,%3}, [%4];"
                    : "=r"(af[mt][0]), "=r"(af[mt][1]), "=r"(af[mt][2]), "=r"(af[mt][3])
                    : "r"(aB + mt * 2304 + ks * 32));
#pragma unroll
            for (int np = 0; np < 2; np++)
                asm volatile(
                    "ldmatrix.sync.aligned.m8n8.x4.shared.b16 {%0,%1,%2,%3}, [%4];"
                    : "=r"(bfr[np][0]), "=r"(bfr[np][1]), "=r"(bfr[np][2]), "=r"(bfr[np][3])
                    : "r"(bB + np * 2304 + ks * 32));
#pragma unroll
            for (int mt = 0; mt < 4; mt++) {
                mma_bf16(acc[mt][0], af[mt], &bfr[0][0]);
                mma_bf16(acc[mt][1], af[mt], &bfr[0][2]);
                mma_bf16(acc[mt][2], af[mt], &bfr[1][0]);
                mma_bf16(acc[mt][3], af[mt], &bfr[1][2]);
            }
        }
        buf = (buf == 2) ? 0 : buf + 1;
    }

    int act = flags & 1, outbf = flags & 2, fin = flags & 4;
#pragma unroll
    for (int mt = 0; mt < 4; mt++) {
        int row = bm * 128 + wm + mt * 16 + gid;
#pragma unroll
        for (int nt = 0; nt < 4; nt++) {
            int col = bn * 128 + wn + nt * 8 + tig * 2;
            float b0 = bias ? bias[col] : 0.f;
            float b1 = bias ? bias[col + 1] : 0.f;
            float v0 = acc[mt][nt][0] + b0, v1 = acc[mt][nt][1] + b1;
            float v2 = acc[mt][nt][2] + b0, v3 = acc[mt][nt][3] + b1;
            if (act) { v0 = gelu_tanh(v0); v1 = gelu_tanh(v1); v2 = gelu_tanh(v2); v3 = gelu_tanh(v3); }
            if (fin) {
                float* C = (float*)Cv;
                int goff  = (row < TENC) ? 5120 : 2048;
                int orow0 = (row < TENC) ? (NTOK + row)     : (row - TENC);
                int orow1 = (row < TENC) ? (NTOK + row + 8) : (row + 8 - TENC);
                float ga = g_emb2[goff + col], gb = g_emb2[goff + col + 1];
                float* p0 = C + (size_t)orow0 * N + col;
                float* p1 = C + (size_t)orow1 * N + col;
                p0[0] += ga * v0; p0[1] += gb * v1;
                p1[0] += ga * v2; p1[1] += gb * v3;
            } else if (outbf) {
                bf16* C = (bf16*)Cv;
                *(uint32_t*)(C + (size_t)row * N + col)       = pack_bf2(v0, v1);
                *(uint32_t*)(C + (size_t)(row + 8) * N + col) = pack_bf2(v2, v3);
            } else {
                float* C = (float*)Cv;
                *(float2*)(C + (size_t)row * N + col)       = make_float2(v0, v1);
                *(float2*)(C + (size_t)(row + 8) * N + col) = make_float2(v2, v3);
            }
        }
    }
}

// ------- per-head LN on q and k in one launch (y: 0=q scale .125, 1=k) --------
__global__ __launch_bounds__(256) void qkln2_kernel(
    bf16* __restrict__ buf,
    const float* __restrict__ qg, const float* __restrict__ qb,
    const float* __restrict__ kg, const float* __restrict__ kb)
{
    int seg  = blockIdx.x * 8 + (threadIdx.x >> 5);
    int lane = threadIdx.x & 31;
    int isk  = blockIdx.y;
    const float* g = isk ? kg : qg;
    const float* b = isk ? kb : qb;
    float scale = isk ? 1.0f : 0.125f;
    bf16* p = buf + (size_t)(seg >> 4) * QKVN + isk * 1024 + (seg & 15) * HD_;
    float x0 = __bfloat162float(p[lane]);
    float x1 = __bfloat162float(p[lane + 32]);
    float s = x0 + x1, s2 = x0 * x0 + x1 * x1;
#pragma unroll
    for (int m = 16; m > 0; m >>= 1) {
        s  += __shfl_xor_sync(0xffffffffu, s,  m);
        s2 += __shfl_xor_sync(0xffffffffu, s2, m);
    }
    float mean = s * (1.f / 64.f);
    float var  = s2 * (1.f / 64.f) - mean * mean;
    float inv  = rsqrtf(var + 1e-6f);
    p[lane]      = __float2bfloat16_rn(((x0 - mean) * inv * g[lane]      + b[lane])      * scale);
    p[lane + 32] = __float2bfloat16_rn(((x1 - mean) * inv * g[lane + 32] + b[lane + 32]) * scale);
}

// ---------------- BF16 flash attention, 3-buffer cp.async KV ring -------------
#define KVSTAGE (64 * SSTR)                       // elements per K (or V) stage
#define ATTN_SMEM_B ((128 * SSTR + 6 * KVSTAGE) * 2)   // 73728 B

__global__ __launch_bounds__(256, 2) void attn_bf16_kernel(
    const bf16* __restrict__ qkv, bf16* __restrict__ o)
{
    extern __shared__ bf16 smb[];
    bf16* Qs  = smb;
    bf16* Ks0 = smb + 128 * SSTR;                 // 3 K stages
    bf16* Vs0 = Ks0 + 3 * KVSTAGE;                // 3 V stages

    int qt = blockIdx.x, h = blockIdx.y, w = blockIdx.z;
    int tid = threadIdx.x, lane = tid & 31, wid = tid >> 5;
    int gid = lane >> 2, tig = lane & 3;
    int wq0 = wid * 16;
    const size_t obase = (size_t)w * LWIN * DIMC + (size_t)h * HD_;

    size_t qrow0 = (size_t)qt * 128 + (qt ? (size_t)w * SROW : 0);
    const bf16* qg = qkv + qrow0 * QKVN + h * HD_;

#pragma unroll
    for (int i = 0; i < 4; i++) {
        int e = tid + i * 256;
        int r = e >> 3, dc = (e & 7) << 3;
        *(uint4*)(Qs + r * SSTR + dc) = *(const uint4*)(qg + (size_t)r * QKVN + dc);
    }

#define KV_LOAD(kt, buf)                                                           \
    {                                                                              \
        size_t krow0 = (size_t)(kt) * 64 + ((kt) >= 2 ? (size_t)w * SROW : 0);     \
        const bf16* kg = qkv + krow0 * QKVN + 1024 + h * HD_;                      \
        const bf16* vg = qkv + krow0 * QKVN + 2048 + h * HD_;                      \
        bf16* kd = Ks0 + (buf) * KVSTAGE;                                          \
        bf16* vd = Vs0 + (buf) * KVSTAGE;                                          \
        _Pragma("unroll")                                                          \
        for (int i = 0; i < 2; i++) {                                              \
            int e = tid + i * 256;                                                 \
            int r = e >> 3, dc = (e & 7) << 3;                                     \
            uint32_t dk = (uint32_t)__cvta_generic_to_shared(kd + r * SSTR + dc);  \
            uint32_t dv = (uint32_t)__cvta_generic_to_shared(vd + r * SSTR + dc);  \
            asm volatile("cp.async.cg.shared.global [%0], [%1], 16;"               \
                         :: "r"(dk), "l"(kg + (size_t)r * QKVN + dc));             \
            asm volatile("cp.async.cg.shared.global [%0], [%1], 16;"               \
                         :: "r"(dv), "l"(vg + (size_t)r * QKVN + dc));             \
        }                                                                          \
    }

    KV_LOAD(0, 0);
    asm volatile("cp.async.commit_group;");
    KV_LOAD(1, 1);
    asm volatile("cp.async.commit_group;");

    float accO[8][4];
#pragma unroll
    for (int nt = 0; nt < 8; nt++)
#pragma unroll
        for (int i = 0; i < 4; i++) accO[nt][i] = 0.f;
    float m0 = -1e30f, m1 = -1e30f, l0 = 0.f, l1 = 0.f;

    int buf = 0;
    for (int kt = 0; kt < 20; kt++) {
        if (kt + 1 < 20) asm volatile("cp.async.wait_group 1;");
        else             asm volatile("cp.async.wait_group 0;");
        __syncthreads();
        if (kt + 2 < 20) {
            int nb = (kt + 2) % 3;
            KV_LOAD(kt + 2, nb);
            asm volatile("cp.async.commit_group;");
        }

        const bf16* Ks = Ks0 + buf * KVSTAGE;
        const bf16* Vs = Vs0 + buf * KVSTAGE;

        float s[8][4];
#pragma unroll
        for (int nt = 0; nt < 8; nt++)
#pragma unroll
            for (int i = 0; i < 4; i++) s[nt][i] = 0.f;

        const uint32_t* Qw = (const uint32_t*)Qs;
        const uint32_t* Kw = (const uint32_t*)Ks;
#pragma unroll
        for (int ks = 0; ks < 4; ks++) {
            uint32_t af[4];
            int ai = (wq0 + gid) * 36 + ks * 8 + tig;
            af[0] = Qw[ai]; af[1] = Qw[ai + 288];
            af[2] = Qw[ai + 4]; af[3] = Qw[ai + 292];
#pragma unroll
            for (int nt = 0; nt < 8; nt++) {
                uint32_t bfr[2];
                int bi = (nt * 8 + gid) * 36 + ks * 8 + tig;
                bfr[0] = Kw[bi]; bfr[1] = Kw[bi + 4];
                mma_bf16(s[nt], af, bfr);
            }
        }

        float mx0 = -1e30f, mx1 = -1e30f;
#pragma unroll
        for (int nt = 0; nt < 8; nt++) {
            mx0 = fmaxf(mx0, fmaxf(s[nt][0], s[nt][1]));
            mx1 = fmaxf(mx1, fmaxf(s[nt][2], s[nt][3]));
        }
        mx0 = fmaxf(mx0, __shfl_xor_sync(0xffffffffu, mx0, 1));
        mx0 = fmaxf(mx0, __shfl_xor_sync(0xffffffffu, mx0, 2));
        mx1 = fmaxf(mx1, __shfl_xor_sync(0xffffffffu, mx1, 1));
        mx1 = fmaxf(mx1, __shfl_xor_sync(0xffffffffu, mx1, 2));
        float mn0 = fmaxf(m0, mx0), mn1 = fmaxf(m1, mx1);
        float f0 = __expf(m0 - mn0), f1 = __expf(m1 - mn1);
        m0 = mn0; m1 = mn1;
        float sum0 = 0.f, sum1 = 0.f;
#pragma unroll
        for (int nt = 0; nt < 8; nt++) {
            s[nt][0] = __expf(s[nt][0] - mn0);
            s[nt][1] = __expf(s[nt][1] - mn0);
            s[nt][2] = __expf(s[nt][2] - mn1);
            s[nt][3] = __expf(s[nt][3] - mn1);
            sum0 += s[nt][0] + s[nt][1];
            sum1 += s[nt][2] + s[nt][3];
        }
        sum0 += __shfl_xor_sync(0xffffffffu, sum0, 1);
        sum0 += __shfl_xor_sync(0xffffffffu, sum0, 2);
        sum1 += __shfl_xor_sync(0xffffffffu, sum1, 1);
        sum1 += __shfl_xor_sync(0xffffffffu, sum1, 2);
        l0 = l0 * f0 + sum0;
        l1 = l1 * f1 + sum1;
#pragma unroll
        for (int nt = 0; nt < 8; nt++) {
            accO[nt][0] *= f0; accO[nt][1] *= f0;
            accO[nt][2] *= f1; accO[nt][3] *= f1;
        }

#pragma unroll
        for (int kc = 0; kc < 4; kc++) {
            uint32_t aP[4];
            aP[0] = pack_bf2(s[2 * kc][0],     s[2 * kc][1]);
            aP[1] = pack_bf2(s[2 * kc][2],     s[2 * kc][3]);
            aP[2] = pack_bf2(s[2 * kc + 1][0], s[2 * kc + 1][1]);
            aP[3] = pack_bf2(s[2 * kc + 1][2], s[2 * kc + 1][3]);
#pragma unroll
            for (int ntp = 0; ntp < 4; ntp++) {
                int row = kc * 16 + ((lane >> 3) & 1) * 8 + (lane & 7);
                int col = ntp * 16 + (lane >> 4) * 8;
                uint32_t smaddr = smem_u32(Vs + row * SSTR + col);
                uint32_t b0, b1, b2, b3;
                asm volatile(
                    "ldmatrix.sync.aligned.m8n8.x4.trans.shared.b16 {%0,%1,%2,%3}, [%4];"
                    : "=r"(b0), "=r"(b1), "=r"(b2), "=r"(b3) : "r"(smaddr));
                uint32_t blo[2] = {b0, b1}, bhi[2] = {b2, b3};
                mma_bf16(accO[2 * ntp],     aP, blo);
                mma_bf16(accO[2 * ntp + 1], aP, bhi);
            }
        }
        buf = (buf == 2) ? 0 : buf + 1;
    }

    float il0 = 1.f / l0, il1 = 1.f / l1;
    int row0 = qt * 128 + wq0 + gid;
#pragma unroll
    for (int nt = 0; nt < 8; nt++) {
        int col = nt * 8 + tig * 2;
        *(uint32_t*)(o + obase + (size_t)row0 * DIMC + col) =
            pack_bf2(accO[nt][0] * il0, accO[nt][1] * il0);
        *(uint32_t*)(o + obase + (size_t)(row0 + 8) * DIMC + col) =
            pack_bf2(accO[nt][2] * il1, accO[nt][3] * il1);
    }
}

// ------- blend attention outputs across windows (before wo) -------------------
__global__ __launch_bounds__(256) void blend_ao_kernel()
{
    int row = blockIdx.x;            // 0..MFF-1
    int tid = threadIdx.x;
    bf16* dst = g_x + (size_t)row * DIMC;
    if (row < TENC) {
#pragma unroll
        for (int i = 0; i < 4; i++) {
            int d = tid + i * 256;
            float a = 0.f;
#pragma unroll
            for (int w = 0; w < WQN; w++)
                a += __bfloat162float(g_ao[((size_t)w * LWIN + row) * DIMC + d]);
            dst[d] = __float2bfloat16_rn(a * 0.2f);
        }
    } else {
        int gdx = row - TENC;
        int blk = gdx / SROW;
        float acc[4] = {0.f, 0.f, 0.f, 0.f};
        float wsum = 0.f;
#pragma unroll
        for (int dw = -1; dw <= 0; dw++) {
            int w = blk + dw;
            if (w < 0 || w > 4) continue;
            int lv = gdx - w * SROW;
            float wt = c_pyr[lv / 144];
            wsum += wt;
            const bf16* op = g_ao + ((size_t)w * LWIN + TENC + lv) * DIMC;
#pragma unroll
            for (int i = 0; i < 4; i++)
                acc[i] += wt * __bfloat162float(op[tid + i * 256]);
        }
        float inv = 1.f / wsum;
#pragma unroll
        for (int i = 0; i < 4; i++)
            dst[tid + i * 256] = __float2bfloat16_rn(acc[i] * inv);
    }
}

// ------- post-wo combine: residual + LN2 -> out and ffin ----------------------
__global__ __launch_bounds__(256) void combine_post_kernel(
    const float* __restrict__ hs, const float* __restrict__ enc,
    float* __restrict__ out, const float* __restrict__ g, const float* __restrict__ b)
{
    int row = blockIdx.x;            // 0..MFF-1 (o2 row)
    int tid = threadIdx.x;
    const float* o2 = g_o2 + (size_t)row * DIMC;
    const float* src; float* outp; int gate_off, sc_off, sh_off;
    if (row < TENC) {
        src = enc + (size_t)row * DIMC;
        outp = out + (size_t)(NTOK + row) * DIMC;
        gate_off = 5120; sc_off = 4096; sh_off = 3072;
    } else {
        int gdx = row - TENC;
        src = hs + (size_t)gdx * DIMC;
        outp = out + (size_t)gdx * DIMC;
        gate_off = 2048; sc_off = 1024; sh_off = 0;
    }
    float r[4]; float s = 0.f, s2 = 0.f;
#pragma unroll
    for (int i = 0; i < 4; i++) {
        int d = tid + i * 256;
        r[i] = src[d] + g_emb1[gate_off + d] * o2[d];
        outp[d] = r[i];
        s += r[i]; s2 += r[i] * r[i];
    }
    block_reduce_2(s, s2);
    float mean = s * (1.f / DIMC);
    float var  = s2 * (1.f / DIMC) - mean * mean;
    float inv2 = rsqrtf(var + 1e-5f);
    bf16* dst = g_ffin + (size_t)row * DIMC;
#pragma unroll
    for (int i = 0; i < 4; i++) {
        int d = tid + i * 256;
        float v = (r[i] - mean) * inv2 * g[d] + b[d];
        dst[d] = __float2bfloat16_rn(v * (1.f + g_emb2[sc_off + d]) + g_emb2[sh_off + d]);
    }
}

// ---------------- host side ----------------
static void launch_gemm(const bf16* A, const bf16* B, const float* bias,
                        void* C, int M, int N, int K, int flags)
{
    dim3 grid(N / 128, M / 128);
    gemm_bf16_kernel<<<grid, 256, GEMM_SMEM_B>>>(A, B, bias, C, M, N, K, flags);
}

extern "C" void kernel_launch(void* const* d_in, const int* in_sizes, int n_in,
                              void* d_out, int out_size)
{
    const float* hs    = (const float*)d_in[0];
    const float* enc   = (const float*)d_in[1];
    const float* temb  = (const float*)d_in[2];
    const float* n1w   = (const float*)d_in[3];
    const float* n1b   = (const float*)d_in[4];
    const float* n1g   = (const float*)d_in[5];
    const float* n1bb  = (const float*)d_in[6];
    const float* wq    = (const float*)d_in[7];
    const float* wk    = (const float*)d_in[8];
    const float* wv    = (const float*)d_in[9];
    const float* nqg   = (const float*)d_in[10];
    const float* nqb   = (const float*)d_in[11];
    const float* nkg   = (const float*)d_in[12];
    const float* nkb   = (const float*)d_in[13];
    const float* wo    = (const float*)d_in[14];
    const float* bo    = (const float*)d_in[15];
    const float* n2w   = (const float*)d_in[16];
    const float* n2b   = (const float*)d_in[17];
    const float* n2g   = (const float*)d_in[18];
    const float* n2bb  = (const float*)d_in[19];
    const float* ffw1  = (const float*)d_in[20];
    const float* ffb1  = (const float*)d_in[21];
    const float* ffw2  = (const float*)d_in[22];
    const float* ffb2  = (const float*)d_in[23];
    (void)in_sizes; (void)n_in;

    float* out = (float*)d_out;
    (void)out_size;

    bf16 *p_x, *p_qkv, *p_ao, *p_ffin, *p_h1, *p_wt;
    float *p_o2;
    cudaGetSymbolAddress((void**)&p_x,    g_x);
    cudaGetSymbolAddress((void**)&p_qkv,  g_qkv);
    cudaGetSymbolAddress((void**)&p_ao,   g_ao);
    cudaGetSymbolAddress((void**)&p_o2,   g_o2);
    cudaGetSymbolAddress((void**)&p_ffin, g_ffin);
    cudaGetSymbolAddress((void**)&p_h1,   g_h1);
    cudaGetSymbolAddress((void**)&p_wt,   g_wt);

    bf16* wtqkv = p_wt;                       // [3072][1024] (wq^T|wk^T|wv^T)
    bf16* wtwo  = p_wt + (size_t)3 * MEG;     // [1024][1024]
    bf16* wtw1  = p_wt + (size_t)4 * MEG;     // [4096][1024]
    bf16* wtw2  = p_wt + (size_t)8 * MEG;     // [1024][4096]

    cudaFuncSetAttribute(attn_bf16_kernel, cudaFuncAttributeMaxDynamicSharedMemorySize, ATTN_SMEM_B);
    cudaFuncSetAttribute(gemm_bf16_kernel, cudaFuncAttributeMaxDynamicSharedMemorySize, GEMM_SMEM_B);

    // 0. weight prep (4 square transposes in 1 launch; ffn pair in 1 launch)
    dim3 tb(32, 8);
    round_wT4_kernel<<<dim3(32, 32, 4), tb>>>(wq, wk, wv, wo, wtqkv);
    round_wT2_kernel<<<dim3(128, 32, 2), tb>>>(ffw1, wtw1, ffw2, wtw2);

    // 1. modulation embeddings (high-occupancy)
    emb2_kernel<<<384, 256>>>(temb, n1w, n1b, n2w, n2b);
    // 2. unique x rows (bf16)
    build_x_kernel<<<MFF, 256>>>(hs, enc, n1g, n1bb);
    // 3. fused QKV projection -> bf16
    launch_gemm(p_x, wtqkv, nullptr, p_qkv, MFF, QKVN, DIMC, 2);
    // 4. per-head LN on q (x0.125 folded) and k, one launch
    qkln2_kernel<<<dim3(MFF * HEADS_ / 8, 2), 256>>>(p_qkv, nqg, nqb, nkg, nkb);
    // 5. attention (3-buffer cp.async KV ring)
    attn_bf16_kernel<<<dim3(LWIN / 128, HEADS_, WQN), 256, ATTN_SMEM_B>>>(p_qkv, p_ao);
    // 6. blend windows BEFORE wo (row-linear commute), then wo on 3584 rows
    blend_ao_kernel<<<MFF, 256>>>();
    launch_gemm(p_x, wtwo, bo, p_o2, MFF, DIMC, DIMC, 0);
    // 7. residual + LN2 -> out, ffin
    combine_post_kernel<<<MFF, 256>>>(hs, enc, out, n2g, n2bb);
    // 8. FFN; ffn2 fuses final gated residual into out
    launch_gemm(p_ffin, wtw1, ffb1, p_h1, MFF, 4096, DIMC, 1 | 2);
    launch_gemm(p_h1, wtw2, ffb2, out, MFF, DIMC, 4096, 4);
}